// round 2
// baseline (speedup 1.0000x reference)
#include <cuda_runtime.h>
#include <cuda_bf16.h>

#define B_SZ 2
#define SEQL 2048
#define DMODEL 2048
#define DINNER 4096
#define DSTATE 128
#define HEADDIM 64
#define NHEADS 64
#define CHUNKL 256
#define NCHUNK 8
#define CONV_DIM 4352     // DINNER + 2*DSTATE
#define D_IN_PROJ 8512    // 2*DINNER + 2*DSTATE + NHEADS
#define EPSV 1e-5f

// ---------------- scratch (device globals; no allocation allowed) ----------------
__device__ float g_zx[B_SZ*SEQL*D_IN_PROJ];                       // in_proj output
__device__ float g_xBC[B_SZ*SEQL*CONV_DIM];                       // conv+silu output
__device__ float g_dt[B_SZ*SEQL*NHEADS];                          // softplus dt
__device__ float g_Acs[B_SZ*NHEADS*NCHUNK*CHUNKL];                // per-chunk inclusive cumsum of dA
__device__ float g_states[(size_t)B_SZ*NCHUNK*NHEADS*HEADDIM*DSTATE];
__device__ float g_prev[(size_t)B_SZ*NCHUNK*NHEADS*HEADDIM*DSTATE];
__device__ float g_yg[B_SZ*SEQL*DINNER];                          // gated pre-norm
__device__ float g_yn[B_SZ*SEQL*DINNER];                          // normalized

__device__ __forceinline__ float siluf(float a) { return a / (1.f + expf(-a)); }

// ---------------- generic SGEMM: C[M,N] = A[M,K] * B[N,K]^T (row major) ----------------
__global__ __launch_bounds__(256) void sgemm_abt(
    const float* __restrict__ A, const float* __restrict__ B,
    float* __restrict__ C, int M, int N, int K)
{
    __shared__ float As[16][132];
    __shared__ float Bs[16][132];
    const int tid = threadIdx.x;
    const int tx = tid & 15, ty = tid >> 4;
    const int m0 = blockIdx.y << 7, n0 = blockIdx.x << 7;

    float acc[8][8];
#pragma unroll
    for (int i = 0; i < 8; i++)
#pragma unroll
        for (int j = 0; j < 8; j++) acc[i][j] = 0.f;

    for (int k0 = 0; k0 < K; k0 += 16) {
#pragma unroll
        for (int it = 0; it < 2; it++) {
            int v = tid + (it << 8);
            int r = v >> 2;
            int kc = (v & 3) << 2;
            float4 fa = *(const float4*)(A + (size_t)(m0 + r) * K + k0 + kc);
            As[kc + 0][r] = fa.x; As[kc + 1][r] = fa.y;
            As[kc + 2][r] = fa.z; As[kc + 3][r] = fa.w;
            float4 fb = make_float4(0.f, 0.f, 0.f, 0.f);
            if (n0 + r < N) fb = *(const float4*)(B + (size_t)(n0 + r) * K + k0 + kc);
            Bs[kc + 0][r] = fb.x; Bs[kc + 1][r] = fb.y;
            Bs[kc + 2][r] = fb.z; Bs[kc + 3][r] = fb.w;
        }
        __syncthreads();
#pragma unroll
        for (int k = 0; k < 16; k++) {
            float a[8], bb[8];
            *(float4*)(a)      = *(const float4*)&As[k][ty * 8];
            *(float4*)(a + 4)  = *(const float4*)&As[k][ty * 8 + 4];
            *(float4*)(bb)     = *(const float4*)&Bs[k][tx * 8];
            *(float4*)(bb + 4) = *(const float4*)&Bs[k][tx * 8 + 4];
#pragma unroll
            for (int i = 0; i < 8; i++)
#pragma unroll
                for (int j = 0; j < 8; j++) acc[i][j] += a[i] * bb[j];
        }
        __syncthreads();
    }
#pragma unroll
    for (int i = 0; i < 8; i++) {
        int m = m0 + ty * 8 + i;
#pragma unroll
        for (int j = 0; j < 8; j += 4) {
            int n = n0 + tx * 8 + j;
            if (n < N)
                *(float4*)(C + (size_t)m * N + n) =
                    make_float4(acc[i][j], acc[i][j+1], acc[i][j+2], acc[i][j+3]);
        }
    }
}

// ---------------- causal depthwise conv (width 4) + silu ----------------
__global__ void conv_silu_kernel(const float* __restrict__ conv_w,
                                 const float* __restrict__ conv_b)
{
    int c = blockIdx.x * 128 + threadIdx.x;       // channel < CONV_DIM
    int b = blockIdx.y;
    int t0 = blockIdx.z * 256;                    // time segment
    float w0 = conv_w[c * 4 + 0], w1 = conv_w[c * 4 + 1];
    float w2 = conv_w[c * 4 + 2], w3 = conv_w[c * 4 + 3];
    float bias = conv_b[c];
    const float* src = g_zx + (size_t)b * SEQL * D_IN_PROJ + DINNER + c;
    float* dst = g_xBC + (size_t)b * SEQL * CONV_DIM + c;
    float x0 = (t0 >= 3) ? src[(size_t)(t0 - 3) * D_IN_PROJ] : 0.f;
    float x1 = (t0 >= 2) ? src[(size_t)(t0 - 2) * D_IN_PROJ] : 0.f;
    float x2 = (t0 >= 1) ? src[(size_t)(t0 - 1) * D_IN_PROJ] : 0.f;
    for (int t = t0; t < t0 + 256; t++) {
        float x3 = src[(size_t)t * D_IN_PROJ];
        float a = bias + w0 * x0 + w1 * x1 + w2 * x2 + w3 * x3;
        dst[(size_t)t * CONV_DIM] = siluf(a);
        x0 = x1; x1 = x2; x2 = x3;
    }
}

// ---------------- dt = softplus(raw + bias), dA = dt*(-exp(A_log)), per-chunk cumsum ----------------
__global__ void dt_scan_kernel(const float* __restrict__ dt_bias,
                               const float* __restrict__ A_log)
{
    int idx = blockIdx.x;
    int c = idx % NCHUNK; idx /= NCHUNK;
    int h = idx % NHEADS;
    int b = idx / NHEADS;
    int l = threadIdx.x;
    int t = c * CHUNKL + l;
    float raw = g_zx[(size_t)(b * SEQL + t) * D_IN_PROJ + DINNER + CONV_DIM + h];
    float xv = raw + dt_bias[h];
    float dt = (xv > 20.f) ? xv : log1pf(expf(xv));
    g_dt[(b * SEQL + t) * NHEADS + h] = dt;
    float dA = dt * (-expf(A_log[h]));
    __shared__ float s[CHUNKL];
    s[l] = dA;
    __syncthreads();
    for (int off = 1; off < CHUNKL; off <<= 1) {
        float v = (l >= off) ? s[l - off] : 0.f;
        __syncthreads();
        s[l] += v;
        __syncthreads();
    }
    g_Acs[((b * NHEADS + h) * NCHUNK + c) * CHUNKL + l] = s[l];
}

// ---------------- per-chunk states: states[b,c,h,p,n] = sum_l B[l,n]*decay[l]*X[l,p] ----------------
__global__ __launch_bounds__(256) void states_kernel()
{
    __shared__ float Bd[32][132];
    __shared__ float Xs[32][68];
    __shared__ float dec[32];
    __shared__ float dts[32];
    int idx = blockIdx.x;
    int h = idx % NHEADS; idx /= NHEADS;
    int c = idx % NCHUNK;
    int b = idx / NCHUNK;
    int tid = threadIdx.x;
    int tx = tid & 15, ty = tid >> 4;
    const float* acs = g_Acs + ((b * NHEADS + h) * NCHUNK + c) * CHUNKL;
    float acs_last = acs[CHUNKL - 1];
    float acc[4][8];
#pragma unroll
    for (int i = 0; i < 4; i++)
#pragma unroll
        for (int j = 0; j < 8; j++) acc[i][j] = 0.f;

    for (int l0 = 0; l0 < CHUNKL; l0 += 32) {
        if (tid < 32) {
            int t = c * CHUNKL + l0 + tid;
            dec[tid] = expf(acs_last - acs[l0 + tid]);
            dts[tid] = g_dt[(b * SEQL + t) * NHEADS + h];
        }
        __syncthreads();
#pragma unroll
        for (int it = 0; it < 4; it++) {       // B*decay: 32x128
            int v = tid + it * 256;
            int r = v >> 5, nn = (v & 31) << 2;
            int t = c * CHUNKL + l0 + r;
            float4 f = *(const float4*)(g_xBC + (size_t)(b * SEQL + t) * CONV_DIM + DINNER + nn);
            float d = dec[r];
            Bd[r][nn + 0] = f.x * d; Bd[r][nn + 1] = f.y * d;
            Bd[r][nn + 2] = f.z * d; Bd[r][nn + 3] = f.w * d;
        }
#pragma unroll
        for (int it = 0; it < 2; it++) {       // X = x_ssm*dt: 32x64
            int v = tid + it * 256;
            int r = v >> 4, pp = (v & 15) << 2;
            int t = c * CHUNKL + l0 + r;
            float4 f = *(const float4*)(g_xBC + (size_t)(b * SEQL + t) * CONV_DIM + h * HEADDIM + pp);
            float d = dts[r];
            *(float4*)&Xs[r][pp] = make_float4(f.x * d, f.y * d, f.z * d, f.w * d);
        }
        __syncthreads();
#pragma unroll
        for (int l = 0; l < 32; l++) {
            float a[4], bb[8];
            *(float4*)a = *(const float4*)&Xs[l][ty * 4];
            *(float4*)(bb)     = *(const float4*)&Bd[l][tx * 8];
            *(float4*)(bb + 4) = *(const float4*)&Bd[l][tx * 8 + 4];
#pragma unroll
            for (int i = 0; i < 4; i++)
#pragma unroll
                for (int j = 0; j < 8; j++) acc[i][j] += a[i] * bb[j];
        }
        __syncthreads();
    }
    float* out = g_states + (size_t)((b * NCHUNK + c) * NHEADS + h) * HEADDIM * DSTATE;
#pragma unroll
    for (int i = 0; i < 4; i++)
#pragma unroll
        for (int j = 0; j < 8; j += 4)
            *(float4*)(out + (ty * 4 + i) * DSTATE + tx * 8 + j) =
                make_float4(acc[i][j], acc[i][j+1], acc[i][j+2], acc[i][j+3]);
}

// ---------------- inter-chunk recurrence: prev[b,c] = state before chunk c ----------------
__global__ __launch_bounds__(256) void prev_kernel()
{
    int b = blockIdx.x >> 6;
    int h = blockIdx.x & 63;
    int tid = threadIdx.x;
    float P[32];
#pragma unroll
    for (int i = 0; i < 32; i++) P[i] = 0.f;
    for (int c = 0; c < NCHUNK; c++) {
        float decay = expf(g_Acs[((b * NHEADS + h) * NCHUNK + c) * CHUNKL + CHUNKL - 1]);
        size_t base = (size_t)((b * NCHUNK + c) * NHEADS + h) * HEADDIM * DSTATE;
#pragma unroll
        for (int i = 0; i < 32; i++) {
            int e = i * 256 + tid;
            g_prev[base + e] = P[i];
            P[i] = P[i] * decay + g_states[base + e];
        }
    }
}

// ---------------- Y = Y_diag + Y_off + D*x_ssm, then gate with silu(z) ----------------
__global__ __launch_bounds__(256, 2) void y_kernel(const float* __restrict__ Dp)
{
    extern __shared__ float sm[];
    float* Cst = sm;                 // [128][68]  C^T  (n-major)
    float* Bst = Cst + 128 * 68;     // [128][68]  B^T / prev^T
    float* Xs  = Bst + 128 * 68;     // [64][68]   X (s-major)
    float* St  = Xs  + 64 * 68;      // [64][68]   S^T (s-major)
    float* acs = St  + 64 * 68;      // [256]

    int idx = blockIdx.x;
    int lt = idx & 3; idx >>= 2;
    int h = idx % NHEADS; idx /= NHEADS;
    int c = idx % NCHUNK;
    int b = idx / NCHUNK;
    int tid = threadIdx.x;
    int tx = tid & 15, ty = tid >> 4;
    int l0 = lt * 64;

    const float* acs_g = g_Acs + ((b * NHEADS + h) * NCHUNK + c) * CHUNKL;
    acs[tid] = acs_g[tid];

#pragma unroll
    for (int it = 0; it < 8; it++) {       // C tile (l0..l0+63) transposed
        int v = tid + it * 256;
        int r = v >> 5, nn = (v & 31) << 2;
        int t = c * CHUNKL + l0 + r;
        float4 f = *(const float4*)(g_xBC + (size_t)(b * SEQL + t) * CONV_DIM + DINNER + DSTATE + nn);
        Cst[(nn + 0) * 68 + r] = f.x; Cst[(nn + 1) * 68 + r] = f.y;
        Cst[(nn + 2) * 68 + r] = f.z; Cst[(nn + 3) * 68 + r] = f.w;
    }
    __syncthreads();

    float Yacc[4][4];
#pragma unroll
    for (int i = 0; i < 4; i++)
#pragma unroll
        for (int j = 0; j < 4; j++) Yacc[i][j] = 0.f;

    for (int st = 0; st <= lt; st++) {
        int s0 = st * 64;
#pragma unroll
        for (int it = 0; it < 8; it++) {   // B tile transposed
            int v = tid + it * 256;
            int r = v >> 5, nn = (v & 31) << 2;
            int t = c * CHUNKL + s0 + r;
            float4 f = *(const float4*)(g_xBC + (size_t)(b * SEQL + t) * CONV_DIM + DINNER + nn);
            Bst[(nn + 0) * 68 + r] = f.x; Bst[(nn + 1) * 68 + r] = f.y;
            Bst[(nn + 2) * 68 + r] = f.z; Bst[(nn + 3) * 68 + r] = f.w;
        }
#pragma unroll
        for (int it = 0; it < 4; it++) {   // X tile (row-major s)
            int v = tid + it * 256;
            int r = v >> 4, pp = (v & 15) << 2;
            int t = c * CHUNKL + s0 + r;
            float4 f = *(const float4*)(g_xBC + (size_t)(b * SEQL + t) * CONV_DIM + h * HEADDIM + pp);
            float d = g_dt[(b * SEQL + t) * NHEADS + h];
            *(float4*)&Xs[r * 68 + pp] = make_float4(f.x * d, f.y * d, f.z * d, f.w * d);
        }
        __syncthreads();

        float sacc[4][4];
#pragma unroll
        for (int i = 0; i < 4; i++)
#pragma unroll
            for (int j = 0; j < 4; j++) sacc[i][j] = 0.f;
#pragma unroll 4
        for (int n = 0; n < 128; n++) {    // S = C B^T (K = DSTATE)
            float4 a4 = *(const float4*)&Cst[n * 68 + (ty << 2)];
            float4 b4 = *(const float4*)&Bst[n * 68 + (tx << 2)];
            float a[4] = {a4.x, a4.y, a4.z, a4.w};
            float bb[4] = {b4.x, b4.y, b4.z, b4.w};
#pragma unroll
            for (int i = 0; i < 4; i++)
#pragma unroll
                for (int j = 0; j < 4; j++) sacc[i][j] += a[i] * bb[j];
        }
        // mask + exp(Acs_l - Acs_s), write S^T
#pragma unroll
        for (int j = 0; j < 4; j++) {
            int sg = s0 + (tx << 2) + j;
            float col[4];
#pragma unroll
            for (int i = 0; i < 4; i++) {
                int lg = l0 + (ty << 2) + i;
                col[i] = (sg <= lg) ? sacc[i][j] * expf(acs[lg] - acs[sg]) : 0.f;
            }
            *(float4*)&St[((tx << 2) + j) * 68 + (ty << 2)] =
                make_float4(col[0], col[1], col[2], col[3]);
        }
        __syncthreads();
#pragma unroll 4
        for (int s = 0; s < 64; s++) {     // Y += S X
            float4 a4 = *(const float4*)&St[s * 68 + (ty << 2)];
            float4 x4 = *(const float4*)&Xs[s * 68 + (tx << 2)];
            float a[4] = {a4.x, a4.y, a4.z, a4.w};
            float xx[4] = {x4.x, x4.y, x4.z, x4.w};
#pragma unroll
            for (int i = 0; i < 4; i++)
#pragma unroll
                for (int j = 0; j < 4; j++) Yacc[i][j] += a[i] * xx[j];
        }
        __syncthreads();
    }

    // off-diagonal: load prev^T into Bst, GEMM with C^T
    size_t pbase = (size_t)((b * NCHUNK + c) * NHEADS + h) * HEADDIM * DSTATE;
#pragma unroll
    for (int it = 0; it < 8; it++) {
        int v = tid + it * 256;
        int p = v >> 5, nn = (v & 31) << 2;
        float4 f = *(const float4*)(g_prev + pbase + p * DSTATE + nn);
        Bst[(nn + 0) * 68 + p] = f.x; Bst[(nn + 1) * 68 + p] = f.y;
        Bst[(nn + 2) * 68 + p] = f.z; Bst[(nn + 3) * 68 + p] = f.w;
    }
    __syncthreads();
    float toff[4][4];
#pragma unroll
    for (int i = 0; i < 4; i++)
#pragma unroll
        for (int j = 0; j < 4; j++) toff[i][j] = 0.f;
#pragma unroll 4
    for (int n = 0; n < 128; n++) {
        float4 a4 = *(const float4*)&Cst[n * 68 + (ty << 2)];
        float4 b4 = *(const float4*)&Bst[n * 68 + (tx << 2)];
        float a[4] = {a4.x, a4.y, a4.z, a4.w};
        float bb[4] = {b4.x, b4.y, b4.z, b4.w};
#pragma unroll
        for (int i = 0; i < 4; i++)
#pragma unroll
            for (int j = 0; j < 4; j++) toff[i][j] += a[i] * bb[j];
    }

    float Dh = Dp[h];
#pragma unroll
    for (int i = 0; i < 4; i++) {
        int lg = l0 + (ty << 2) + i;
        int t = c * CHUNKL + lg;
        float el = expf(acs[lg]);
        float4 xs4 = *(const float4*)(g_xBC + (size_t)(b * SEQL + t) * CONV_DIM + h * HEADDIM + (tx << 2));
        float4 z4  = *(const float4*)(g_zx + (size_t)(b * SEQL + t) * D_IN_PROJ + h * HEADDIM + (tx << 2));
        float4 o;
        o.x = (Yacc[i][0] + el * toff[i][0] + xs4.x * Dh) * siluf(z4.x);
        o.y = (Yacc[i][1] + el * toff[i][1] + xs4.y * Dh) * siluf(z4.y);
        o.z = (Yacc[i][2] + el * toff[i][2] + xs4.z * Dh) * siluf(z4.z);
        o.w = (Yacc[i][3] + el * toff[i][3] + xs4.w * Dh) * siluf(z4.w);
        *(float4*)(g_yg + (size_t)(b * SEQL + t) * DINNER + h * HEADDIM + (tx << 2)) = o;
    }
}

// ---------------- RMSNorm ----------------
__global__ __launch_bounds__(256) void rmsnorm_kernel(const float* __restrict__ w)
{
    int row = blockIdx.x;
    const float* y = g_yg + (size_t)row * DINNER;
    float* o = g_yn + (size_t)row * DINNER;
    int tid = threadIdx.x;
    float ss = 0.f;
#pragma unroll
    for (int it = 0; it < 4; it++) {
        float4 v = *(const float4*)(y + it * 1024 + tid * 4);
        ss += v.x * v.x + v.y * v.y + v.z * v.z + v.w * v.w;
    }
#pragma unroll
    for (int off = 16; off; off >>= 1) ss += __shfl_xor_sync(0xFFFFFFFFu, ss, off);
    __shared__ float red[8];
    if ((tid & 31) == 0) red[tid >> 5] = ss;
    __syncthreads();
    float tot = 0.f;
#pragma unroll
    for (int i = 0; i < 8; i++) tot += red[i];
    float scale = rsqrtf(tot / (float)DINNER + EPSV);
#pragma unroll
    for (int it = 0; it < 4; it++) {
        int i = it * 1024 + tid * 4;
        float4 v = *(const float4*)(y + i);
        float4 wv = *(const float4*)(w + i);
        *(float4*)(o + i) = make_float4(v.x * scale * wv.x, v.y * scale * wv.y,
                                        v.z * scale * wv.z, v.w * scale * wv.w);
    }
}

// ---------------- launch ----------------
extern "C" void kernel_launch(void* const* d_in, const int* in_sizes, int n_in,
                              void* d_out, int out_size)
{
    const float* x          = (const float*)d_in[0];
    const float* in_proj_w  = (const float*)d_in[1];
    const float* conv_w     = (const float*)d_in[2];
    const float* conv_b     = (const float*)d_in[3];
    const float* dt_bias    = (const float*)d_in[4];
    const float* A_log      = (const float*)d_in[5];
    const float* Dp         = (const float*)d_in[6];
    const float* norm_w     = (const float*)d_in[7];
    const float* out_proj_w = (const float*)d_in[8];
    float* out = (float*)d_out;

    float *zx_p = nullptr, *yn_p = nullptr;
    cudaGetSymbolAddress((void**)&zx_p, g_zx);
    cudaGetSymbolAddress((void**)&yn_p, g_yn);

    const int M = B_SZ * SEQL; // 4096

    // 1) in_proj GEMM: (4096 x 2048) x (8512 x 2048)^T
    sgemm_abt<<<dim3((D_IN_PROJ + 127) / 128, M / 128), 256>>>(
        x, in_proj_w, zx_p, M, D_IN_PROJ, DMODEL);

    // 2) depthwise causal conv + silu
    conv_silu_kernel<<<dim3(CONV_DIM / 128, B_SZ, SEQL / 256), 128>>>(conv_w, conv_b);

    // 3) dt softplus + per-chunk cumsum of dA
    dt_scan_kernel<<<B_SZ * NHEADS * NCHUNK, CHUNKL>>>(dt_bias, A_log);

    // 4) per-chunk states
    states_kernel<<<B_SZ * NCHUNK * NHEADS, 256>>>();

    // 5) inter-chunk recurrence
    prev_kernel<<<B_SZ * NHEADS, 256>>>();

    // 6) Y (diag + off) + gate
    const int YSMEM = (2 * 128 * 68 + 2 * 64 * 68 + 256) * sizeof(float); // 105472
    cudaFuncSetAttribute(y_kernel, cudaFuncAttributeMaxDynamicSharedMemorySize, YSMEM);
    y_kernel<<<B_SZ * NCHUNK * NHEADS * 4, 256, YSMEM>>>(Dp);

    // 7) RMSNorm
    rmsnorm_kernel<<<B_SZ * SEQL, 256>>>(norm_w);

    // 8) out_proj GEMM: (4096 x 4096) x (2048 x 4096)^T
    sgemm_abt<<<dim3(DMODEL / 128, M / 128), 256>>>(
        yn_p, out_proj_w, out, M, DMODEL, DINNER);

    (void)in_sizes; (void)n_in; (void)out_size;
}

// round 4
// speedup vs baseline: 1.7865x; 1.7865x over previous
#include <cuda_runtime.h>
#include <cuda_bf16.h>
#include <cstdint>

#define B_SZ 2
#define SEQL 2048
#define DMODEL 2048
#define DINNER 4096
#define DSTATE 128
#define HEADDIM 64
#define NHEADS 64
#define CHUNKL 256
#define NCHUNK 8
#define CONV_DIM 4352     // DINNER + 2*DSTATE
#define D_IN_PROJ 8512    // 2*DINNER + 2*DSTATE + NHEADS
#define DIP_PAD 8576      // 67*128
#define EPSV 1e-5f

// ---------------- scratch ----------------
__device__ float g_zx[B_SZ*SEQL*D_IN_PROJ];
__device__ float g_xBC[B_SZ*SEQL*CONV_DIM];
__device__ float g_dt[B_SZ*SEQL*NHEADS];
__device__ float g_Acs[B_SZ*NHEADS*NCHUNK*CHUNKL];
__device__ float g_states[(size_t)B_SZ*NCHUNK*NHEADS*HEADDIM*DSTATE];
__device__ float g_prev[(size_t)B_SZ*NCHUNK*NHEADS*HEADDIM*DSTATE];
__device__ float g_yg[B_SZ*SEQL*DINNER];
// bf16 hi/lo operands for tensor-core GEMMs
__device__ __nv_bfloat16 g_xh[B_SZ*SEQL*DMODEL];
__device__ __nv_bfloat16 g_xl[B_SZ*SEQL*DMODEL];
__device__ __nv_bfloat16 g_wih[(size_t)DIP_PAD*DMODEL];
__device__ __nv_bfloat16 g_wil[(size_t)DIP_PAD*DMODEL];
__device__ __nv_bfloat16 g_ynh[B_SZ*SEQL*DINNER];
__device__ __nv_bfloat16 g_ynl[B_SZ*SEQL*DINNER];
__device__ __nv_bfloat16 g_owh[(size_t)DMODEL*DINNER];
__device__ __nv_bfloat16 g_owl[(size_t)DMODEL*DINNER];

__device__ __forceinline__ float siluf(float a) { return a / (1.f + expf(-a)); }

// ================= bf16-split HMMA GEMM: C[M,N] = A[M,K] * B[N,K]^T =================
// Block tile 128x128, BK=32, 2-stage cp.async double buffer.
// Smem operand layout: 128 rows x 20 words (16 bf16-pairs data + 4 pad) -> conflict-free.
#define ROWW 20                       // words per smem row (32 bf16 data + 8 pad)
#define OPW  (128 * ROWW)             // words per operand  (2560)
#define STGW (4 * OPW)                // words per stage    (10240)
#define GEMM_SMEM (2 * STGW * 4)      // bytes (81920)

__device__ __forceinline__ void mma16816(float* c, const uint32_t* a, const uint32_t* b) {
    asm volatile(
        "mma.sync.aligned.m16n8k16.row.col.f32.bf16.bf16.f32 "
        "{%0,%1,%2,%3}, {%4,%5,%6,%7}, {%8,%9}, {%0,%1,%2,%3};"
        : "+f"(c[0]), "+f"(c[1]), "+f"(c[2]), "+f"(c[3])
        : "r"(a[0]), "r"(a[1]), "r"(a[2]), "r"(a[3]), "r"(b[0]), "r"(b[1]));
}

__device__ __forceinline__ void cp16(uint32_t dst, const void* src) {
    asm volatile("cp.async.cg.shared.global [%0], [%1], 16;" :: "r"(dst), "l"(src));
}
__device__ __forceinline__ uint32_t smem_u32(const void* p) {
    uint32_t a;
    asm("{ .reg .u64 t; cvta.to.shared.u64 t, %1; cvt.u32.u64 %0, t; }" : "=r"(a) : "l"(p));
    return a;
}

// load one 128x32 bf16 tile into smem operand slot (rows stride ROWW words)
__device__ __forceinline__ void load_op(uint32_t sbase_b, const __nv_bfloat16* g, int ldk, int tid) {
#pragma unroll
    for (int it = 0; it < 2; it++) {
        int v = tid + (it << 8);        // 0..511
        int r = v >> 2, ch = v & 3;     // row, 16B chunk
        cp16(sbase_b + (r * ROWW + ch * 4) * 4, g + (size_t)r * ldk + (ch << 3));
    }
}

__global__ __launch_bounds__(256) void gemm_hmma_split(
    const __nv_bfloat16* __restrict__ Ah, const __nv_bfloat16* __restrict__ Al,
    const __nv_bfloat16* __restrict__ Bh, const __nv_bfloat16* __restrict__ Bl,
    float* __restrict__ C, int M, int Nreal, int K)
{
    extern __shared__ uint32_t sw[];
    const uint32_t sb = smem_u32(sw);
    const int tid = threadIdx.x, wid = tid >> 5, lane = tid & 31;
    const int warp_m = wid & 1, warp_n = wid >> 1;      // 2 x 4 warps
    const int m0 = blockIdx.y << 7, n0 = blockIdx.x << 7;
    const int KT = K >> 5;                               // BK=32 stages

    const __nv_bfloat16* Abh = Ah + (size_t)m0 * K;
    const __nv_bfloat16* Abl = Al + (size_t)m0 * K;
    const __nv_bfloat16* Bbh = Bh + (size_t)n0 * K;
    const __nv_bfloat16* Bbl = Bl + (size_t)n0 * K;

    float acc[4][4][4];
#pragma unroll
    for (int i = 0; i < 4; i++)
#pragma unroll
        for (int j = 0; j < 4; j++)
#pragma unroll
            for (int q = 0; q < 4; q++) acc[i][j][q] = 0.f;

    // prologue: stage 0
    {
        load_op(sb + (0 * STGW + 0 * OPW) * 4, Abh, K, tid);
        load_op(sb + (0 * STGW + 1 * OPW) * 4, Abl, K, tid);
        load_op(sb + (0 * STGW + 2 * OPW) * 4, Bbh, K, tid);
        load_op(sb + (0 * STGW + 3 * OPW) * 4, Bbl, K, tid);
        asm volatile("cp.async.commit_group;" ::: "memory");
    }

    const int arow = warp_m * 64 + (lane >> 2);          // + mi*16 (+8)
    const int brow = warp_n * 32 + (lane >> 2);          // + ni*8
    const int kwl  = lane & 3;                           // word within k-group

    for (int kt = 0; kt < KT; kt++) {
        if (kt + 1 < KT) {
            int s = (kt + 1) & 1;
            int koff = (kt + 1) << 5;
            load_op(sb + (s * STGW + 0 * OPW) * 4, Abh + koff, K, tid);
            load_op(sb + (s * STGW + 1 * OPW) * 4, Abl + koff, K, tid);
            load_op(sb + (s * STGW + 2 * OPW) * 4, Bbh + koff, K, tid);
            load_op(sb + (s * STGW + 3 * OPW) * 4, Bbl + koff, K, tid);
            asm volatile("cp.async.commit_group;" ::: "memory");
            asm volatile("cp.async.wait_group 1;" ::: "memory");
        } else {
            asm volatile("cp.async.wait_group 0;" ::: "memory");
        }
        __syncthreads();

        const uint32_t* stg = sw + ((kt & 1) ? STGW : 0);
        const uint32_t* sAh = stg;
        const uint32_t* sAl = stg + OPW;
        const uint32_t* sBh = stg + 2 * OPW;
        const uint32_t* sBl = stg + 3 * OPW;

#pragma unroll
        for (int kk = 0; kk < 2; kk++) {                 // two k16 per stage
            const int k0w = kk << 3;                     // 16 bf16 = 8 words
            uint32_t ah[4][4], al[4][4], bh[4][2], bl[4][2];
#pragma unroll
            for (int mi = 0; mi < 4; mi++) {
                int r0 = (arow + mi * 16) * ROWW + k0w + kwl;
                int r1 = r0 + 8 * ROWW;
                ah[mi][0] = sAh[r0];     ah[mi][1] = sAh[r1];
                ah[mi][2] = sAh[r0 + 4]; ah[mi][3] = sAh[r1 + 4];
                al[mi][0] = sAl[r0];     al[mi][1] = sAl[r1];
                al[mi][2] = sAl[r0 + 4]; al[mi][3] = sAl[r1 + 4];
            }
#pragma unroll
            for (int ni = 0; ni < 4; ni++) {
                int r0 = (brow + ni * 8) * ROWW + k0w + kwl;
                bh[ni][0] = sBh[r0]; bh[ni][1] = sBh[r0 + 4];
                bl[ni][0] = sBl[r0]; bl[ni][1] = sBl[r0 + 4];
            }
#pragma unroll
            for (int mi = 0; mi < 4; mi++)
#pragma unroll
                for (int ni = 0; ni < 4; ni++) {
                    mma16816(acc[mi][ni], ah[mi], bh[ni]);
                    mma16816(acc[mi][ni], ah[mi], bl[ni]);
                    mma16816(acc[mi][ni], al[mi], bh[ni]);
                }
        }
        __syncthreads();
    }

    // epilogue: direct stores (C fragment: c0,c1 @ (r, n,n+1); c2,c3 @ (r+8, n,n+1))
#pragma unroll
    for (int mi = 0; mi < 4; mi++) {
        int rg0 = m0 + warp_m * 64 + mi * 16 + (lane >> 2);
#pragma unroll
        for (int ni = 0; ni < 4; ni++) {
            int cg = n0 + warp_n * 32 + ni * 8 + ((lane & 3) << 1);
            if (cg < Nreal) {
                *(float2*)(C + (size_t)rg0 * Nreal + cg) =
                    make_float2(acc[mi][ni][0], acc[mi][ni][1]);
                *(float2*)(C + (size_t)(rg0 + 8) * Nreal + cg) =
                    make_float2(acc[mi][ni][2], acc[mi][ni][3]);
            }
        }
    }
}

// ---------------- fp32 -> bf16 hi/lo split (with zero-pad tail) ----------------
__global__ void cvt_split(const float* __restrict__ src, __nv_bfloat16* __restrict__ hi,
                          __nv_bfloat16* __restrict__ lo, long n_src, long n_tot)
{
    long i = ((long)blockIdx.x * 256 + threadIdx.x) * 4;
    if (i >= n_tot) return;
    float4 v = (i < n_src) ? *(const float4*)(src + i) : make_float4(0.f, 0.f, 0.f, 0.f);
    float vv[4] = {v.x, v.y, v.z, v.w};
    __nv_bfloat16 h[4], l[4];
#pragma unroll
    for (int j = 0; j < 4; j++) {
        h[j] = __float2bfloat16(vv[j]);
        l[j] = __float2bfloat16(vv[j] - __bfloat162float(h[j]));
    }
    __nv_bfloat162* hp = (__nv_bfloat162*)(hi + i);
    __nv_bfloat162* lp = (__nv_bfloat162*)(lo + i);
    hp[0] = __nv_bfloat162(h[0], h[1]); hp[1] = __nv_bfloat162(h[2], h[3]);
    lp[0] = __nv_bfloat162(l[0], l[1]); lp[1] = __nv_bfloat162(l[2], l[3]);
}

// ---------------- causal depthwise conv (width 4) + silu ----------------
__global__ void conv_silu_kernel(const float* __restrict__ conv_w,
                                 const float* __restrict__ conv_b)
{
    int c = blockIdx.x * 128 + threadIdx.x;
    int b = blockIdx.y;
    int t0 = blockIdx.z * 256;
    float w0 = conv_w[c * 4 + 0], w1 = conv_w[c * 4 + 1];
    float w2 = conv_w[c * 4 + 2], w3 = conv_w[c * 4 + 3];
    float bias = conv_b[c];
    const float* src = g_zx + (size_t)b * SEQL * D_IN_PROJ + DINNER + c;
    float* dst = g_xBC + (size_t)b * SEQL * CONV_DIM + c;
    float x0 = (t0 >= 3) ? src[(size_t)(t0 - 3) * D_IN_PROJ] : 0.f;
    float x1 = (t0 >= 2) ? src[(size_t)(t0 - 2) * D_IN_PROJ] : 0.f;
    float x2 = (t0 >= 1) ? src[(size_t)(t0 - 1) * D_IN_PROJ] : 0.f;
    for (int t = t0; t < t0 + 256; t++) {
        float x3 = src[(size_t)t * D_IN_PROJ];
        float a = bias + w0 * x0 + w1 * x1 + w2 * x2 + w3 * x3;
        dst[(size_t)t * CONV_DIM] = siluf(a);
        x0 = x1; x1 = x2; x2 = x3;
    }
}

// ---------------- dt softplus + per-chunk cumsum of dA ----------------
__global__ void dt_scan_kernel(const float* __restrict__ dt_bias,
                               const float* __restrict__ A_log)
{
    int idx = blockIdx.x;
    int c = idx % NCHUNK; idx /= NCHUNK;
    int h = idx % NHEADS;
    int b = idx / NHEADS;
    int l = threadIdx.x;
    int t = c * CHUNKL + l;
    float raw = g_zx[(size_t)(b * SEQL + t) * D_IN_PROJ + DINNER + CONV_DIM + h];
    float xv = raw + dt_bias[h];
    float dt = (xv > 20.f) ? xv : log1pf(expf(xv));
    g_dt[(b * SEQL + t) * NHEADS + h] = dt;
    float dA = dt * (-expf(A_log[h]));
    __shared__ float s[CHUNKL];
    s[l] = dA;
    __syncthreads();
    for (int off = 1; off < CHUNKL; off <<= 1) {
        float v = (l >= off) ? s[l - off] : 0.f;
        __syncthreads();
        s[l] += v;
        __syncthreads();
    }
    g_Acs[((b * NHEADS + h) * NCHUNK + c) * CHUNKL + l] = s[l];
}

// ---------------- per-chunk states ----------------
__global__ __launch_bounds__(256) void states_kernel()
{
    __shared__ float Bd[32][132];
    __shared__ float Xs[32][68];
    __shared__ float dec[32];
    __shared__ float dts[32];
    int idx = blockIdx.x;
    int h = idx % NHEADS; idx /= NHEADS;
    int c = idx % NCHUNK;
    int b = idx / NCHUNK;
    int tid = threadIdx.x;
    int tx = tid & 15, ty = tid >> 4;
    const float* acs = g_Acs + ((b * NHEADS + h) * NCHUNK + c) * CHUNKL;
    float acs_last = acs[CHUNKL - 1];
    float acc[4][8];
#pragma unroll
    for (int i = 0; i < 4; i++)
#pragma unroll
        for (int j = 0; j < 8; j++) acc[i][j] = 0.f;

    for (int l0 = 0; l0 < CHUNKL; l0 += 32) {
        if (tid < 32) {
            int t = c * CHUNKL + l0 + tid;
            dec[tid] = expf(acs_last - acs[l0 + tid]);
            dts[tid] = g_dt[(b * SEQL + t) * NHEADS + h];
        }
        __syncthreads();
#pragma unroll
        for (int it = 0; it < 4; it++) {
            int v = tid + it * 256;
            int r = v >> 5, nn = (v & 31) << 2;
            int t = c * CHUNKL + l0 + r;
            float4 f = *(const float4*)(g_xBC + (size_t)(b * SEQL + t) * CONV_DIM + DINNER + nn);
            float d = dec[r];
            Bd[r][nn + 0] = f.x * d; Bd[r][nn + 1] = f.y * d;
            Bd[r][nn + 2] = f.z * d; Bd[r][nn + 3] = f.w * d;
        }
#pragma unroll
        for (int it = 0; it < 2; it++) {
            int v = tid + it * 256;
            int r = v >> 4, pp = (v & 15) << 2;
            int t = c * CHUNKL + l0 + r;
            float4 f = *(const float4*)(g_xBC + (size_t)(b * SEQL + t) * CONV_DIM + h * HEADDIM + pp);
            float d = dts[r];
            *(float4*)&Xs[r][pp] = make_float4(f.x * d, f.y * d, f.z * d, f.w * d);
        }
        __syncthreads();
#pragma unroll
        for (int l = 0; l < 32; l++) {
            float a[4], bb[8];
            *(float4*)a = *(const float4*)&Xs[l][ty * 4];
            *(float4*)(bb)     = *(const float4*)&Bd[l][tx * 8];
            *(float4*)(bb + 4) = *(const float4*)&Bd[l][tx * 8 + 4];
#pragma unroll
            for (int i = 0; i < 4; i++)
#pragma unroll
                for (int j = 0; j < 8; j++) acc[i][j] += a[i] * bb[j];
        }
        __syncthreads();
    }
    float* out = g_states + (size_t)((b * NCHUNK + c) * NHEADS + h) * HEADDIM * DSTATE;
#pragma unroll
    for (int i = 0; i < 4; i++)
#pragma unroll
        for (int j = 0; j < 8; j += 4)
            *(float4*)(out + (ty * 4 + i) * DSTATE + tx * 8 + j) =
                make_float4(acc[i][j], acc[i][j+1], acc[i][j+2], acc[i][j+3]);
}

// ---------------- inter-chunk recurrence ----------------
__global__ __launch_bounds__(256) void prev_kernel()
{
    int b = blockIdx.x >> 6;
    int h = blockIdx.x & 63;
    int tid = threadIdx.x;
    float P[32];
#pragma unroll
    for (int i = 0; i < 32; i++) P[i] = 0.f;
    for (int c = 0; c < NCHUNK; c++) {
        float decay = expf(g_Acs[((b * NHEADS + h) * NCHUNK + c) * CHUNKL + CHUNKL - 1]);
        size_t base = (size_t)((b * NCHUNK + c) * NHEADS + h) * HEADDIM * DSTATE;
#pragma unroll
        for (int i = 0; i < 32; i++) {
            int e = i * 256 + tid;
            g_prev[base + e] = P[i];
            P[i] = P[i] * decay + g_states[base + e];
        }
    }
}

// ---------------- Y (diag + off) + gate ----------------
__global__ __launch_bounds__(256, 2) void y_kernel(const float* __restrict__ Dp)
{
    extern __shared__ float sm[];
    float* Cst = sm;
    float* Bst = Cst + 128 * 68;
    float* Xs  = Bst + 128 * 68;
    float* St  = Xs  + 64 * 68;
    float* acs = St  + 64 * 68;

    int idx = blockIdx.x;
    int lt = idx & 3; idx >>= 2;
    int h = idx % NHEADS; idx /= NHEADS;
    int c = idx % NCHUNK;
    int b = idx / NCHUNK;
    int tid = threadIdx.x;
    int tx = tid & 15, ty = tid >> 4;
    int l0 = lt * 64;

    const float* acs_g = g_Acs + ((b * NHEADS + h) * NCHUNK + c) * CHUNKL;
    acs[tid] = acs_g[tid];

#pragma unroll
    for (int it = 0; it < 8; it++) {
        int v = tid + it * 256;
        int r = v >> 5, nn = (v & 31) << 2;
        int t = c * CHUNKL + l0 + r;
        float4 f = *(const float4*)(g_xBC + (size_t)(b * SEQL + t) * CONV_DIM + DINNER + DSTATE + nn);
        Cst[(nn + 0) * 68 + r] = f.x; Cst[(nn + 1) * 68 + r] = f.y;
        Cst[(nn + 2) * 68 + r] = f.z; Cst[(nn + 3) * 68 + r] = f.w;
    }
    __syncthreads();

    float Yacc[4][4];
#pragma unroll
    for (int i = 0; i < 4; i++)
#pragma unroll
        for (int j = 0; j < 4; j++) Yacc[i][j] = 0.f;

    for (int st = 0; st <= lt; st++) {
        int s0 = st * 64;
#pragma unroll
        for (int it = 0; it < 8; it++) {
            int v = tid + it * 256;
            int r = v >> 5, nn = (v & 31) << 2;
            int t = c * CHUNKL + s0 + r;
            float4 f = *(const float4*)(g_xBC + (size_t)(b * SEQL + t) * CONV_DIM + DINNER + nn);
            Bst[(nn + 0) * 68 + r] = f.x; Bst[(nn + 1) * 68 + r] = f.y;
            Bst[(nn + 2) * 68 + r] = f.z; Bst[(nn + 3) * 68 + r] = f.w;
        }
#pragma unroll
        for (int it = 0; it < 4; it++) {
            int v = tid + it * 256;
            int r = v >> 4, pp = (v & 15) << 2;
            int t = c * CHUNKL + s0 + r;
            float4 f = *(const float4*)(g_xBC + (size_t)(b * SEQL + t) * CONV_DIM + h * HEADDIM + pp);
            float d = g_dt[(b * SEQL + t) * NHEADS + h];
            *(float4*)&Xs[r * 68 + pp] = make_float4(f.x * d, f.y * d, f.z * d, f.w * d);
        }
        __syncthreads();

        float sacc[4][4];
#pragma unroll
        for (int i = 0; i < 4; i++)
#pragma unroll
            for (int j = 0; j < 4; j++) sacc[i][j] = 0.f;
#pragma unroll 4
        for (int n = 0; n < 128; n++) {
            float4 a4 = *(const float4*)&Cst[n * 68 + (ty << 2)];
            float4 b4 = *(const float4*)&Bst[n * 68 + (tx << 2)];
            float a[4] = {a4.x, a4.y, a4.z, a4.w};
            float bb[4] = {b4.x, b4.y, b4.z, b4.w};
#pragma unroll
            for (int i = 0; i < 4; i++)
#pragma unroll
                for (int j = 0; j < 4; j++) sacc[i][j] += a[i] * bb[j];
        }
#pragma unroll
        for (int j = 0; j < 4; j++) {
            int sg = s0 + (tx << 2) + j;
            float col[4];
#pragma unroll
            for (int i = 0; i < 4; i++) {
                int lg = l0 + (ty << 2) + i;
                col[i] = (sg <= lg) ? sacc[i][j] * expf(acs[lg] - acs[sg]) : 0.f;
            }
            *(float4*)&St[((tx << 2) + j) * 68 + (ty << 2)] =
                make_float4(col[0], col[1], col[2], col[3]);
        }
        __syncthreads();
#pragma unroll 4
        for (int s = 0; s < 64; s++) {
            float4 a4 = *(const float4*)&St[s * 68 + (ty << 2)];
            float4 x4 = *(const float4*)&Xs[s * 68 + (tx << 2)];
            float a[4] = {a4.x, a4.y, a4.z, a4.w};
            float xx[4] = {x4.x, x4.y, x4.z, x4.w};
#pragma unroll
            for (int i = 0; i < 4; i++)
#pragma unroll
                for (int j = 0; j < 4; j++) Yacc[i][j] += a[i] * xx[j];
        }
        __syncthreads();
    }

    size_t pbase = (size_t)((b * NCHUNK + c) * NHEADS + h) * HEADDIM * DSTATE;
#pragma unroll
    for (int it = 0; it < 8; it++) {
        int v = tid + it * 256;
        int p = v >> 5, nn = (v & 31) << 2;
        float4 f = *(const float4*)(g_prev + pbase + p * DSTATE + nn);
        Bst[(nn + 0) * 68 + p] = f.x; Bst[(nn + 1) * 68 + p] = f.y;
        Bst[(nn + 2) * 68 + p] = f.z; Bst[(nn + 3) * 68 + p] = f.w;
    }
    __syncthreads();
    float toff[4][4];
#pragma unroll
    for (int i = 0; i < 4; i++)
#pragma unroll
        for (int j = 0; j < 4; j++) toff[i][j] = 0.f;
#pragma unroll 4
    for (int n = 0; n < 128; n++) {
        float4 a4 = *(const float4*)&Cst[n * 68 + (ty << 2)];
        float4 b4 = *(const float4*)&Bst[n * 68 + (tx << 2)];
        float a[4] = {a4.x, a4.y, a4.z, a4.w};
        float bb[4] = {b4.x, b4.y, b4.z, b4.w};
#pragma unroll
        for (int i = 0; i < 4; i++)
#pragma unroll
            for (int j = 0; j < 4; j++) toff[i][j] += a[i] * bb[j];
    }

    float Dh = Dp[h];
#pragma unroll
    for (int i = 0; i < 4; i++) {
        int lg = l0 + (ty << 2) + i;
        int t = c * CHUNKL + lg;
        float el = expf(acs[lg]);
        float4 xs4 = *(const float4*)(g_xBC + (size_t)(b * SEQL + t) * CONV_DIM + h * HEADDIM + (tx << 2));
        float4 z4  = *(const float4*)(g_zx + (size_t)(b * SEQL + t) * D_IN_PROJ + h * HEADDIM + (tx << 2));
        float4 o;
        o.x = (Yacc[i][0] + el * toff[i][0] + xs4.x * Dh) * siluf(z4.x);
        o.y = (Yacc[i][1] + el * toff[i][1] + xs4.y * Dh) * siluf(z4.y);
        o.z = (Yacc[i][2] + el * toff[i][2] + xs4.z * Dh) * siluf(z4.z);
        o.w = (Yacc[i][3] + el * toff[i][3] + xs4.w * Dh) * siluf(z4.w);
        *(float4*)(g_yg + (size_t)(b * SEQL + t) * DINNER + h * HEADDIM + (tx << 2)) = o;
    }
}

// ---------------- RMSNorm -> bf16 hi/lo ----------------
__global__ __launch_bounds__(256) void rmsnorm_kernel(const float* __restrict__ w)
{
    int row = blockIdx.x;
    const float* y = g_yg + (size_t)row * DINNER;
    __nv_bfloat16* oh = g_ynh + (size_t)row * DINNER;
    __nv_bfloat16* ol = g_ynl + (size_t)row * DINNER;
    int tid = threadIdx.x;
    float ss = 0.f;
#pragma unroll
    for (int it = 0; it < 4; it++) {
        float4 v = *(const float4*)(y + it * 1024 + tid * 4);
        ss += v.x * v.x + v.y * v.y + v.z * v.z + v.w * v.w;
    }
#pragma unroll
    for (int off = 16; off; off >>= 1) ss += __shfl_xor_sync(0xFFFFFFFFu, ss, off);
    __shared__ float red[8];
    if ((tid & 31) == 0) red[tid >> 5] = ss;
    __syncthreads();
    float tot = 0.f;
#pragma unroll
    for (int i = 0; i < 8; i++) tot += red[i];
    float scale = rsqrtf(tot / (float)DINNER + EPSV);
#pragma unroll
    for (int it = 0; it < 4; it++) {
        int i = it * 1024 + tid * 4;
        float4 v = *(const float4*)(y + i);
        float4 wv = *(const float4*)(w + i);
        float o[4] = {v.x * scale * wv.x, v.y * scale * wv.y,
                      v.z * scale * wv.z, v.w * scale * wv.w};
        __nv_bfloat16 h[4], l[4];
#pragma unroll
        for (int j = 0; j < 4; j++) {
            h[j] = __float2bfloat16(o[j]);
            l[j] = __float2bfloat16(o[j] - __bfloat162float(h[j]));
        }
        __nv_bfloat162* hp = (__nv_bfloat162*)(oh + i);
        __nv_bfloat162* lp = (__nv_bfloat162*)(ol + i);
        hp[0] = __nv_bfloat162(h[0], h[1]); hp[1] = __nv_bfloat162(h[2], h[3]);
        lp[0] = __nv_bfloat162(l[0], l[1]); lp[1] = __nv_bfloat162(l[2], l[3]);
    }
}

// ---------------- launch ----------------
extern "C" void kernel_launch(void* const* d_in, const int* in_sizes, int n_in,
                              void* d_out, int out_size)
{
    const float* x          = (const float*)d_in[0];
    const float* in_proj_w  = (const float*)d_in[1];
    const float* conv_w     = (const float*)d_in[2];
    const float* conv_b     = (const float*)d_in[3];
    const float* dt_bias    = (const float*)d_in[4];
    const float* A_log      = (const float*)d_in[5];
    const float* Dp         = (const float*)d_in[6];
    const float* norm_w     = (const float*)d_in[7];
    const float* out_proj_w = (const float*)d_in[8];
    float* out = (float*)d_out;

    float *zx_p = nullptr;
    __nv_bfloat16 *xh_p, *xl_p, *wih_p, *wil_p, *ynh_p, *ynl_p, *owh_p, *owl_p;
    cudaGetSymbolAddress((void**)&zx_p, g_zx);
    cudaGetSymbolAddress((void**)&xh_p, g_xh);
    cudaGetSymbolAddress((void**)&xl_p, g_xl);
    cudaGetSymbolAddress((void**)&wih_p, g_wih);
    cudaGetSymbolAddress((void**)&wil_p, g_wil);
    cudaGetSymbolAddress((void**)&ynh_p, g_ynh);
    cudaGetSymbolAddress((void**)&ynl_p, g_ynl);
    cudaGetSymbolAddress((void**)&owh_p, g_owh);
    cudaGetSymbolAddress((void**)&owl_p, g_owl);

    static bool attr_set = false;
    if (!attr_set) {
        cudaFuncSetAttribute(gemm_hmma_split, cudaFuncAttributeMaxDynamicSharedMemorySize, GEMM_SMEM);
        const int YS = (2 * 128 * 68 + 2 * 64 * 68 + 256) * sizeof(float);
        cudaFuncSetAttribute(y_kernel, cudaFuncAttributeMaxDynamicSharedMemorySize, YS);
        attr_set = true;
    }

    const int M = B_SZ * SEQL; // 4096

    // converts
    {
        long n = (long)M * DMODEL;
        cvt_split<<<(unsigned)((n / 4 + 255) / 256), 256>>>(x, xh_p, xl_p, n, n);
    }
    {
        long ns = (long)D_IN_PROJ * DMODEL, nt = (long)DIP_PAD * DMODEL;
        cvt_split<<<(unsigned)((nt / 4 + 255) / 256), 256>>>(in_proj_w, wih_p, wil_p, ns, nt);
    }
    {
        long n = (long)DMODEL * DINNER;
        cvt_split<<<(unsigned)((n / 4 + 255) / 256), 256>>>(out_proj_w, owh_p, owl_p, n, n);
    }

    // 1) in_proj GEMM (HMMA): (4096 x 2048) x (8512 x 2048)^T
    gemm_hmma_split<<<dim3(DIP_PAD / 128, M / 128), 256, GEMM_SMEM>>>(
        xh_p, xl_p, wih_p, wil_p, zx_p, M, D_IN_PROJ, DMODEL);

    // 2) conv + silu
    conv_silu_kernel<<<dim3(CONV_DIM / 128, B_SZ, SEQL / 256), 128>>>(conv_w, conv_b);

    // 3) dt softplus + cumsum
    dt_scan_kernel<<<B_SZ * NHEADS * NCHUNK, CHUNKL>>>(dt_bias, A_log);

    // 4) states
    states_kernel<<<B_SZ * NCHUNK * NHEADS, 256>>>();

    // 5) recurrence
    prev_kernel<<<B_SZ * NHEADS, 256>>>();

    // 6) Y + gate
    const int YS = (2 * 128 * 68 + 2 * 64 * 68 + 256) * sizeof(float);
    y_kernel<<<B_SZ * NCHUNK * NHEADS * 4, 256, YS>>>(Dp);

    // 7) RMSNorm -> bf16 hi/lo
    rmsnorm_kernel<<<B_SZ * SEQL, 256>>>(norm_w);

    // 8) out_proj GEMM (HMMA): (4096 x 4096) x (2048 x 4096)^T
    gemm_hmma_split<<<dim3(DMODEL / 128, M / 128), 256, GEMM_SMEM>>>(
        ynh_p, ynl_p, owh_p, owl_p, out, M, DMODEL, DINNER);

    (void)in_sizes; (void)n_in; (void)out_size;
}

// round 5
// speedup vs baseline: 2.0219x; 1.1318x over previous
#include <cuda_runtime.h>
#include <cuda_bf16.h>
#include <cstdint>

#define B_SZ 2
#define SEQL 2048
#define DMODEL 2048
#define DINNER 4096
#define DSTATE 128
#define HEADDIM 64
#define NHEADS 64
#define CHUNKL 256
#define NCHUNK 8
#define CONV_DIM 4352     // DINNER + 2*DSTATE
#define D_IN_PROJ 8512    // 2*DINNER + 2*DSTATE + NHEADS
#define DIP_PAD 8576      // 67*128
#define EPSV 1e-5f

// ---------------- scratch ----------------
__device__ float g_zx[B_SZ*SEQL*D_IN_PROJ];
__device__ float g_xBC[B_SZ*SEQL*CONV_DIM];
__device__ float g_dt[B_SZ*SEQL*NHEADS];
__device__ float g_Acs[B_SZ*NHEADS*NCHUNK*CHUNKL];
__device__ float g_states[(size_t)B_SZ*NCHUNK*NHEADS*HEADDIM*DSTATE];
__device__ float g_prev[(size_t)B_SZ*NCHUNK*NHEADS*HEADDIM*DSTATE];
__device__ float g_yg[B_SZ*SEQL*DINNER];
// bf16 hi/lo operands for tensor-core GEMMs
__device__ __nv_bfloat16 g_xh[B_SZ*SEQL*DMODEL];
__device__ __nv_bfloat16 g_xl[B_SZ*SEQL*DMODEL];
__device__ __nv_bfloat16 g_wih[(size_t)DIP_PAD*DMODEL];
__device__ __nv_bfloat16 g_wil[(size_t)DIP_PAD*DMODEL];
__device__ __nv_bfloat16 g_ynh[B_SZ*SEQL*DINNER];
__device__ __nv_bfloat16 g_ynl[B_SZ*SEQL*DINNER];
__device__ __nv_bfloat16 g_owh[(size_t)DMODEL*DINNER];
__device__ __nv_bfloat16 g_owl[(size_t)DMODEL*DINNER];

__device__ __forceinline__ float siluf(float a) { return a / (1.f + expf(-a)); }

// ================= bf16-split HMMA GEMM: C[M,N] = A[M,K] * B[N,K]^T =================
// Block tile 128x128, BK=32, 2-stage cp.async double buffer, 2 CTAs/SM.
#define ROWW 20                       // words per smem row (32 bf16 data + 8 pad)
#define OPW  (128 * ROWW)             // words per operand  (2560)
#define STGW (4 * OPW)                // words per stage    (10240)
#define GEMM_SMEM (2 * STGW * 4)      // bytes (81920)

__device__ __forceinline__ void mma16816(float* c, const uint32_t* a, const uint32_t* b) {
    asm volatile(
        "mma.sync.aligned.m16n8k16.row.col.f32.bf16.bf16.f32 "
        "{%0,%1,%2,%3}, {%4,%5,%6,%7}, {%8,%9}, {%0,%1,%2,%3};"
        : "+f"(c[0]), "+f"(c[1]), "+f"(c[2]), "+f"(c[3])
        : "r"(a[0]), "r"(a[1]), "r"(a[2]), "r"(a[3]), "r"(b[0]), "r"(b[1]));
}
__device__ __forceinline__ void ldsm4(uint32_t* r, uint32_t addr) {
    asm volatile("ldmatrix.sync.aligned.m8n8.x4.shared.b16 {%0,%1,%2,%3}, [%4];"
        : "=r"(r[0]), "=r"(r[1]), "=r"(r[2]), "=r"(r[3]) : "r"(addr));
}
__device__ __forceinline__ void cp16(uint32_t dst, const void* src) {
    asm volatile("cp.async.cg.shared.global [%0], [%1], 16;" :: "r"(dst), "l"(src));
}
__device__ __forceinline__ uint32_t smem_u32(const void* p) {
    uint32_t a;
    asm("{ .reg .u64 t; cvta.to.shared.u64 t, %1; cvt.u32.u64 %0, t; }" : "=r"(a) : "l"(p));
    return a;
}

// load one 128x32 bf16 tile into smem operand slot (rows stride ROWW words)
__device__ __forceinline__ void load_op(uint32_t sbase_b, const __nv_bfloat16* g, int ldk, int tid) {
#pragma unroll
    for (int it = 0; it < 2; it++) {
        int v = tid + (it << 8);        // 0..511
        int r = v >> 2, ch = v & 3;     // row, 16B chunk
        cp16(sbase_b + (r * ROWW + ch * 4) * 4, g + (size_t)r * ldk + (ch << 3));
    }
}

__global__ __launch_bounds__(256, 2) void gemm_hmma_split(
    const __nv_bfloat16* __restrict__ Ah, const __nv_bfloat16* __restrict__ Al,
    const __nv_bfloat16* __restrict__ Bh, const __nv_bfloat16* __restrict__ Bl,
    float* __restrict__ C, int M, int Nreal, int K)
{
    extern __shared__ uint32_t sw[];
    const uint32_t sb = smem_u32(sw);
    const int tid = threadIdx.x, wid = tid >> 5, lane = tid & 31;
    const int warp_m = wid & 1, warp_n = wid >> 1;      // 2 x 4 warps
    const int m0 = blockIdx.y << 7, n0 = blockIdx.x << 7;
    const int KT = K >> 5;                               // BK=32 stages

    const __nv_bfloat16* Abh = Ah + (size_t)m0 * K;
    const __nv_bfloat16* Abl = Al + (size_t)m0 * K;
    const __nv_bfloat16* Bbh = Bh + (size_t)n0 * K;
    const __nv_bfloat16* Bbl = Bl + (size_t)n0 * K;

    float acc[4][4][4];
#pragma unroll
    for (int i = 0; i < 4; i++)
#pragma unroll
        for (int j = 0; j < 4; j++)
#pragma unroll
            for (int q = 0; q < 4; q++) acc[i][j][q] = 0.f;

    // prologue: stage 0
    {
        load_op(sb + (0 * STGW + 0 * OPW) * 4, Abh, K, tid);
        load_op(sb + (0 * STGW + 1 * OPW) * 4, Abl, K, tid);
        load_op(sb + (0 * STGW + 2 * OPW) * 4, Bbh, K, tid);
        load_op(sb + (0 * STGW + 3 * OPW) * 4, Bbl, K, tid);
        asm volatile("cp.async.commit_group;" ::: "memory");
    }

    // ldmatrix per-lane address components
    const int rowA = warp_m * 64 + ((lane >> 3) & 1) * 8 + (lane & 7);  // + mi*16
    const int kwA  = (lane >> 4) * 4;                                    // + k0w
    const int rowB = warp_n * 32 + ((lane >> 4) & 1) * 8 + (lane & 7);  // + np*16
    const int kwB  = ((lane >> 3) & 1) * 4;                              // + k0w

    for (int kt = 0; kt < KT; kt++) {
        if (kt + 1 < KT) {
            int s = (kt + 1) & 1;
            int koff = (kt + 1) << 5;
            load_op(sb + (s * STGW + 0 * OPW) * 4, Abh + koff, K, tid);
            load_op(sb + (s * STGW + 1 * OPW) * 4, Abl + koff, K, tid);
            load_op(sb + (s * STGW + 2 * OPW) * 4, Bbh + koff, K, tid);
            load_op(sb + (s * STGW + 3 * OPW) * 4, Bbl + koff, K, tid);
            asm volatile("cp.async.commit_group;" ::: "memory");
            asm volatile("cp.async.wait_group 1;" ::: "memory");
        } else {
            asm volatile("cp.async.wait_group 0;" ::: "memory");
        }
        __syncthreads();

        const uint32_t stgb = sb + ((kt & 1) ? STGW * 4u : 0u);
        const uint32_t sAh = stgb;
        const uint32_t sAl = stgb + OPW * 4u;
        const uint32_t sBh = stgb + 2u * OPW * 4u;
        const uint32_t sBl = stgb + 3u * OPW * 4u;

#pragma unroll
        for (int kk = 0; kk < 2; kk++) {                 // two k16 per stage
            const int k0w = kk << 3;
            uint32_t ah[4][4], al[4][4];
#pragma unroll
            for (int mi = 0; mi < 4; mi++) {
                uint32_t off = (((rowA + mi * 16) * ROWW) + k0w + kwA) * 4u;
                ldsm4(ah[mi], sAh + off);
                ldsm4(al[mi], sAl + off);
            }
#pragma unroll
            for (int np = 0; np < 2; np++) {             // n-pair: ni = 2*np, 2*np+1
                uint32_t boff = (((rowB + np * 16) * ROWW) + k0w + kwB) * 4u;
                uint32_t bh[4], bl[4];
                ldsm4(bh, sBh + boff);
                ldsm4(bl, sBl + boff);
#pragma unroll
                for (int mi = 0; mi < 4; mi++) {
                    mma16816(acc[mi][2 * np], ah[mi], bh);
                    mma16816(acc[mi][2 * np], ah[mi], bl);
                    mma16816(acc[mi][2 * np], al[mi], bh);
                    mma16816(acc[mi][2 * np + 1], ah[mi], bh + 2);
                    mma16816(acc[mi][2 * np + 1], ah[mi], bl + 2);
                    mma16816(acc[mi][2 * np + 1], al[mi], bh + 2);
                }
            }
        }
        __syncthreads();
    }

    // epilogue: direct stores
#pragma unroll
    for (int mi = 0; mi < 4; mi++) {
        int rg0 = m0 + warp_m * 64 + mi * 16 + (lane >> 2);
#pragma unroll
        for (int ni = 0; ni < 4; ni++) {
            int cg = n0 + warp_n * 32 + ni * 8 + ((lane & 3) << 1);
            if (cg < Nreal) {
                *(float2*)(C + (size_t)rg0 * Nreal + cg) =
                    make_float2(acc[mi][ni][0], acc[mi][ni][1]);
                *(float2*)(C + (size_t)(rg0 + 8) * Nreal + cg) =
                    make_float2(acc[mi][ni][2], acc[mi][ni][3]);
            }
        }
    }
}

// ---------------- fp32 -> bf16 hi/lo split (with zero-pad tail) ----------------
__global__ void cvt_split(const float* __restrict__ src, __nv_bfloat16* __restrict__ hi,
                          __nv_bfloat16* __restrict__ lo, long n_src, long n_tot)
{
    long i = ((long)blockIdx.x * 256 + threadIdx.x) * 4;
    if (i >= n_tot) return;
    float4 v = (i < n_src) ? *(const float4*)(src + i) : make_float4(0.f, 0.f, 0.f, 0.f);
    float vv[4] = {v.x, v.y, v.z, v.w};
    __nv_bfloat16 h[4], l[4];
#pragma unroll
    for (int j = 0; j < 4; j++) {
        h[j] = __float2bfloat16(vv[j]);
        l[j] = __float2bfloat16(vv[j] - __bfloat162float(h[j]));
    }
    __nv_bfloat162* hp = (__nv_bfloat162*)(hi + i);
    __nv_bfloat162* lp = (__nv_bfloat162*)(lo + i);
    hp[0] = __nv_bfloat162(h[0], h[1]); hp[1] = __nv_bfloat162(h[2], h[3]);
    lp[0] = __nv_bfloat162(l[0], l[1]); lp[1] = __nv_bfloat162(l[2], l[3]);
}

// ---------------- causal depthwise conv (width 4) + silu ----------------
__global__ void conv_silu_kernel(const float* __restrict__ conv_w,
                                 const float* __restrict__ conv_b)
{
    int c = blockIdx.x * 128 + threadIdx.x;
    int b = blockIdx.y;
    int t0 = blockIdx.z * 256;
    float w0 = conv_w[c * 4 + 0], w1 = conv_w[c * 4 + 1];
    float w2 = conv_w[c * 4 + 2], w3 = conv_w[c * 4 + 3];
    float bias = conv_b[c];
    const float* src = g_zx + (size_t)b * SEQL * D_IN_PROJ + DINNER + c;
    float* dst = g_xBC + (size_t)b * SEQL * CONV_DIM + c;
    float x0 = (t0 >= 3) ? src[(size_t)(t0 - 3) * D_IN_PROJ] : 0.f;
    float x1 = (t0 >= 2) ? src[(size_t)(t0 - 2) * D_IN_PROJ] : 0.f;
    float x2 = (t0 >= 1) ? src[(size_t)(t0 - 1) * D_IN_PROJ] : 0.f;
    for (int t = t0; t < t0 + 256; t++) {
        float x3 = src[(size_t)t * D_IN_PROJ];
        float a = bias + w0 * x0 + w1 * x1 + w2 * x2 + w3 * x3;
        dst[(size_t)t * CONV_DIM] = siluf(a);
        x0 = x1; x1 = x2; x2 = x3;
    }
}

// ---------------- dt softplus + per-chunk cumsum of dA ----------------
__global__ void dt_scan_kernel(const float* __restrict__ dt_bias,
                               const float* __restrict__ A_log)
{
    int idx = blockIdx.x;
    int c = idx % NCHUNK; idx /= NCHUNK;
    int h = idx % NHEADS;
    int b = idx / NHEADS;
    int l = threadIdx.x;
    int t = c * CHUNKL + l;
    float raw = g_zx[(size_t)(b * SEQL + t) * D_IN_PROJ + DINNER + CONV_DIM + h];
    float xv = raw + dt_bias[h];
    float dt = (xv > 20.f) ? xv : log1pf(expf(xv));
    g_dt[(b * SEQL + t) * NHEADS + h] = dt;
    float dA = dt * (-expf(A_log[h]));
    __shared__ float s[CHUNKL];
    s[l] = dA;
    __syncthreads();
    for (int off = 1; off < CHUNKL; off <<= 1) {
        float v = (l >= off) ? s[l - off] : 0.f;
        __syncthreads();
        s[l] += v;
        __syncthreads();
    }
    g_Acs[((b * NHEADS + h) * NCHUNK + c) * CHUNKL + l] = s[l];
}

// ---------------- per-chunk states ----------------
__global__ __launch_bounds__(256) void states_kernel()
{
    __shared__ float Bd[32][132];
    __shared__ float Xs[32][68];
    __shared__ float dec[32];
    __shared__ float dts[32];
    int idx = blockIdx.x;
    int h = idx % NHEADS; idx /= NHEADS;
    int c = idx % NCHUNK;
    int b = idx / NCHUNK;
    int tid = threadIdx.x;
    int tx = tid & 15, ty = tid >> 4;
    const float* acs = g_Acs + ((b * NHEADS + h) * NCHUNK + c) * CHUNKL;
    float acs_last = acs[CHUNKL - 1];
    float acc[4][8];
#pragma unroll
    for (int i = 0; i < 4; i++)
#pragma unroll
        for (int j = 0; j < 8; j++) acc[i][j] = 0.f;

    for (int l0 = 0; l0 < CHUNKL; l0 += 32) {
        if (tid < 32) {
            int t = c * CHUNKL + l0 + tid;
            dec[tid] = expf(acs_last - acs[l0 + tid]);
            dts[tid] = g_dt[(b * SEQL + t) * NHEADS + h];
        }
        __syncthreads();
#pragma unroll
        for (int it = 0; it < 4; it++) {
            int v = tid + it * 256;
            int r = v >> 5, nn = (v & 31) << 2;
            int t = c * CHUNKL + l0 + r;
            float4 f = *(const float4*)(g_xBC + (size_t)(b * SEQL + t) * CONV_DIM + DINNER + nn);
            float d = dec[r];
            Bd[r][nn + 0] = f.x * d; Bd[r][nn + 1] = f.y * d;
            Bd[r][nn + 2] = f.z * d; Bd[r][nn + 3] = f.w * d;
        }
#pragma unroll
        for (int it = 0; it < 2; it++) {
            int v = tid + it * 256;
            int r = v >> 4, pp = (v & 15) << 2;
            int t = c * CHUNKL + l0 + r;
            float4 f = *(const float4*)(g_xBC + (size_t)(b * SEQL + t) * CONV_DIM + h * HEADDIM + pp);
            float d = dts[r];
            *(float4*)&Xs[r][pp] = make_float4(f.x * d, f.y * d, f.z * d, f.w * d);
        }
        __syncthreads();
#pragma unroll
        for (int l = 0; l < 32; l++) {
            float a[4], bb[8];
            *(float4*)a = *(const float4*)&Xs[l][ty * 4];
            *(float4*)(bb)     = *(const float4*)&Bd[l][tx * 8];
            *(float4*)(bb + 4) = *(const float4*)&Bd[l][tx * 8 + 4];
#pragma unroll
            for (int i = 0; i < 4; i++)
#pragma unroll
                for (int j = 0; j < 8; j++) acc[i][j] += a[i] * bb[j];
        }
        __syncthreads();
    }
    float* out = g_states + (size_t)((b * NCHUNK + c) * NHEADS + h) * HEADDIM * DSTATE;
#pragma unroll
    for (int i = 0; i < 4; i++)
#pragma unroll
        for (int j = 0; j < 8; j += 4)
            *(float4*)(out + (ty * 4 + i) * DSTATE + tx * 8 + j) =
                make_float4(acc[i][j], acc[i][j+1], acc[i][j+2], acc[i][j+3]);
}

// ---------------- inter-chunk recurrence ----------------
__global__ __launch_bounds__(256) void prev_kernel()
{
    int b = blockIdx.x >> 6;
    int h = blockIdx.x & 63;
    int tid = threadIdx.x;
    float P[32];
#pragma unroll
    for (int i = 0; i < 32; i++) P[i] = 0.f;
    for (int c = 0; c < NCHUNK; c++) {
        float decay = expf(g_Acs[((b * NHEADS + h) * NCHUNK + c) * CHUNKL + CHUNKL - 1]);
        size_t base = (size_t)((b * NCHUNK + c) * NHEADS + h) * HEADDIM * DSTATE;
#pragma unroll
        for (int i = 0; i < 32; i++) {
            int e = i * 256 + tid;
            g_prev[base + e] = P[i];
            P[i] = P[i] * decay + g_states[base + e];
        }
    }
}

// ---------------- Y (diag + off) + gate ----------------
__global__ __launch_bounds__(256, 2) void y_kernel(const float* __restrict__ Dp)
{
    extern __shared__ float sm[];
    float* Cst = sm;
    float* Bst = Cst + 128 * 68;
    float* Xs  = Bst + 128 * 68;
    float* St  = Xs  + 64 * 68;
    float* acs = St  + 64 * 68;

    int idx = blockIdx.x;
    int lt = idx & 3; idx >>= 2;
    int h = idx % NHEADS; idx /= NHEADS;
    int c = idx % NCHUNK;
    int b = idx / NCHUNK;
    int tid = threadIdx.x;
    int tx = tid & 15, ty = tid >> 4;
    int l0 = lt * 64;

    const float* acs_g = g_Acs + ((b * NHEADS + h) * NCHUNK + c) * CHUNKL;
    acs[tid] = acs_g[tid];

#pragma unroll
    for (int it = 0; it < 8; it++) {
        int v = tid + it * 256;
        int r = v >> 5, nn = (v & 31) << 2;
        int t = c * CHUNKL + l0 + r;
        float4 f = *(const float4*)(g_xBC + (size_t)(b * SEQL + t) * CONV_DIM + DINNER + DSTATE + nn);
        Cst[(nn + 0) * 68 + r] = f.x; Cst[(nn + 1) * 68 + r] = f.y;
        Cst[(nn + 2) * 68 + r] = f.z; Cst[(nn + 3) * 68 + r] = f.w;
    }
    __syncthreads();

    float Yacc[4][4];
#pragma unroll
    for (int i = 0; i < 4; i++)
#pragma unroll
        for (int j = 0; j < 4; j++) Yacc[i][j] = 0.f;

    for (int st = 0; st <= lt; st++) {
        int s0 = st * 64;
#pragma unroll
        for (int it = 0; it < 8; it++) {
            int v = tid + it * 256;
            int r = v >> 5, nn = (v & 31) << 2;
            int t = c * CHUNKL + s0 + r;
            float4 f = *(const float4*)(g_xBC + (size_t)(b * SEQL + t) * CONV_DIM + DINNER + nn);
            Bst[(nn + 0) * 68 + r] = f.x; Bst[(nn + 1) * 68 + r] = f.y;
            Bst[(nn + 2) * 68 + r] = f.z; Bst[(nn + 3) * 68 + r] = f.w;
        }
#pragma unroll
        for (int it = 0; it < 4; it++) {
            int v = tid + it * 256;
            int r = v >> 4, pp = (v & 15) << 2;
            int t = c * CHUNKL + s0 + r;
            float4 f = *(const float4*)(g_xBC + (size_t)(b * SEQL + t) * CONV_DIM + h * HEADDIM + pp);
            float d = g_dt[(b * SEQL + t) * NHEADS + h];
            *(float4*)&Xs[r * 68 + pp] = make_float4(f.x * d, f.y * d, f.z * d, f.w * d);
        }
        __syncthreads();

        float sacc[4][4];
#pragma unroll
        for (int i = 0; i < 4; i++)
#pragma unroll
            for (int j = 0; j < 4; j++) sacc[i][j] = 0.f;
#pragma unroll 4
        for (int n = 0; n < 128; n++) {
            float4 a4 = *(const float4*)&Cst[n * 68 + (ty << 2)];
            float4 b4 = *(const float4*)&Bst[n * 68 + (tx << 2)];
            float a[4] = {a4.x, a4.y, a4.z, a4.w};
            float bb[4] = {b4.x, b4.y, b4.z, b4.w};
#pragma unroll
            for (int i = 0; i < 4; i++)
#pragma unroll
                for (int j = 0; j < 4; j++) sacc[i][j] += a[i] * bb[j];
        }
#pragma unroll
        for (int j = 0; j < 4; j++) {
            int sg = s0 + (tx << 2) + j;
            float col[4];
#pragma unroll
            for (int i = 0; i < 4; i++) {
                int lg = l0 + (ty << 2) + i;
                col[i] = (sg <= lg) ? sacc[i][j] * expf(acs[lg] - acs[sg]) : 0.f;
            }
            *(float4*)&St[((tx << 2) + j) * 68 + (ty << 2)] =
                make_float4(col[0], col[1], col[2], col[3]);
        }
        __syncthreads();
#pragma unroll 4
        for (int s = 0; s < 64; s++) {
            float4 a4 = *(const float4*)&St[s * 68 + (ty << 2)];
            float4 x4 = *(const float4*)&Xs[s * 68 + (tx << 2)];
            float a[4] = {a4.x, a4.y, a4.z, a4.w};
            float xx[4] = {x4.x, x4.y, x4.z, x4.w};
#pragma unroll
            for (int i = 0; i < 4; i++)
#pragma unroll
                for (int j = 0; j < 4; j++) Yacc[i][j] += a[i] * xx[j];
        }
        __syncthreads();
    }

    size_t pbase = (size_t)((b * NCHUNK + c) * NHEADS + h) * HEADDIM * DSTATE;
#pragma unroll
    for (int it = 0; it < 8; it++) {
        int v = tid + it * 256;
        int p = v >> 5, nn = (v & 31) << 2;
        float4 f = *(const float4*)(g_prev + pbase + p * DSTATE + nn);
        Bst[(nn + 0) * 68 + p] = f.x; Bst[(nn + 1) * 68 + p] = f.y;
        Bst[(nn + 2) * 68 + p] = f.z; Bst[(nn + 3) * 68 + p] = f.w;
    }
    __syncthreads();
    float toff[4][4];
#pragma unroll
    for (int i = 0; i < 4; i++)
#pragma unroll
        for (int j = 0; j < 4; j++) toff[i][j] = 0.f;
#pragma unroll 4
    for (int n = 0; n < 128; n++) {
        float4 a4 = *(const float4*)&Cst[n * 68 + (ty << 2)];
        float4 b4 = *(const float4*)&Bst[n * 68 + (tx << 2)];
        float a[4] = {a4.x, a4.y, a4.z, a4.w};
        float bb[4] = {b4.x, b4.y, b4.z, b4.w};
#pragma unroll
        for (int i = 0; i < 4; i++)
#pragma unroll
            for (int j = 0; j < 4; j++) toff[i][j] += a[i] * bb[j];
    }

    float Dh = Dp[h];
#pragma unroll
    for (int i = 0; i < 4; i++) {
        int lg = l0 + (ty << 2) + i;
        int t = c * CHUNKL + lg;
        float el = expf(acs[lg]);
        float4 xs4 = *(const float4*)(g_xBC + (size_t)(b * SEQL + t) * CONV_DIM + h * HEADDIM + (tx << 2));
        float4 z4  = *(const float4*)(g_zx + (size_t)(b * SEQL + t) * D_IN_PROJ + h * HEADDIM + (tx << 2));
        float4 o;
        o.x = (Yacc[i][0] + el * toff[i][0] + xs4.x * Dh) * siluf(z4.x);
        o.y = (Yacc[i][1] + el * toff[i][1] + xs4.y * Dh) * siluf(z4.y);
        o.z = (Yacc[i][2] + el * toff[i][2] + xs4.z * Dh) * siluf(z4.z);
        o.w = (Yacc[i][3] + el * toff[i][3] + xs4.w * Dh) * siluf(z4.w);
        *(float4*)(g_yg + (size_t)(b * SEQL + t) * DINNER + h * HEADDIM + (tx << 2)) = o;
    }
}

// ---------------- RMSNorm -> bf16 hi/lo ----------------
__global__ __launch_bounds__(256) void rmsnorm_kernel(const float* __restrict__ w)
{
    int row = blockIdx.x;
    const float* y = g_yg + (size_t)row * DINNER;
    __nv_bfloat16* oh = g_ynh + (size_t)row * DINNER;
    __nv_bfloat16* ol = g_ynl + (size_t)row * DINNER;
    int tid = threadIdx.x;
    float ss = 0.f;
#pragma unroll
    for (int it = 0; it < 4; it++) {
        float4 v = *(const float4*)(y + it * 1024 + tid * 4);
        ss += v.x * v.x + v.y * v.y + v.z * v.z + v.w * v.w;
    }
#pragma unroll
    for (int off = 16; off; off >>= 1) ss += __shfl_xor_sync(0xFFFFFFFFu, ss, off);
    __shared__ float red[8];
    if ((tid & 31) == 0) red[tid >> 5] = ss;
    __syncthreads();
    float tot = 0.f;
#pragma unroll
    for (int i = 0; i < 8; i++) tot += red[i];
    float scale = rsqrtf(tot / (float)DINNER + EPSV);
#pragma unroll
    for (int it = 0; it < 4; it++) {
        int i = it * 1024 + tid * 4;
        float4 v = *(const float4*)(y + i);
        float4 wv = *(const float4*)(w + i);
        float o[4] = {v.x * scale * wv.x, v.y * scale * wv.y,
                      v.z * scale * wv.z, v.w * scale * wv.w};
        __nv_bfloat16 h[4], l[4];
#pragma unroll
        for (int j = 0; j < 4; j++) {
            h[j] = __float2bfloat16(o[j]);
            l[j] = __float2bfloat16(o[j] - __bfloat162float(h[j]));
        }
        __nv_bfloat162* hp = (__nv_bfloat162*)(oh + i);
        __nv_bfloat162* lp = (__nv_bfloat162*)(ol + i);
        hp[0] = __nv_bfloat162(h[0], h[1]); hp[1] = __nv_bfloat162(h[2], h[3]);
        lp[0] = __nv_bfloat162(l[0], l[1]); lp[1] = __nv_bfloat162(l[2], l[3]);
    }
}

// ---------------- launch ----------------
extern "C" void kernel_launch(void* const* d_in, const int* in_sizes, int n_in,
                              void* d_out, int out_size)
{
    const float* x          = (const float*)d_in[0];
    const float* in_proj_w  = (const float*)d_in[1];
    const float* conv_w     = (const float*)d_in[2];
    const float* conv_b     = (const float*)d_in[3];
    const float* dt_bias    = (const float*)d_in[4];
    const float* A_log      = (const float*)d_in[5];
    const float* Dp         = (const float*)d_in[6];
    const float* norm_w     = (const float*)d_in[7];
    const float* out_proj_w = (const float*)d_in[8];
    float* out = (float*)d_out;

    float *zx_p = nullptr;
    __nv_bfloat16 *xh_p, *xl_p, *wih_p, *wil_p, *ynh_p, *ynl_p, *owh_p, *owl_p;
    cudaGetSymbolAddress((void**)&zx_p, g_zx);
    cudaGetSymbolAddress((void**)&xh_p, g_xh);
    cudaGetSymbolAddress((void**)&xl_p, g_xl);
    cudaGetSymbolAddress((void**)&wih_p, g_wih);
    cudaGetSymbolAddress((void**)&wil_p, g_wil);
    cudaGetSymbolAddress((void**)&ynh_p, g_ynh);
    cudaGetSymbolAddress((void**)&ynl_p, g_ynl);
    cudaGetSymbolAddress((void**)&owh_p, g_owh);
    cudaGetSymbolAddress((void**)&owl_p, g_owl);

    static bool attr_set = false;
    if (!attr_set) {
        cudaFuncSetAttribute(gemm_hmma_split, cudaFuncAttributeMaxDynamicSharedMemorySize, GEMM_SMEM);
        const int YS = (2 * 128 * 68 + 2 * 64 * 68 + 256) * sizeof(float);
        cudaFuncSetAttribute(y_kernel, cudaFuncAttributeMaxDynamicSharedMemorySize, YS);
        attr_set = true;
    }

    const int M = B_SZ * SEQL; // 4096

    // converts
    {
        long n = (long)M * DMODEL;
        cvt_split<<<(unsigned)((n / 4 + 255) / 256), 256>>>(x, xh_p, xl_p, n, n);
    }
    {
        long ns = (long)D_IN_PROJ * DMODEL, nt = (long)DIP_PAD * DMODEL;
        cvt_split<<<(unsigned)((nt / 4 + 255) / 256), 256>>>(in_proj_w, wih_p, wil_p, ns, nt);
    }
    {
        long n = (long)DMODEL * DINNER;
        cvt_split<<<(unsigned)((n / 4 + 255) / 256), 256>>>(out_proj_w, owh_p, owl_p, n, n);
    }

    // 1) in_proj GEMM (HMMA): (4096 x 2048) x (8512 x 2048)^T
    gemm_hmma_split<<<dim3(DIP_PAD / 128, M / 128), 256, GEMM_SMEM>>>(
        xh_p, xl_p, wih_p, wil_p, zx_p, M, D_IN_PROJ, DMODEL);

    // 2) conv + silu
    conv_silu_kernel<<<dim3(CONV_DIM / 128, B_SZ, SEQL / 256), 128>>>(conv_w, conv_b);

    // 3) dt softplus + cumsum
    dt_scan_kernel<<<B_SZ * NHEADS * NCHUNK, CHUNKL>>>(dt_bias, A_log);

    // 4) states
    states_kernel<<<B_SZ * NCHUNK * NHEADS, 256>>>();

    // 5) recurrence
    prev_kernel<<<B_SZ * NHEADS, 256>>>();

    // 6) Y + gate
    const int YS = (2 * 128 * 68 + 2 * 64 * 68 + 256) * sizeof(float);
    y_kernel<<<B_SZ * NCHUNK * NHEADS * 4, 256, YS>>>(Dp);

    // 7) RMSNorm -> bf16 hi/lo
    rmsnorm_kernel<<<B_SZ * SEQL, 256>>>(norm_w);

    // 8) out_proj GEMM (HMMA): (4096 x 4096) x (2048 x 4096)^T
    gemm_hmma_split<<<dim3(DMODEL / 128, M / 128), 256, GEMM_SMEM>>>(
        ynh_p, ynl_p, owh_p, owl_p, out, M, DMODEL, DINNER);

    (void)in_sizes; (void)n_in; (void)out_size;
}

// round 6
// speedup vs baseline: 2.4820x; 1.2276x over previous
#include <cuda_runtime.h>
#include <cuda_bf16.h>
#include <cuda_fp16.h>
#include <cstdint>

#define B_SZ 2
#define SEQL 2048
#define DMODEL 2048
#define DINNER 4096
#define DSTATE 128
#define HEADDIM 64
#define NHEADS 64
#define CHUNKL 256
#define NCHUNK 8
#define CONV_DIM 4352     // DINNER + 2*DSTATE
#define D_IN_PROJ 8512    // 2*DINNER + 2*DSTATE + NHEADS
#define DIP_PAD 8576      // 67*128
#define EPSV 1e-5f

// ---------------- scratch ----------------
__device__ float g_zx[B_SZ*SEQL*D_IN_PROJ];
__device__ float g_xBC[B_SZ*SEQL*CONV_DIM];
__device__ float g_dt[B_SZ*SEQL*NHEADS];
__device__ float g_Acs[B_SZ*NHEADS*NCHUNK*CHUNKL];
__device__ float g_states[(size_t)B_SZ*NCHUNK*NHEADS*HEADDIM*DSTATE];
__device__ float g_prev[(size_t)B_SZ*NCHUNK*NHEADS*HEADDIM*DSTATE];
__device__ float g_yg[B_SZ*SEQL*DINNER];
// bf16 hi/lo operands (in_proj), fp16 operands (out_proj reuses hi buffers)
__device__ __nv_bfloat16 g_xh[B_SZ*SEQL*DMODEL];
__device__ __nv_bfloat16 g_xl[B_SZ*SEQL*DMODEL];
__device__ __nv_bfloat16 g_wih[(size_t)DIP_PAD*DMODEL];
__device__ __nv_bfloat16 g_wil[(size_t)DIP_PAD*DMODEL];
__device__ __nv_bfloat16 g_ynh[B_SZ*SEQL*DINNER];     // used as __half
__device__ __nv_bfloat16 g_owh[(size_t)DMODEL*DINNER]; // used as __half

__device__ __forceinline__ float siluf(float a) { return a / (1.f + expf(-a)); }

// ================= HMMA GEMM common =================
// Operand tile: 128 rows x 32 half-words (64B/row), XOR-swizzled, 8KB.
#define OPW  2048                         // words per operand tile
#define STGW_S (4 * OPW)                  // split-kernel stage words (Ah,Al,Bh,Bl)
#define GEMM_SMEM  (3 * STGW_S * 4)       // 98304 B, 3 stages
#define STGW_H (2 * OPW)                  // fp16-kernel stage words (A,B)
#define GEMM1_SMEM (4 * STGW_H * 4)       // 65536 B, 4 stages

__device__ __forceinline__ void mma_bf16(float* c, const uint32_t* a, const uint32_t* b) {
    asm volatile(
        "mma.sync.aligned.m16n8k16.row.col.f32.bf16.bf16.f32 "
        "{%0,%1,%2,%3}, {%4,%5,%6,%7}, {%8,%9}, {%0,%1,%2,%3};"
        : "+f"(c[0]), "+f"(c[1]), "+f"(c[2]), "+f"(c[3])
        : "r"(a[0]), "r"(a[1]), "r"(a[2]), "r"(a[3]), "r"(b[0]), "r"(b[1]));
}
__device__ __forceinline__ void mma_fp16(float* c, const uint32_t* a, const uint32_t* b) {
    asm volatile(
        "mma.sync.aligned.m16n8k16.row.col.f32.f16.f16.f32 "
        "{%0,%1,%2,%3}, {%4,%5,%6,%7}, {%8,%9}, {%0,%1,%2,%3};"
        : "+f"(c[0]), "+f"(c[1]), "+f"(c[2]), "+f"(c[3])
        : "r"(a[0]), "r"(a[1]), "r"(a[2]), "r"(a[3]), "r"(b[0]), "r"(b[1]));
}
__device__ __forceinline__ void ldsm4(uint32_t* r, uint32_t addr) {
    asm volatile("ldmatrix.sync.aligned.m8n8.x4.shared.b16 {%0,%1,%2,%3}, [%4];"
        : "=r"(r[0]), "=r"(r[1]), "=r"(r[2]), "=r"(r[3]) : "r"(addr));
}
__device__ __forceinline__ void cp16(uint32_t dst, const void* src) {
    asm volatile("cp.async.cg.shared.global [%0], [%1], 16;" :: "r"(dst), "l"(src));
}
__device__ __forceinline__ uint32_t smem_u32(const void* p) {
    uint32_t a;
    asm("{ .reg .u64 t; cvta.to.shared.u64 t, %1; cvt.u32.u64 %0, t; }" : "=r"(a) : "l"(p));
    return a;
}
// swizzled 128x32x16bit tile load: logical (r, chunk) -> word r*16 + ((chunk^((r>>1)&3))<<2)
__device__ __forceinline__ void load_op(uint32_t sbase_b, const __nv_bfloat16* g, int ldk, int tid) {
#pragma unroll
    for (int it = 0; it < 2; it++) {
        int v = tid + (it << 8);
        int r = v >> 2, ch = v & 3;
        int sch = ch ^ ((r >> 1) & 3);
        cp16(sbase_b + (r * 16 + (sch << 2)) * 4, g + (size_t)r * ldk + (ch << 3));
    }
}

// ---------------- bf16-split GEMM (3 products): C = A * B^T ----------------
__global__ __launch_bounds__(256, 2) void gemm_hmma_split(
    const __nv_bfloat16* __restrict__ Ah, const __nv_bfloat16* __restrict__ Al,
    const __nv_bfloat16* __restrict__ Bh, const __nv_bfloat16* __restrict__ Bl,
    float* __restrict__ C, int M, int Nreal, int K)
{
    extern __shared__ uint32_t sw[];
    const uint32_t sb = smem_u32(sw);
    const int tid = threadIdx.x, wid = tid >> 5, lane = tid & 31;
    const int warp_m = wid & 1, warp_n = wid >> 1;
    const int m0 = blockIdx.y << 7, n0 = blockIdx.x << 7;
    const int KT = K >> 5;

    const __nv_bfloat16* Abh = Ah + (size_t)m0 * K;
    const __nv_bfloat16* Abl = Al + (size_t)m0 * K;
    const __nv_bfloat16* Bbh = Bh + (size_t)n0 * K;
    const __nv_bfloat16* Bbl = Bl + (size_t)n0 * K;

    float acc[4][4][4];
#pragma unroll
    for (int i = 0; i < 4; i++)
#pragma unroll
        for (int j = 0; j < 4; j++)
#pragma unroll
            for (int q = 0; q < 4; q++) acc[i][j][q] = 0.f;

    // prologue: stages 0,1
#pragma unroll
    for (int s = 0; s < 2; s++) {
        int koff = s << 5;
        load_op(sb + (s * STGW_S + 0 * OPW) * 4, Abh + koff, K, tid);
        load_op(sb + (s * STGW_S + 1 * OPW) * 4, Abl + koff, K, tid);
        load_op(sb + (s * STGW_S + 2 * OPW) * 4, Bbh + koff, K, tid);
        load_op(sb + (s * STGW_S + 3 * OPW) * 4, Bbl + koff, K, tid);
        asm volatile("cp.async.commit_group;" ::: "memory");
    }

    const int rowA = warp_m * 64 + ((lane >> 3) & 1) * 8 + (lane & 7);
    const int swzA = (rowA >> 1) & 3;
    const int cA0  = lane >> 4;
    const int rowB = warp_n * 32 + ((lane >> 4) & 1) * 8 + (lane & 7);
    const int swzB = (rowB >> 1) & 3;
    const int cB0  = (lane >> 3) & 1;

    int buf = 0;
    for (int kt = 0; kt < KT; kt++) {
        asm volatile("cp.async.wait_group 1;" ::: "memory");
        __syncthreads();
        if (kt + 2 < KT) {
            int s = buf + 2; if (s >= 3) s -= 3;
            int koff = (kt + 2) << 5;
            load_op(sb + (s * STGW_S + 0 * OPW) * 4, Abh + koff, K, tid);
            load_op(sb + (s * STGW_S + 1 * OPW) * 4, Abl + koff, K, tid);
            load_op(sb + (s * STGW_S + 2 * OPW) * 4, Bbh + koff, K, tid);
            load_op(sb + (s * STGW_S + 3 * OPW) * 4, Bbl + koff, K, tid);
        }
        asm volatile("cp.async.commit_group;" ::: "memory");

        const uint32_t stgb = sb + (uint32_t)buf * STGW_S * 4u;
        const uint32_t sAh = stgb;
        const uint32_t sAl = stgb + OPW * 4u;
        const uint32_t sBh = stgb + 2u * OPW * 4u;
        const uint32_t sBl = stgb + 3u * OPW * 4u;

#pragma unroll
        for (int kk = 0; kk < 2; kk++) {
            const int cA = (kk << 1) + cA0;
            const int cB = (kk << 1) + cB0;
            uint32_t ah[4][4], al[4][4];
#pragma unroll
            for (int mi = 0; mi < 4; mi++) {
                uint32_t off = (((rowA + mi * 16) * 16) + ((cA ^ swzA) << 2)) * 4u;
                ldsm4(ah[mi], sAh + off);
                ldsm4(al[mi], sAl + off);
            }
#pragma unroll
            for (int np = 0; np < 2; np++) {
                uint32_t boff = (((rowB + np * 16) * 16) + ((cB ^ swzB) << 2)) * 4u;
                uint32_t bh[4], bl[4];
                ldsm4(bh, sBh + boff);
                ldsm4(bl, sBl + boff);
#pragma unroll
                for (int mi = 0; mi < 4; mi++) {
                    mma_bf16(acc[mi][2 * np], ah[mi], bh);
                    mma_bf16(acc[mi][2 * np], ah[mi], bl);
                    mma_bf16(acc[mi][2 * np], al[mi], bh);
                    mma_bf16(acc[mi][2 * np + 1], ah[mi], bh + 2);
                    mma_bf16(acc[mi][2 * np + 1], ah[mi], bl + 2);
                    mma_bf16(acc[mi][2 * np + 1], al[mi], bh + 2);
                }
            }
        }
        buf++; if (buf == 3) buf = 0;
    }

#pragma unroll
    for (int mi = 0; mi < 4; mi++) {
        int rg0 = m0 + warp_m * 64 + mi * 16 + (lane >> 2);
#pragma unroll
        for (int ni = 0; ni < 4; ni++) {
            int cg = n0 + warp_n * 32 + ni * 8 + ((lane & 3) << 1);
            if (cg < Nreal) {
                *(float2*)(C + (size_t)rg0 * Nreal + cg) =
                    make_float2(acc[mi][ni][0], acc[mi][ni][1]);
                *(float2*)(C + (size_t)(rg0 + 8) * Nreal + cg) =
                    make_float2(acc[mi][ni][2], acc[mi][ni][3]);
            }
        }
    }
}

// ---------------- fp16 single-product GEMM: C = A * B^T ----------------
__global__ __launch_bounds__(256, 2) void gemm_hmma_fp16(
    const __half* __restrict__ A, const __half* __restrict__ B,
    float* __restrict__ C, int M, int Nreal, int K)
{
    extern __shared__ uint32_t sw[];
    const uint32_t sb = smem_u32(sw);
    const int tid = threadIdx.x, wid = tid >> 5, lane = tid & 31;
    const int warp_m = wid & 1, warp_n = wid >> 1;
    const int m0 = blockIdx.y << 7, n0 = blockIdx.x << 7;
    const int KT = K >> 5;

    const __nv_bfloat16* Ab = (const __nv_bfloat16*)(A + (size_t)m0 * K);
    const __nv_bfloat16* Bb = (const __nv_bfloat16*)(B + (size_t)n0 * K);

    float acc[4][4][4];
#pragma unroll
    for (int i = 0; i < 4; i++)
#pragma unroll
        for (int j = 0; j < 4; j++)
#pragma unroll
            for (int q = 0; q < 4; q++) acc[i][j][q] = 0.f;

    // prologue: stages 0..2
#pragma unroll
    for (int s = 0; s < 3; s++) {
        int koff = s << 5;
        load_op(sb + (s * STGW_H + 0 * OPW) * 4, Ab + koff, K, tid);
        load_op(sb + (s * STGW_H + 1 * OPW) * 4, Bb + koff, K, tid);
        asm volatile("cp.async.commit_group;" ::: "memory");
    }

    const int rowA = warp_m * 64 + ((lane >> 3) & 1) * 8 + (lane & 7);
    const int swzA = (rowA >> 1) & 3;
    const int cA0  = lane >> 4;
    const int rowB = warp_n * 32 + ((lane >> 4) & 1) * 8 + (lane & 7);
    const int swzB = (rowB >> 1) & 3;
    const int cB0  = (lane >> 3) & 1;

    int buf = 0;
    for (int kt = 0; kt < KT; kt++) {
        asm volatile("cp.async.wait_group 2;" ::: "memory");
        __syncthreads();
        if (kt + 3 < KT) {
            int s = buf + 3; if (s >= 4) s -= 4;
            int koff = (kt + 3) << 5;
            load_op(sb + (s * STGW_H + 0 * OPW) * 4, Ab + koff, K, tid);
            load_op(sb + (s * STGW_H + 1 * OPW) * 4, Bb + koff, K, tid);
        }
        asm volatile("cp.async.commit_group;" ::: "memory");

        const uint32_t stgb = sb + (uint32_t)buf * STGW_H * 4u;
        const uint32_t sA = stgb;
        const uint32_t sB = stgb + OPW * 4u;

#pragma unroll
        for (int kk = 0; kk < 2; kk++) {
            const int cA = (kk << 1) + cA0;
            const int cB = (kk << 1) + cB0;
            uint32_t a[4][4];
#pragma unroll
            for (int mi = 0; mi < 4; mi++) {
                uint32_t off = (((rowA + mi * 16) * 16) + ((cA ^ swzA) << 2)) * 4u;
                ldsm4(a[mi], sA + off);
            }
#pragma unroll
            for (int np = 0; np < 2; np++) {
                uint32_t boff = (((rowB + np * 16) * 16) + ((cB ^ swzB) << 2)) * 4u;
                uint32_t b[4];
                ldsm4(b, sB + boff);
#pragma unroll
                for (int mi = 0; mi < 4; mi++) {
                    mma_fp16(acc[mi][2 * np], a[mi], b);
                    mma_fp16(acc[mi][2 * np + 1], a[mi], b + 2);
                }
            }
        }
        buf++; if (buf == 4) buf = 0;
    }

#pragma unroll
    for (int mi = 0; mi < 4; mi++) {
        int rg0 = m0 + warp_m * 64 + mi * 16 + (lane >> 2);
#pragma unroll
        for (int ni = 0; ni < 4; ni++) {
            int cg = n0 + warp_n * 32 + ni * 8 + ((lane & 3) << 1);
            if (cg < Nreal) {
                *(float2*)(C + (size_t)rg0 * Nreal + cg) =
                    make_float2(acc[mi][ni][0], acc[mi][ni][1]);
                *(float2*)(C + (size_t)(rg0 + 8) * Nreal + cg) =
                    make_float2(acc[mi][ni][2], acc[mi][ni][3]);
            }
        }
    }
}

// ---------------- fp32 -> bf16 hi/lo split (with zero-pad tail) ----------------
__global__ void cvt_split(const float* __restrict__ src, __nv_bfloat16* __restrict__ hi,
                          __nv_bfloat16* __restrict__ lo, long n_src, long n_tot)
{
    long i = ((long)blockIdx.x * 256 + threadIdx.x) * 4;
    if (i >= n_tot) return;
    float4 v = (i < n_src) ? *(const float4*)(src + i) : make_float4(0.f, 0.f, 0.f, 0.f);
    float vv[4] = {v.x, v.y, v.z, v.w};
    __nv_bfloat16 h[4], l[4];
#pragma unroll
    for (int j = 0; j < 4; j++) {
        h[j] = __float2bfloat16(vv[j]);
        l[j] = __float2bfloat16(vv[j] - __bfloat162float(h[j]));
    }
    __nv_bfloat162* hp = (__nv_bfloat162*)(hi + i);
    __nv_bfloat162* lp = (__nv_bfloat162*)(lo + i);
    hp[0] = __nv_bfloat162(h[0], h[1]); hp[1] = __nv_bfloat162(h[2], h[3]);
    lp[0] = __nv_bfloat162(l[0], l[1]); lp[1] = __nv_bfloat162(l[2], l[3]);
}

// ---------------- fp32 -> fp16 ----------------
__global__ void cvt_half(const float* __restrict__ src, __half* __restrict__ dst, long n)
{
    long i = ((long)blockIdx.x * 256 + threadIdx.x) * 4;
    if (i >= n) return;
    float4 v = *(const float4*)(src + i);
    __half2* dp = (__half2*)(dst + i);
    dp[0] = __floats2half2_rn(v.x, v.y);
    dp[1] = __floats2half2_rn(v.z, v.w);
}

// ---------------- causal depthwise conv (width 4) + silu ----------------
__global__ void conv_silu_kernel(const float* __restrict__ conv_w,
                                 const float* __restrict__ conv_b)
{
    int c = blockIdx.x * 128 + threadIdx.x;
    int b = blockIdx.y;
    int t0 = blockIdx.z * 256;
    float w0 = conv_w[c * 4 + 0], w1 = conv_w[c * 4 + 1];
    float w2 = conv_w[c * 4 + 2], w3 = conv_w[c * 4 + 3];
    float bias = conv_b[c];
    const float* src = g_zx + (size_t)b * SEQL * D_IN_PROJ + DINNER + c;
    float* dst = g_xBC + (size_t)b * SEQL * CONV_DIM + c;
    float x0 = (t0 >= 3) ? src[(size_t)(t0 - 3) * D_IN_PROJ] : 0.f;
    float x1 = (t0 >= 2) ? src[(size_t)(t0 - 2) * D_IN_PROJ] : 0.f;
    float x2 = (t0 >= 1) ? src[(size_t)(t0 - 1) * D_IN_PROJ] : 0.f;
    for (int t = t0; t < t0 + 256; t++) {
        float x3 = src[(size_t)t * D_IN_PROJ];
        float a = bias + w0 * x0 + w1 * x1 + w2 * x2 + w3 * x3;
        dst[(size_t)t * CONV_DIM] = siluf(a);
        x0 = x1; x1 = x2; x2 = x3;
    }
}

// ---------------- dt softplus + per-chunk cumsum of dA ----------------
__global__ void dt_scan_kernel(const float* __restrict__ dt_bias,
                               const float* __restrict__ A_log)
{
    int idx = blockIdx.x;
    int c = idx % NCHUNK; idx /= NCHUNK;
    int h = idx % NHEADS;
    int b = idx / NHEADS;
    int l = threadIdx.x;
    int t = c * CHUNKL + l;
    float raw = g_zx[(size_t)(b * SEQL + t) * D_IN_PROJ + DINNER + CONV_DIM + h];
    float xv = raw + dt_bias[h];
    float dt = (xv > 20.f) ? xv : log1pf(expf(xv));
    g_dt[(b * SEQL + t) * NHEADS + h] = dt;
    float dA = dt * (-expf(A_log[h]));
    __shared__ float s[CHUNKL];
    s[l] = dA;
    __syncthreads();
    for (int off = 1; off < CHUNKL; off <<= 1) {
        float v = (l >= off) ? s[l - off] : 0.f;
        __syncthreads();
        s[l] += v;
        __syncthreads();
    }
    g_Acs[((b * NHEADS + h) * NCHUNK + c) * CHUNKL + l] = s[l];
}

// ---------------- per-chunk states ----------------
__global__ __launch_bounds__(256) void states_kernel()
{
    __shared__ float Bd[32][132];
    __shared__ float Xs[32][68];
    __shared__ float dec[32];
    __shared__ float dts[32];
    int idx = blockIdx.x;
    int h = idx % NHEADS; idx /= NHEADS;
    int c = idx % NCHUNK;
    int b = idx / NCHUNK;
    int tid = threadIdx.x;
    int tx = tid & 15, ty = tid >> 4;
    const float* acs = g_Acs + ((b * NHEADS + h) * NCHUNK + c) * CHUNKL;
    float acs_last = acs[CHUNKL - 1];
    float acc[4][8];
#pragma unroll
    for (int i = 0; i < 4; i++)
#pragma unroll
        for (int j = 0; j < 8; j++) acc[i][j] = 0.f;

    for (int l0 = 0; l0 < CHUNKL; l0 += 32) {
        if (tid < 32) {
            int t = c * CHUNKL + l0 + tid;
            dec[tid] = expf(acs_last - acs[l0 + tid]);
            dts[tid] = g_dt[(b * SEQL + t) * NHEADS + h];
        }
        __syncthreads();
#pragma unroll
        for (int it = 0; it < 4; it++) {
            int v = tid + it * 256;
            int r = v >> 5, nn = (v & 31) << 2;
            int t = c * CHUNKL + l0 + r;
            float4 f = *(const float4*)(g_xBC + (size_t)(b * SEQL + t) * CONV_DIM + DINNER + nn);
            float d = dec[r];
            Bd[r][nn + 0] = f.x * d; Bd[r][nn + 1] = f.y * d;
            Bd[r][nn + 2] = f.z * d; Bd[r][nn + 3] = f.w * d;
        }
#pragma unroll
        for (int it = 0; it < 2; it++) {
            int v = tid + it * 256;
            int r = v >> 4, pp = (v & 15) << 2;
            int t = c * CHUNKL + l0 + r;
            float4 f = *(const float4*)(g_xBC + (size_t)(b * SEQL + t) * CONV_DIM + h * HEADDIM + pp);
            float d = dts[r];
            *(float4*)&Xs[r][pp] = make_float4(f.x * d, f.y * d, f.z * d, f.w * d);
        }
        __syncthreads();
#pragma unroll
        for (int l = 0; l < 32; l++) {
            float a[4], bb[8];
            *(float4*)a = *(const float4*)&Xs[l][ty * 4];
            *(float4*)(bb)     = *(const float4*)&Bd[l][tx * 8];
            *(float4*)(bb + 4) = *(const float4*)&Bd[l][tx * 8 + 4];
#pragma unroll
            for (int i = 0; i < 4; i++)
#pragma unroll
                for (int j = 0; j < 8; j++) acc[i][j] += a[i] * bb[j];
        }
        __syncthreads();
    }
    float* out = g_states + (size_t)((b * NCHUNK + c) * NHEADS + h) * HEADDIM * DSTATE;
#pragma unroll
    for (int i = 0; i < 4; i++)
#pragma unroll
        for (int j = 0; j < 8; j += 4)
            *(float4*)(out + (ty * 4 + i) * DSTATE + tx * 8 + j) =
                make_float4(acc[i][j], acc[i][j+1], acc[i][j+2], acc[i][j+3]);
}

// ---------------- inter-chunk recurrence ----------------
__global__ __launch_bounds__(256) void prev_kernel()
{
    int b = blockIdx.x >> 6;
    int h = blockIdx.x & 63;
    int tid = threadIdx.x;
    float P[32];
#pragma unroll
    for (int i = 0; i < 32; i++) P[i] = 0.f;
    for (int c = 0; c < NCHUNK; c++) {
        float decay = expf(g_Acs[((b * NHEADS + h) * NCHUNK + c) * CHUNKL + CHUNKL - 1]);
        size_t base = (size_t)((b * NCHUNK + c) * NHEADS + h) * HEADDIM * DSTATE;
#pragma unroll
        for (int i = 0; i < 32; i++) {
            int e = i * 256 + tid;
            g_prev[base + e] = P[i];
            P[i] = P[i] * decay + g_states[base + e];
        }
    }
}

// ---------------- Y (diag + off) + gate ----------------
__global__ __launch_bounds__(256, 2) void y_kernel(const float* __restrict__ Dp)
{
    extern __shared__ float sm[];
    float* Cst = sm;
    float* Bst = Cst + 128 * 68;
    float* Xs  = Bst + 128 * 68;
    float* St  = Xs  + 64 * 68;
    float* acs = St  + 64 * 68;

    int idx = blockIdx.x;
    int lt = idx & 3; idx >>= 2;
    int h = idx % NHEADS; idx /= NHEADS;
    int c = idx % NCHUNK;
    int b = idx / NCHUNK;
    int tid = threadIdx.x;
    int tx = tid & 15, ty = tid >> 4;
    int l0 = lt * 64;

    const float* acs_g = g_Acs + ((b * NHEADS + h) * NCHUNK + c) * CHUNKL;
    acs[tid] = acs_g[tid];

#pragma unroll
    for (int it = 0; it < 8; it++) {
        int v = tid + it * 256;
        int r = v >> 5, nn = (v & 31) << 2;
        int t = c * CHUNKL + l0 + r;
        float4 f = *(const float4*)(g_xBC + (size_t)(b * SEQL + t) * CONV_DIM + DINNER + DSTATE + nn);
        Cst[(nn + 0) * 68 + r] = f.x; Cst[(nn + 1) * 68 + r] = f.y;
        Cst[(nn + 2) * 68 + r] = f.z; Cst[(nn + 3) * 68 + r] = f.w;
    }
    __syncthreads();

    float Yacc[4][4];
#pragma unroll
    for (int i = 0; i < 4; i++)
#pragma unroll
        for (int j = 0; j < 4; j++) Yacc[i][j] = 0.f;

    for (int st = 0; st <= lt; st++) {
        int s0 = st * 64;
#pragma unroll
        for (int it = 0; it < 8; it++) {
            int v = tid + it * 256;
            int r = v >> 5, nn = (v & 31) << 2;
            int t = c * CHUNKL + s0 + r;
            float4 f = *(const float4*)(g_xBC + (size_t)(b * SEQL + t) * CONV_DIM + DINNER + nn);
            Bst[(nn + 0) * 68 + r] = f.x; Bst[(nn + 1) * 68 + r] = f.y;
            Bst[(nn + 2) * 68 + r] = f.z; Bst[(nn + 3) * 68 + r] = f.w;
        }
#pragma unroll
        for (int it = 0; it < 4; it++) {
            int v = tid + it * 256;
            int r = v >> 4, pp = (v & 15) << 2;
            int t = c * CHUNKL + s0 + r;
            float4 f = *(const float4*)(g_xBC + (size_t)(b * SEQL + t) * CONV_DIM + h * HEADDIM + pp);
            float d = g_dt[(b * SEQL + t) * NHEADS + h];
            *(float4*)&Xs[r * 68 + pp] = make_float4(f.x * d, f.y * d, f.z * d, f.w * d);
        }
        __syncthreads();

        float sacc[4][4];
#pragma unroll
        for (int i = 0; i < 4; i++)
#pragma unroll
            for (int j = 0; j < 4; j++) sacc[i][j] = 0.f;
#pragma unroll 4
        for (int n = 0; n < 128; n++) {
            float4 a4 = *(const float4*)&Cst[n * 68 + (ty << 2)];
            float4 b4 = *(const float4*)&Bst[n * 68 + (tx << 2)];
            float a[4] = {a4.x, a4.y, a4.z, a4.w};
            float bb[4] = {b4.x, b4.y, b4.z, b4.w};
#pragma unroll
            for (int i = 0; i < 4; i++)
#pragma unroll
                for (int j = 0; j < 4; j++) sacc[i][j] += a[i] * bb[j];
        }
#pragma unroll
        for (int j = 0; j < 4; j++) {
            int sg = s0 + (tx << 2) + j;
            float col[4];
#pragma unroll
            for (int i = 0; i < 4; i++) {
                int lg = l0 + (ty << 2) + i;
                col[i] = (sg <= lg) ? sacc[i][j] * expf(acs[lg] - acs[sg]) : 0.f;
            }
            *(float4*)&St[((tx << 2) + j) * 68 + (ty << 2)] =
                make_float4(col[0], col[1], col[2], col[3]);
        }
        __syncthreads();
#pragma unroll 4
        for (int s = 0; s < 64; s++) {
            float4 a4 = *(const float4*)&St[s * 68 + (ty << 2)];
            float4 x4 = *(const float4*)&Xs[s * 68 + (tx << 2)];
            float a[4] = {a4.x, a4.y, a4.z, a4.w};
            float xx[4] = {x4.x, x4.y, x4.z, x4.w};
#pragma unroll
            for (int i = 0; i < 4; i++)
#pragma unroll
                for (int j = 0; j < 4; j++) Yacc[i][j] += a[i] * xx[j];
        }
        __syncthreads();
    }

    size_t pbase = (size_t)((b * NCHUNK + c) * NHEADS + h) * HEADDIM * DSTATE;
#pragma unroll
    for (int it = 0; it < 8; it++) {
        int v = tid + it * 256;
        int p = v >> 5, nn = (v & 31) << 2;
        float4 f = *(const float4*)(g_prev + pbase + p * DSTATE + nn);
        Bst[(nn + 0) * 68 + p] = f.x; Bst[(nn + 1) * 68 + p] = f.y;
        Bst[(nn + 2) * 68 + p] = f.z; Bst[(nn + 3) * 68 + p] = f.w;
    }
    __syncthreads();
    float toff[4][4];
#pragma unroll
    for (int i = 0; i < 4; i++)
#pragma unroll
        for (int j = 0; j < 4; j++) toff[i][j] = 0.f;
#pragma unroll 4
    for (int n = 0; n < 128; n++) {
        float4 a4 = *(const float4*)&Cst[n * 68 + (ty << 2)];
        float4 b4 = *(const float4*)&Bst[n * 68 + (tx << 2)];
        float a[4] = {a4.x, a4.y, a4.z, a4.w};
        float bb[4] = {b4.x, b4.y, b4.z, b4.w};
#pragma unroll
        for (int i = 0; i < 4; i++)
#pragma unroll
            for (int j = 0; j < 4; j++) toff[i][j] += a[i] * bb[j];
    }

    float Dh = Dp[h];
#pragma unroll
    for (int i = 0; i < 4; i++) {
        int lg = l0 + (ty << 2) + i;
        int t = c * CHUNKL + lg;
        float el = expf(acs[lg]);
        float4 xs4 = *(const float4*)(g_xBC + (size_t)(b * SEQL + t) * CONV_DIM + h * HEADDIM + (tx << 2));
        float4 z4  = *(const float4*)(g_zx + (size_t)(b * SEQL + t) * D_IN_PROJ + h * HEADDIM + (tx << 2));
        float4 o;
        o.x = (Yacc[i][0] + el * toff[i][0] + xs4.x * Dh) * siluf(z4.x);
        o.y = (Yacc[i][1] + el * toff[i][1] + xs4.y * Dh) * siluf(z4.y);
        o.z = (Yacc[i][2] + el * toff[i][2] + xs4.z * Dh) * siluf(z4.z);
        o.w = (Yacc[i][3] + el * toff[i][3] + xs4.w * Dh) * siluf(z4.w);
        *(float4*)(g_yg + (size_t)(b * SEQL + t) * DINNER + h * HEADDIM + (tx << 2)) = o;
    }
}

// ---------------- RMSNorm -> fp16 ----------------
__global__ __launch_bounds__(256) void rmsnorm_kernel(const float* __restrict__ w)
{
    int row = blockIdx.x;
    const float* y = g_yg + (size_t)row * DINNER;
    __half* oh = reinterpret_cast<__half*>(g_ynh) + (size_t)row * DINNER;
    int tid = threadIdx.x;
    float ss = 0.f;
#pragma unroll
    for (int it = 0; it < 4; it++) {
        float4 v = *(const float4*)(y + it * 1024 + tid * 4);
        ss += v.x * v.x + v.y * v.y + v.z * v.z + v.w * v.w;
    }
#pragma unroll
    for (int off = 16; off; off >>= 1) ss += __shfl_xor_sync(0xFFFFFFFFu, ss, off);
    __shared__ float red[8];
    if ((tid & 31) == 0) red[tid >> 5] = ss;
    __syncthreads();
    float tot = 0.f;
#pragma unroll
    for (int i = 0; i < 8; i++) tot += red[i];
    float scale = rsqrtf(tot / (float)DINNER + EPSV);
#pragma unroll
    for (int it = 0; it < 4; it++) {
        int i = it * 1024 + tid * 4;
        float4 v = *(const float4*)(y + i);
        float4 wv = *(const float4*)(w + i);
        __half2* hp = (__half2*)(oh + i);
        hp[0] = __floats2half2_rn(v.x * scale * wv.x, v.y * scale * wv.y);
        hp[1] = __floats2half2_rn(v.z * scale * wv.z, v.w * scale * wv.w);
    }
}

// ---------------- launch ----------------
extern "C" void kernel_launch(void* const* d_in, const int* in_sizes, int n_in,
                              void* d_out, int out_size)
{
    const float* x          = (const float*)d_in[0];
    const float* in_proj_w  = (const float*)d_in[1];
    const float* conv_w     = (const float*)d_in[2];
    const float* conv_b     = (const float*)d_in[3];
    const float* dt_bias    = (const float*)d_in[4];
    const float* A_log      = (const float*)d_in[5];
    const float* Dp         = (const float*)d_in[6];
    const float* norm_w     = (const float*)d_in[7];
    const float* out_proj_w = (const float*)d_in[8];
    float* out = (float*)d_out;

    float *zx_p = nullptr;
    __nv_bfloat16 *xh_p, *xl_p, *wih_p, *wil_p, *ynh_p, *owh_p;
    cudaGetSymbolAddress((void**)&zx_p, g_zx);
    cudaGetSymbolAddress((void**)&xh_p, g_xh);
    cudaGetSymbolAddress((void**)&xl_p, g_xl);
    cudaGetSymbolAddress((void**)&wih_p, g_wih);
    cudaGetSymbolAddress((void**)&wil_p, g_wil);
    cudaGetSymbolAddress((void**)&ynh_p, g_ynh);
    cudaGetSymbolAddress((void**)&owh_p, g_owh);

    static bool attr_set = false;
    if (!attr_set) {
        cudaFuncSetAttribute(gemm_hmma_split, cudaFuncAttributeMaxDynamicSharedMemorySize, GEMM_SMEM);
        cudaFuncSetAttribute(gemm_hmma_fp16, cudaFuncAttributeMaxDynamicSharedMemorySize, GEMM1_SMEM);
        const int YS = (2 * 128 * 68 + 2 * 64 * 68 + 256) * sizeof(float);
        cudaFuncSetAttribute(y_kernel, cudaFuncAttributeMaxDynamicSharedMemorySize, YS);
        attr_set = true;
    }

    const int M = B_SZ * SEQL; // 4096

    // converts
    {
        long n = (long)M * DMODEL;
        cvt_split<<<(unsigned)((n / 4 + 255) / 256), 256>>>(x, xh_p, xl_p, n, n);
    }
    {
        long ns = (long)D_IN_PROJ * DMODEL, nt = (long)DIP_PAD * DMODEL;
        cvt_split<<<(unsigned)((nt / 4 + 255) / 256), 256>>>(in_proj_w, wih_p, wil_p, ns, nt);
    }
    {
        long n = (long)DMODEL * DINNER;
        cvt_half<<<(unsigned)((n / 4 + 255) / 256), 256>>>(out_proj_w, (__half*)owh_p, n);
    }

    // 1) in_proj GEMM (bf16 3-product): (4096 x 2048) x (8512 x 2048)^T
    gemm_hmma_split<<<dim3(DIP_PAD / 128, M / 128), 256, GEMM_SMEM>>>(
        xh_p, xl_p, wih_p, wil_p, zx_p, M, D_IN_PROJ, DMODEL);

    // 2) conv + silu
    conv_silu_kernel<<<dim3(CONV_DIM / 128, B_SZ, SEQL / 256), 128>>>(conv_w, conv_b);

    // 3) dt softplus + cumsum
    dt_scan_kernel<<<B_SZ * NHEADS * NCHUNK, CHUNKL>>>(dt_bias, A_log);

    // 4) states
    states_kernel<<<B_SZ * NCHUNK * NHEADS, 256>>>();

    // 5) recurrence
    prev_kernel<<<B_SZ * NHEADS, 256>>>();

    // 6) Y + gate
    const int YS = (2 * 128 * 68 + 2 * 64 * 68 + 256) * sizeof(float);
    y_kernel<<<B_SZ * NCHUNK * NHEADS * 4, 256, YS>>>(Dp);

    // 7) RMSNorm -> fp16
    rmsnorm_kernel<<<B_SZ * SEQL, 256>>>(norm_w);

    // 8) out_proj GEMM (fp16 single-product): (4096 x 4096) x (2048 x 4096)^T
    gemm_hmma_fp16<<<dim3(DMODEL / 128, M / 128), 256, GEMM1_SMEM>>>(
        (const __half*)ynh_p, (const __half*)owh_p, out, M, DMODEL, DINNER);

    (void)in_sizes; (void)n_in; (void)out_size;
}

// round 7
// speedup vs baseline: 3.2617x; 1.3141x over previous
#include <cuda_runtime.h>
#include <cuda_bf16.h>
#include <cuda_fp16.h>
#include <cstdint>

#define B_SZ 2
#define SEQL 2048
#define DMODEL 2048
#define DINNER 4096
#define DSTATE 128
#define HEADDIM 64
#define NHEADS 64
#define CHUNKL 256
#define NCHUNK 8
#define CONV_DIM 4352     // DINNER + 2*DSTATE
#define D_IN_PROJ 8512    // 2*DINNER + 2*DSTATE + NHEADS
#define DIP_PAD 8576      // 67*128
#define EPSV 1e-5f

// ---------------- scratch ----------------
__device__ float g_zx[B_SZ*SEQL*D_IN_PROJ];
__device__ float g_xBC[B_SZ*SEQL*CONV_DIM];
__device__ float g_dt[B_SZ*SEQL*NHEADS];
__device__ float g_Acs[B_SZ*NHEADS*NCHUNK*CHUNKL];
__device__ float g_states[(size_t)B_SZ*NCHUNK*NHEADS*HEADDIM*DSTATE];
__device__ float g_prev[(size_t)B_SZ*NCHUNK*NHEADS*HEADDIM*DSTATE];
__device__ float g_yg[B_SZ*SEQL*DINNER];
// fp16 operands
__device__ __half g_xh[B_SZ*SEQL*DMODEL];
__device__ __half g_wih[(size_t)DIP_PAD*DMODEL];
__device__ __half g_ynh[B_SZ*SEQL*DINNER];
__device__ __half g_owh[(size_t)DMODEL*DINNER];

__device__ __forceinline__ float siluf(float a) { return a / (1.f + expf(-a)); }

// ================= fp16 HMMA GEMM =================
// Operand tile: 128 rows x 32 half-words (64B/row), XOR-swizzled, 8KB.
#define OPW  2048                         // words per operand tile
#define STGW_H (2 * OPW)                  // stage words (A,B)
#define GEMM1_SMEM (4 * STGW_H * 4)       // 65536 B, 4 stages

__device__ __forceinline__ void mma_fp16(float* c, const uint32_t* a, const uint32_t* b) {
    asm volatile(
        "mma.sync.aligned.m16n8k16.row.col.f32.f16.f16.f32 "
        "{%0,%1,%2,%3}, {%4,%5,%6,%7}, {%8,%9}, {%0,%1,%2,%3};"
        : "+f"(c[0]), "+f"(c[1]), "+f"(c[2]), "+f"(c[3])
        : "r"(a[0]), "r"(a[1]), "r"(a[2]), "r"(a[3]), "r"(b[0]), "r"(b[1]));
}
__device__ __forceinline__ void ldsm4(uint32_t* r, uint32_t addr) {
    asm volatile("ldmatrix.sync.aligned.m8n8.x4.shared.b16 {%0,%1,%2,%3}, [%4];"
        : "=r"(r[0]), "=r"(r[1]), "=r"(r[2]), "=r"(r[3]) : "r"(addr));
}
__device__ __forceinline__ void cp16(uint32_t dst, const void* src) {
    asm volatile("cp.async.cg.shared.global [%0], [%1], 16;" :: "r"(dst), "l"(src));
}
__device__ __forceinline__ uint32_t smem_u32(const void* p) {
    uint32_t a;
    asm("{ .reg .u64 t; cvta.to.shared.u64 t, %1; cvt.u32.u64 %0, t; }" : "=r"(a) : "l"(p));
    return a;
}
// swizzled 128x32x16bit tile load: logical (r, chunk) -> word r*16 + ((chunk^((r>>1)&3))<<2)
__device__ __forceinline__ void load_op(uint32_t sbase_b, const __half* g, int ldk, int tid) {
#pragma unroll
    for (int it = 0; it < 2; it++) {
        int v = tid + (it << 8);
        int r = v >> 2, ch = v & 3;
        int sch = ch ^ ((r >> 1) & 3);
        cp16(sbase_b + (r * 16 + (sch << 2)) * 4, g + (size_t)r * ldk + (ch << 3));
    }
}

// ---------------- fp16 single-product GEMM: C = A * B^T ----------------
__global__ __launch_bounds__(256, 2) void gemm_hmma_fp16(
    const __half* __restrict__ A, const __half* __restrict__ B,
    float* __restrict__ C, int M, int Nreal, int K)
{
    extern __shared__ uint32_t sw[];
    const uint32_t sb = smem_u32(sw);
    const int tid = threadIdx.x, wid = tid >> 5, lane = tid & 31;
    const int warp_m = wid & 1, warp_n = wid >> 1;
    const int m0 = blockIdx.y << 7, n0 = blockIdx.x << 7;
    const int KT = K >> 5;

    const __half* Ab = A + (size_t)m0 * K;
    const __half* Bb = B + (size_t)n0 * K;

    float acc[4][4][4];
#pragma unroll
    for (int i = 0; i < 4; i++)
#pragma unroll
        for (int j = 0; j < 4; j++)
#pragma unroll
            for (int q = 0; q < 4; q++) acc[i][j][q] = 0.f;

    // prologue: stages 0..2
#pragma unroll
    for (int s = 0; s < 3; s++) {
        int koff = s << 5;
        load_op(sb + (s * STGW_H + 0 * OPW) * 4, Ab + koff, K, tid);
        load_op(sb + (s * STGW_H + 1 * OPW) * 4, Bb + koff, K, tid);
        asm volatile("cp.async.commit_group;" ::: "memory");
    }

    const int rowA = warp_m * 64 + ((lane >> 3) & 1) * 8 + (lane & 7);
    const int swzA = (rowA >> 1) & 3;
    const int cA0  = lane >> 4;
    const int rowB = warp_n * 32 + ((lane >> 4) & 1) * 8 + (lane & 7);
    const int swzB = (rowB >> 1) & 3;
    const int cB0  = (lane >> 3) & 1;

    int buf = 0;
    for (int kt = 0; kt < KT; kt++) {
        asm volatile("cp.async.wait_group 2;" ::: "memory");
        __syncthreads();
        if (kt + 3 < KT) {
            int s = buf + 3; if (s >= 4) s -= 4;
            int koff = (kt + 3) << 5;
            load_op(sb + (s * STGW_H + 0 * OPW) * 4, Ab + koff, K, tid);
            load_op(sb + (s * STGW_H + 1 * OPW) * 4, Bb + koff, K, tid);
        }
        asm volatile("cp.async.commit_group;" ::: "memory");

        const uint32_t stgb = sb + (uint32_t)buf * STGW_H * 4u;
        const uint32_t sA = stgb;
        const uint32_t sB = stgb + OPW * 4u;

#pragma unroll
        for (int kk = 0; kk < 2; kk++) {
            const int cA = (kk << 1) + cA0;
            const int cB = (kk << 1) + cB0;
            uint32_t a[4][4];
#pragma unroll
            for (int mi = 0; mi < 4; mi++) {
                uint32_t off = (((rowA + mi * 16) * 16) + ((cA ^ swzA) << 2)) * 4u;
                ldsm4(a[mi], sA + off);
            }
#pragma unroll
            for (int np = 0; np < 2; np++) {
                uint32_t boff = (((rowB + np * 16) * 16) + ((cB ^ swzB) << 2)) * 4u;
                uint32_t b[4];
                ldsm4(b, sB + boff);
#pragma unroll
                for (int mi = 0; mi < 4; mi++) {
                    mma_fp16(acc[mi][2 * np], a[mi], b);
                    mma_fp16(acc[mi][2 * np + 1], a[mi], b + 2);
                }
            }
        }
        buf++; if (buf == 4) buf = 0;
    }

#pragma unroll
    for (int mi = 0; mi < 4; mi++) {
        int rg0 = m0 + warp_m * 64 + mi * 16 + (lane >> 2);
#pragma unroll
        for (int ni = 0; ni < 4; ni++) {
            int cg = n0 + warp_n * 32 + ni * 8 + ((lane & 3) << 1);
            if (cg < Nreal) {
                *(float2*)(C + (size_t)rg0 * Nreal + cg) =
                    make_float2(acc[mi][ni][0], acc[mi][ni][1]);
                *(float2*)(C + (size_t)(rg0 + 8) * Nreal + cg) =
                    make_float2(acc[mi][ni][2], acc[mi][ni][3]);
            }
        }
    }
}

// ---------------- fp32 -> fp16 (with zero-pad tail) ----------------
__global__ void cvt_half(const float* __restrict__ src, __half* __restrict__ dst,
                         long n_src, long n_tot)
{
    long i = ((long)blockIdx.x * 256 + threadIdx.x) * 4;
    if (i >= n_tot) return;
    float4 v = (i < n_src) ? *(const float4*)(src + i) : make_float4(0.f, 0.f, 0.f, 0.f);
    __half2* dp = (__half2*)(dst + i);
    dp[0] = __floats2half2_rn(v.x, v.y);
    dp[1] = __floats2half2_rn(v.z, v.w);
}

// ---------------- causal depthwise conv (width 4) + silu ----------------
__global__ void conv_silu_kernel(const float* __restrict__ conv_w,
                                 const float* __restrict__ conv_b)
{
    int c = blockIdx.x * 128 + threadIdx.x;
    int b = blockIdx.y;
    int t0 = blockIdx.z * 256;
    float w0 = conv_w[c * 4 + 0], w1 = conv_w[c * 4 + 1];
    float w2 = conv_w[c * 4 + 2], w3 = conv_w[c * 4 + 3];
    float bias = conv_b[c];
    const float* src = g_zx + (size_t)b * SEQL * D_IN_PROJ + DINNER + c;
    float* dst = g_xBC + (size_t)b * SEQL * CONV_DIM + c;
    float x0 = (t0 >= 3) ? src[(size_t)(t0 - 3) * D_IN_PROJ] : 0.f;
    float x1 = (t0 >= 2) ? src[(size_t)(t0 - 2) * D_IN_PROJ] : 0.f;
    float x2 = (t0 >= 1) ? src[(size_t)(t0 - 1) * D_IN_PROJ] : 0.f;
    for (int t = t0; t < t0 + 256; t++) {
        float x3 = src[(size_t)t * D_IN_PROJ];
        float a = bias + w0 * x0 + w1 * x1 + w2 * x2 + w3 * x3;
        dst[(size_t)t * CONV_DIM] = siluf(a);
        x0 = x1; x1 = x2; x2 = x3;
    }
}

// ---------------- dt softplus + per-chunk cumsum of dA ----------------
__global__ void dt_scan_kernel(const float* __restrict__ dt_bias,
                               const float* __restrict__ A_log)
{
    int idx = blockIdx.x;
    int c = idx % NCHUNK; idx /= NCHUNK;
    int h = idx % NHEADS;
    int b = idx / NHEADS;
    int l = threadIdx.x;
    int t = c * CHUNKL + l;
    float raw = g_zx[(size_t)(b * SEQL + t) * D_IN_PROJ + DINNER + CONV_DIM + h];
    float xv = raw + dt_bias[h];
    float dt = (xv > 20.f) ? xv : log1pf(expf(xv));
    g_dt[(b * SEQL + t) * NHEADS + h] = dt;
    float dA = dt * (-expf(A_log[h]));
    __shared__ float s[CHUNKL];
    s[l] = dA;
    __syncthreads();
    for (int off = 1; off < CHUNKL; off <<= 1) {
        float v = (l >= off) ? s[l - off] : 0.f;
        __syncthreads();
        s[l] += v;
        __syncthreads();
    }
    g_Acs[((b * NHEADS + h) * NCHUNK + c) * CHUNKL + l] = s[l];
}

// ---------------- per-chunk states ----------------
__global__ __launch_bounds__(256) void states_kernel()
{
    __shared__ float Bd[32][132];
    __shared__ float Xs[32][68];
    __shared__ float dec[32];
    __shared__ float dts[32];
    int idx = blockIdx.x;
    int h = idx % NHEADS; idx /= NHEADS;
    int c = idx % NCHUNK;
    int b = idx / NCHUNK;
    int tid = threadIdx.x;
    int tx = tid & 15, ty = tid >> 4;
    const float* acs = g_Acs + ((b * NHEADS + h) * NCHUNK + c) * CHUNKL;
    float acs_last = acs[CHUNKL - 1];
    float acc[4][8];
#pragma unroll
    for (int i = 0; i < 4; i++)
#pragma unroll
        for (int j = 0; j < 8; j++) acc[i][j] = 0.f;

    for (int l0 = 0; l0 < CHUNKL; l0 += 32) {
        if (tid < 32) {
            int t = c * CHUNKL + l0 + tid;
            dec[tid] = expf(acs_last - acs[l0 + tid]);
            dts[tid] = g_dt[(b * SEQL + t) * NHEADS + h];
        }
        __syncthreads();
#pragma unroll
        for (int it = 0; it < 4; it++) {
            int v = tid + it * 256;
            int r = v >> 5, nn = (v & 31) << 2;
            int t = c * CHUNKL + l0 + r;
            float4 f = *(const float4*)(g_xBC + (size_t)(b * SEQL + t) * CONV_DIM + DINNER + nn);
            float d = dec[r];
            Bd[r][nn + 0] = f.x * d; Bd[r][nn + 1] = f.y * d;
            Bd[r][nn + 2] = f.z * d; Bd[r][nn + 3] = f.w * d;
        }
#pragma unroll
        for (int it = 0; it < 2; it++) {
            int v = tid + it * 256;
            int r = v >> 4, pp = (v & 15) << 2;
            int t = c * CHUNKL + l0 + r;
            float4 f = *(const float4*)(g_xBC + (size_t)(b * SEQL + t) * CONV_DIM + h * HEADDIM + pp);
            float d = dts[r];
            *(float4*)&Xs[r][pp] = make_float4(f.x * d, f.y * d, f.z * d, f.w * d);
        }
        __syncthreads();
#pragma unroll
        for (int l = 0; l < 32; l++) {
            float a[4], bb[8];
            *(float4*)a = *(const float4*)&Xs[l][ty * 4];
            *(float4*)(bb)     = *(const float4*)&Bd[l][tx * 8];
            *(float4*)(bb + 4) = *(const float4*)&Bd[l][tx * 8 + 4];
#pragma unroll
            for (int i = 0; i < 4; i++)
#pragma unroll
                for (int j = 0; j < 8; j++) acc[i][j] += a[i] * bb[j];
        }
        __syncthreads();
    }
    float* out = g_states + (size_t)((b * NCHUNK + c) * NHEADS + h) * HEADDIM * DSTATE;
#pragma unroll
    for (int i = 0; i < 4; i++)
#pragma unroll
        for (int j = 0; j < 8; j += 4)
            *(float4*)(out + (ty * 4 + i) * DSTATE + tx * 8 + j) =
                make_float4(acc[i][j], acc[i][j+1], acc[i][j+2], acc[i][j+3]);
}

// ---------------- inter-chunk recurrence ----------------
__global__ __launch_bounds__(256) void prev_kernel()
{
    int b = blockIdx.x >> 6;
    int h = blockIdx.x & 63;
    int tid = threadIdx.x;
    float P[32];
#pragma unroll
    for (int i = 0; i < 32; i++) P[i] = 0.f;
    for (int c = 0; c < NCHUNK; c++) {
        float decay = expf(g_Acs[((b * NHEADS + h) * NCHUNK + c) * CHUNKL + CHUNKL - 1]);
        size_t base = (size_t)((b * NCHUNK + c) * NHEADS + h) * HEADDIM * DSTATE;
#pragma unroll
        for (int i = 0; i < 32; i++) {
            int e = i * 256 + tid;
            g_prev[base + e] = P[i];
            P[i] = P[i] * decay + g_states[base + e];
        }
    }
}

// ---------------- Y (diag + off) + gate ----------------
__global__ __launch_bounds__(256, 2) void y_kernel(const float* __restrict__ Dp)
{
    extern __shared__ float sm[];
    float* Cst = sm;
    float* Bst = Cst + 128 * 68;
    float* Xs  = Bst + 128 * 68;
    float* St  = Xs  + 64 * 68;
    float* acs = St  + 64 * 68;

    int idx = blockIdx.x;
    int lt = idx & 3; idx >>= 2;
    int h = idx % NHEADS; idx /= NHEADS;
    int c = idx % NCHUNK;
    int b = idx / NCHUNK;
    int tid = threadIdx.x;
    int tx = tid & 15, ty = tid >> 4;
    int l0 = lt * 64;

    const float* acs_g = g_Acs + ((b * NHEADS + h) * NCHUNK + c) * CHUNKL;
    acs[tid] = acs_g[tid];

#pragma unroll
    for (int it = 0; it < 8; it++) {
        int v = tid + it * 256;
        int r = v >> 5, nn = (v & 31) << 2;
        int t = c * CHUNKL + l0 + r;
        float4 f = *(const float4*)(g_xBC + (size_t)(b * SEQL + t) * CONV_DIM + DINNER + DSTATE + nn);
        Cst[(nn + 0) * 68 + r] = f.x; Cst[(nn + 1) * 68 + r] = f.y;
        Cst[(nn + 2) * 68 + r] = f.z; Cst[(nn + 3) * 68 + r] = f.w;
    }
    __syncthreads();

    float Yacc[4][4];
#pragma unroll
    for (int i = 0; i < 4; i++)
#pragma unroll
        for (int j = 0; j < 4; j++) Yacc[i][j] = 0.f;

    for (int st = 0; st <= lt; st++) {
        int s0 = st * 64;
#pragma unroll
        for (int it = 0; it < 8; it++) {
            int v = tid + it * 256;
            int r = v >> 5, nn = (v & 31) << 2;
            int t = c * CHUNKL + s0 + r;
            float4 f = *(const float4*)(g_xBC + (size_t)(b * SEQL + t) * CONV_DIM + DINNER + nn);
            Bst[(nn + 0) * 68 + r] = f.x; Bst[(nn + 1) * 68 + r] = f.y;
            Bst[(nn + 2) * 68 + r] = f.z; Bst[(nn + 3) * 68 + r] = f.w;
        }
#pragma unroll
        for (int it = 0; it < 4; it++) {
            int v = tid + it * 256;
            int r = v >> 4, pp = (v & 15) << 2;
            int t = c * CHUNKL + s0 + r;
            float4 f = *(const float4*)(g_xBC + (size_t)(b * SEQL + t) * CONV_DIM + h * HEADDIM + pp);
            float d = g_dt[(b * SEQL + t) * NHEADS + h];
            *(float4*)&Xs[r * 68 + pp] = make_float4(f.x * d, f.y * d, f.z * d, f.w * d);
        }
        __syncthreads();

        float sacc[4][4];
#pragma unroll
        for (int i = 0; i < 4; i++)
#pragma unroll
            for (int j = 0; j < 4; j++) sacc[i][j] = 0.f;
#pragma unroll 4
        for (int n = 0; n < 128; n++) {
            float4 a4 = *(const float4*)&Cst[n * 68 + (ty << 2)];
            float4 b4 = *(const float4*)&Bst[n * 68 + (tx << 2)];
            float a[4] = {a4.x, a4.y, a4.z, a4.w};
            float bb[4] = {b4.x, b4.y, b4.z, b4.w};
#pragma unroll
            for (int i = 0; i < 4; i++)
#pragma unroll
                for (int j = 0; j < 4; j++) sacc[i][j] += a[i] * bb[j];
        }
#pragma unroll
        for (int j = 0; j < 4; j++) {
            int sg = s0 + (tx << 2) + j;
            float col[4];
#pragma unroll
            for (int i = 0; i < 4; i++) {
                int lg = l0 + (ty << 2) + i;
                col[i] = (sg <= lg) ? sacc[i][j] * expf(acs[lg] - acs[sg]) : 0.f;
            }
            *(float4*)&St[((tx << 2) + j) * 68 + (ty << 2)] =
                make_float4(col[0], col[1], col[2], col[3]);
        }
        __syncthreads();
#pragma unroll 4
        for (int s = 0; s < 64; s++) {
            float4 a4 = *(const float4*)&St[s * 68 + (ty << 2)];
            float4 x4 = *(const float4*)&Xs[s * 68 + (tx << 2)];
            float a[4] = {a4.x, a4.y, a4.z, a4.w};
            float xx[4] = {x4.x, x4.y, x4.z, x4.w};
#pragma unroll
            for (int i = 0; i < 4; i++)
#pragma unroll
                for (int j = 0; j < 4; j++) Yacc[i][j] += a[i] * xx[j];
        }
        __syncthreads();
    }

    size_t pbase = (size_t)((b * NCHUNK + c) * NHEADS + h) * HEADDIM * DSTATE;
#pragma unroll
    for (int it = 0; it < 8; it++) {
        int v = tid + it * 256;
        int p = v >> 5, nn = (v & 31) << 2;
        float4 f = *(const float4*)(g_prev + pbase + p * DSTATE + nn);
        Bst[(nn + 0) * 68 + p] = f.x; Bst[(nn + 1) * 68 + p] = f.y;
        Bst[(nn + 2) * 68 + p] = f.z; Bst[(nn + 3) * 68 + p] = f.w;
    }
    __syncthreads();
    float toff[4][4];
#pragma unroll
    for (int i = 0; i < 4; i++)
#pragma unroll
        for (int j = 0; j < 4; j++) toff[i][j] = 0.f;
#pragma unroll 4
    for (int n = 0; n < 128; n++) {
        float4 a4 = *(const float4*)&Cst[n * 68 + (ty << 2)];
        float4 b4 = *(const float4*)&Bst[n * 68 + (tx << 2)];
        float a[4] = {a4.x, a4.y, a4.z, a4.w};
        float bb[4] = {b4.x, b4.y, b4.z, b4.w};
#pragma unroll
        for (int i = 0; i < 4; i++)
#pragma unroll
            for (int j = 0; j < 4; j++) toff[i][j] += a[i] * bb[j];
    }

    float Dh = Dp[h];
#pragma unroll
    for (int i = 0; i < 4; i++) {
        int lg = l0 + (ty << 2) + i;
        int t = c * CHUNKL + lg;
        float el = expf(acs[lg]);
        float4 xs4 = *(const float4*)(g_xBC + (size_t)(b * SEQL + t) * CONV_DIM + h * HEADDIM + (tx << 2));
        float4 z4  = *(const float4*)(g_zx + (size_t)(b * SEQL + t) * D_IN_PROJ + h * HEADDIM + (tx << 2));
        float4 o;
        o.x = (Yacc[i][0] + el * toff[i][0] + xs4.x * Dh) * siluf(z4.x);
        o.y = (Yacc[i][1] + el * toff[i][1] + xs4.y * Dh) * siluf(z4.y);
        o.z = (Yacc[i][2] + el * toff[i][2] + xs4.z * Dh) * siluf(z4.z);
        o.w = (Yacc[i][3] + el * toff[i][3] + xs4.w * Dh) * siluf(z4.w);
        *(float4*)(g_yg + (size_t)(b * SEQL + t) * DINNER + h * HEADDIM + (tx << 2)) = o;
    }
}

// ---------------- RMSNorm -> fp16 ----------------
__global__ __launch_bounds__(256) void rmsnorm_kernel(const float* __restrict__ w)
{
    int row = blockIdx.x;
    const float* y = g_yg + (size_t)row * DINNER;
    __half* oh = g_ynh + (size_t)row * DINNER;
    int tid = threadIdx.x;
    float ss = 0.f;
#pragma unroll
    for (int it = 0; it < 4; it++) {
        float4 v = *(const float4*)(y + it * 1024 + tid * 4);
        ss += v.x * v.x + v.y * v.y + v.z * v.z + v.w * v.w;
    }
#pragma unroll
    for (int off = 16; off; off >>= 1) ss += __shfl_xor_sync(0xFFFFFFFFu, ss, off);
    __shared__ float red[8];
    if ((tid & 31) == 0) red[tid >> 5] = ss;
    __syncthreads();
    float tot = 0.f;
#pragma unroll
    for (int i = 0; i < 8; i++) tot += red[i];
    float scale = rsqrtf(tot / (float)DINNER + EPSV);
#pragma unroll
    for (int it = 0; it < 4; it++) {
        int i = it * 1024 + tid * 4;
        float4 v = *(const float4*)(y + i);
        float4 wv = *(const float4*)(w + i);
        __half2* hp = (__half2*)(oh + i);
        hp[0] = __floats2half2_rn(v.x * scale * wv.x, v.y * scale * wv.y);
        hp[1] = __floats2half2_rn(v.z * scale * wv.z, v.w * scale * wv.w);
    }
}

// ---------------- launch ----------------
extern "C" void kernel_launch(void* const* d_in, const int* in_sizes, int n_in,
                              void* d_out, int out_size)
{
    const float* x          = (const float*)d_in[0];
    const float* in_proj_w  = (const float*)d_in[1];
    const float* conv_w     = (const float*)d_in[2];
    const float* conv_b     = (const float*)d_in[3];
    const float* dt_bias    = (const float*)d_in[4];
    const float* A_log      = (const float*)d_in[5];
    const float* Dp         = (const float*)d_in[6];
    const float* norm_w     = (const float*)d_in[7];
    const float* out_proj_w = (const float*)d_in[8];
    float* out = (float*)d_out;

    float *zx_p = nullptr;
    __half *xh_p, *wih_p, *ynh_p, *owh_p;
    cudaGetSymbolAddress((void**)&zx_p, g_zx);
    cudaGetSymbolAddress((void**)&xh_p, g_xh);
    cudaGetSymbolAddress((void**)&wih_p, g_wih);
    cudaGetSymbolAddress((void**)&ynh_p, g_ynh);
    cudaGetSymbolAddress((void**)&owh_p, g_owh);

    static bool attr_set = false;
    if (!attr_set) {
        cudaFuncSetAttribute(gemm_hmma_fp16, cudaFuncAttributeMaxDynamicSharedMemorySize, GEMM1_SMEM);
        const int YS = (2 * 128 * 68 + 2 * 64 * 68 + 256) * sizeof(float);
        cudaFuncSetAttribute(y_kernel, cudaFuncAttributeMaxDynamicSharedMemorySize, YS);
        attr_set = true;
    }

    const int M = B_SZ * SEQL; // 4096

    // converts
    {
        long n = (long)M * DMODEL;
        cvt_half<<<(unsigned)((n / 4 + 255) / 256), 256>>>(x, xh_p, n, n);
    }
    {
        long ns = (long)D_IN_PROJ * DMODEL, nt = (long)DIP_PAD * DMODEL;
        cvt_half<<<(unsigned)((nt / 4 + 255) / 256), 256>>>(in_proj_w, wih_p, ns, nt);
    }
    {
        long n = (long)DMODEL * DINNER;
        cvt_half<<<(unsigned)((n / 4 + 255) / 256), 256>>>(out_proj_w, owh_p, n, n);
    }

    // 1) in_proj GEMM (fp16): (4096 x 2048) x (8512 x 2048)^T
    gemm_hmma_fp16<<<dim3(DIP_PAD / 128, M / 128), 256, GEMM1_SMEM>>>(
        xh_p, wih_p, zx_p, M, D_IN_PROJ, DMODEL);

    // 2) conv + silu
    conv_silu_kernel<<<dim3(CONV_DIM / 128, B_SZ, SEQL / 256), 128>>>(conv_w, conv_b);

    // 3) dt softplus + cumsum
    dt_scan_kernel<<<B_SZ * NHEADS * NCHUNK, CHUNKL>>>(dt_bias, A_log);

    // 4) states
    states_kernel<<<B_SZ * NCHUNK * NHEADS, 256>>>();

    // 5) recurrence
    prev_kernel<<<B_SZ * NHEADS, 256>>>();

    // 6) Y + gate
    const int YS = (2 * 128 * 68 + 2 * 64 * 68 + 256) * sizeof(float);
    y_kernel<<<B_SZ * NCHUNK * NHEADS * 4, 256, YS>>>(Dp);

    // 7) RMSNorm -> fp16
    rmsnorm_kernel<<<B_SZ * SEQL, 256>>>(norm_w);

    // 8) out_proj GEMM (fp16): (4096 x 4096) x (2048 x 4096)^T
    gemm_hmma_fp16<<<dim3(DMODEL / 128, M / 128), 256, GEMM1_SMEM>>>(
        ynh_p, owh_p, out, M, DMODEL, DINNER);

    (void)in_sizes; (void)n_in; (void)out_size;
}

// round 8
// speedup vs baseline: 5.0754x; 1.5561x over previous
#include <cuda_runtime.h>
#include <cuda_bf16.h>
#include <cuda_fp16.h>
#include <cstdint>
#include <cstring>

#define B_SZ 2
#define SEQL 2048
#define DMODEL 2048
#define DINNER 4096
#define DSTATE 128
#define HEADDIM 64
#define NHEADS 64
#define CHUNKL 256
#define NCHUNK 8
#define CONV_DIM 4352     // DINNER + 2*DSTATE
#define D_IN_PROJ 8512    // 2*DINNER + 2*DSTATE + NHEADS
#define DIP_PAD 8576      // 67*128
#define EPSV 1e-5f

// ---------------- scratch ----------------
__device__ float g_zx[B_SZ*SEQL*D_IN_PROJ];
__device__ float g_xBC[B_SZ*SEQL*CONV_DIM];
__device__ float g_dt[B_SZ*SEQL*NHEADS];
__device__ float g_Acs[B_SZ*NHEADS*NCHUNK*CHUNKL];
__device__ float g_states[(size_t)B_SZ*NCHUNK*NHEADS*HEADDIM*DSTATE];
__device__ float g_yg[B_SZ*SEQL*DINNER];
// fp16 gemm operands
__device__ __half g_xh[B_SZ*SEQL*DMODEL];
__device__ __half g_wih[(size_t)DIP_PAD*DMODEL];
__device__ __half g_ynh[B_SZ*SEQL*DINNER];
__device__ __half g_owh[(size_t)DMODEL*DINNER];
// split-fp16 SSM operands
__device__ __half g_Bh[B_SZ*SEQL*DSTATE],  g_Bl[B_SZ*SEQL*DSTATE];
__device__ __half g_Ch[B_SZ*SEQL*DSTATE],  g_Cl[B_SZ*SEQL*DSTATE];
__device__ __half g_BTh[B_SZ*DSTATE*SEQL], g_BTl[B_SZ*DSTATE*SEQL];
__device__ __half g_XdTh[(size_t)B_SZ*NHEADS*HEADDIM*SEQL], g_XdTl[(size_t)B_SZ*NHEADS*HEADDIM*SEQL];
__device__ __half g_XdecTh[(size_t)B_SZ*NHEADS*HEADDIM*SEQL], g_XdecTl[(size_t)B_SZ*NHEADS*HEADDIM*SEQL];
__device__ __half g_prevh[(size_t)B_SZ*NCHUNK*NHEADS*HEADDIM*DSTATE];
__device__ __half g_prevl[(size_t)B_SZ*NCHUNK*NHEADS*HEADDIM*DSTATE];

__device__ __forceinline__ float siluf(float a) { return a / (1.f + expf(-a)); }

// ================= common HMMA helpers =================
__device__ __forceinline__ void mma_fp16(float* c, const uint32_t* a, const uint32_t* b) {
    asm volatile(
        "mma.sync.aligned.m16n8k16.row.col.f32.f16.f16.f32 "
        "{%0,%1,%2,%3}, {%4,%5,%6,%7}, {%8,%9}, {%0,%1,%2,%3};"
        : "+f"(c[0]), "+f"(c[1]), "+f"(c[2]), "+f"(c[3])
        : "r"(a[0]), "r"(a[1]), "r"(a[2]), "r"(a[3]), "r"(b[0]), "r"(b[1]));
}
__device__ __forceinline__ void ldsm4(uint32_t* r, uint32_t addr) {
    asm volatile("ldmatrix.sync.aligned.m8n8.x4.shared.b16 {%0,%1,%2,%3}, [%4];"
        : "=r"(r[0]), "=r"(r[1]), "=r"(r[2]), "=r"(r[3]) : "r"(addr));
}
__device__ __forceinline__ void cp16(uint32_t dst, const void* src) {
    asm volatile("cp.async.cg.shared.global [%0], [%1], 16;" :: "r"(dst), "l"(src));
}
__device__ __forceinline__ uint32_t smem_u32(const void* p) {
    uint32_t a;
    asm("{ .reg .u64 t; cvta.to.shared.u64 t, %1; cvt.u32.u64 %0, t; }" : "=r"(a) : "l"(p));
    return a;
}
__device__ __forceinline__ uint32_t packh2(__half a, __half b) {
    __half2 h = __halves2half2(a, b);
    uint32_t u; memcpy(&u, &h, 4); return u;
}
__device__ __forceinline__ void split_store2(__half* hi, __half* lo, size_t o, float a, float b) {
    __half ha = __float2half_rn(a), hb = __float2half_rn(b);
    *(__half2*)(hi + o) = __halves2half2(ha, hb);
    *(__half2*)(lo + o) = __halves2half2(__float2half_rn(a - __half2float(ha)),
                                         __float2half_rn(b - __half2float(hb)));
}

// ================= fp16 HMMA GEMM (projections) =================
#define OPW  2048
#define STGW_H (2 * OPW)
#define GEMM1_SMEM (4 * STGW_H * 4)

__device__ __forceinline__ void load_op(uint32_t sbase_b, const __half* g, int ldk, int tid) {
#pragma unroll
    for (int it = 0; it < 2; it++) {
        int v = tid + (it << 8);
        int r = v >> 2, ch = v & 3;
        int sch = ch ^ ((r >> 1) & 3);
        cp16(sbase_b + (r * 16 + (sch << 2)) * 4, g + (size_t)r * ldk + (ch << 3));
    }
}

__global__ __launch_bounds__(256, 2) void gemm_hmma_fp16(
    const __half* __restrict__ A, const __half* __restrict__ B,
    float* __restrict__ C, int M, int Nreal, int K)
{
    extern __shared__ uint32_t sw[];
    const uint32_t sb = smem_u32(sw);
    const int tid = threadIdx.x, wid = tid >> 5, lane = tid & 31;
    const int warp_m = wid & 1, warp_n = wid >> 1;
    const int m0 = blockIdx.y << 7, n0 = blockIdx.x << 7;
    const int KT = K >> 5;

    const __half* Ab = A + (size_t)m0 * K;
    const __half* Bb = B + (size_t)n0 * K;

    float acc[4][4][4];
#pragma unroll
    for (int i = 0; i < 4; i++)
#pragma unroll
        for (int j = 0; j < 4; j++)
#pragma unroll
            for (int q = 0; q < 4; q++) acc[i][j][q] = 0.f;

#pragma unroll
    for (int s = 0; s < 3; s++) {
        int koff = s << 5;
        load_op(sb + (s * STGW_H + 0 * OPW) * 4, Ab + koff, K, tid);
        load_op(sb + (s * STGW_H + 1 * OPW) * 4, Bb + koff, K, tid);
        asm volatile("cp.async.commit_group;" ::: "memory");
    }

    const int rowA = warp_m * 64 + ((lane >> 3) & 1) * 8 + (lane & 7);
    const int swzA = (rowA >> 1) & 3;
    const int cA0  = lane >> 4;
    const int rowB = warp_n * 32 + ((lane >> 4) & 1) * 8 + (lane & 7);
    const int swzB = (rowB >> 1) & 3;
    const int cB0  = (lane >> 3) & 1;

    int buf = 0;
    for (int kt = 0; kt < KT; kt++) {
        asm volatile("cp.async.wait_group 2;" ::: "memory");
        __syncthreads();
        if (kt + 3 < KT) {
            int s = buf + 3; if (s >= 4) s -= 4;
            int koff = (kt + 3) << 5;
            load_op(sb + (s * STGW_H + 0 * OPW) * 4, Ab + koff, K, tid);
            load_op(sb + (s * STGW_H + 1 * OPW) * 4, Bb + koff, K, tid);
        }
        asm volatile("cp.async.commit_group;" ::: "memory");

        const uint32_t stgb = sb + (uint32_t)buf * STGW_H * 4u;
        const uint32_t sA = stgb;
        const uint32_t sB = stgb + OPW * 4u;

#pragma unroll
        for (int kk = 0; kk < 2; kk++) {
            const int cA = (kk << 1) + cA0;
            const int cB = (kk << 1) + cB0;
            uint32_t a[4][4];
#pragma unroll
            for (int mi = 0; mi < 4; mi++) {
                uint32_t off = (((rowA + mi * 16) * 16) + ((cA ^ swzA) << 2)) * 4u;
                ldsm4(a[mi], sA + off);
            }
#pragma unroll
            for (int np = 0; np < 2; np++) {
                uint32_t boff = (((rowB + np * 16) * 16) + ((cB ^ swzB) << 2)) * 4u;
                uint32_t b[4];
                ldsm4(b, sB + boff);
#pragma unroll
                for (int mi = 0; mi < 4; mi++) {
                    mma_fp16(acc[mi][2 * np], a[mi], b);
                    mma_fp16(acc[mi][2 * np + 1], a[mi], b + 2);
                }
            }
        }
        buf++; if (buf == 4) buf = 0;
    }

#pragma unroll
    for (int mi = 0; mi < 4; mi++) {
        int rg0 = m0 + warp_m * 64 + mi * 16 + (lane >> 2);
#pragma unroll
        for (int ni = 0; ni < 4; ni++) {
            int cg = n0 + warp_n * 32 + ni * 8 + ((lane & 3) << 1);
            if (cg < Nreal) {
                *(float2*)(C + (size_t)rg0 * Nreal + cg) =
                    make_float2(acc[mi][ni][0], acc[mi][ni][1]);
                *(float2*)(C + (size_t)(rg0 + 8) * Nreal + cg) =
                    make_float2(acc[mi][ni][2], acc[mi][ni][3]);
            }
        }
    }
}

// ---------------- fp32 -> fp16 (with zero-pad tail) ----------------
__global__ void cvt_half(const float* __restrict__ src, __half* __restrict__ dst,
                         long n_src, long n_tot)
{
    long i = ((long)blockIdx.x * 256 + threadIdx.x) * 4;
    if (i >= n_tot) return;
    float4 v = (i < n_src) ? *(const float4*)(src + i) : make_float4(0.f, 0.f, 0.f, 0.f);
    __half2* dp = (__half2*)(dst + i);
    dp[0] = __floats2half2_rn(v.x, v.y);
    dp[1] = __floats2half2_rn(v.z, v.w);
}

// ---------------- causal depthwise conv (width 4) + silu ----------------
__global__ void conv_silu_kernel(const float* __restrict__ conv_w,
                                 const float* __restrict__ conv_b)
{
    int c = blockIdx.x * 128 + threadIdx.x;
    int b = blockIdx.y;
    int t0 = blockIdx.z * 256;
    float w0 = conv_w[c * 4 + 0], w1 = conv_w[c * 4 + 1];
    float w2 = conv_w[c * 4 + 2], w3 = conv_w[c * 4 + 3];
    float bias = conv_b[c];
    const float* src = g_zx + (size_t)b * SEQL * D_IN_PROJ + DINNER + c;
    float* dst = g_xBC + (size_t)b * SEQL * CONV_DIM + c;
    float x0 = (t0 >= 3) ? src[(size_t)(t0 - 3) * D_IN_PROJ] : 0.f;
    float x1 = (t0 >= 2) ? src[(size_t)(t0 - 2) * D_IN_PROJ] : 0.f;
    float x2 = (t0 >= 1) ? src[(size_t)(t0 - 1) * D_IN_PROJ] : 0.f;
    for (int t = t0; t < t0 + 256; t++) {
        float x3 = src[(size_t)t * D_IN_PROJ];
        float a = bias + w0 * x0 + w1 * x1 + w2 * x2 + w3 * x3;
        dst[(size_t)t * CONV_DIM] = siluf(a);
        x0 = x1; x1 = x2; x2 = x3;
    }
}

// ---------------- dt softplus + per-chunk cumsum of dA ----------------
__global__ void dt_scan_kernel(const float* __restrict__ dt_bias,
                               const float* __restrict__ A_log)
{
    int idx = blockIdx.x;
    int c = idx % NCHUNK; idx /= NCHUNK;
    int h = idx % NHEADS;
    int b = idx / NHEADS;
    int l = threadIdx.x;
    int t = c * CHUNKL + l;
    float raw = g_zx[(size_t)(b * SEQL + t) * D_IN_PROJ + DINNER + CONV_DIM + h];
    float xv = raw + dt_bias[h];
    float dt = (xv > 20.f) ? xv : log1pf(expf(xv));
    g_dt[(b * SEQL + t) * NHEADS + h] = dt;
    float dA = dt * (-expf(A_log[h]));
    __shared__ float s[CHUNKL];
    s[l] = dA;
    __syncthreads();
    for (int off = 1; off < CHUNKL; off <<= 1) {
        float v = (l >= off) ? s[l - off] : 0.f;
        __syncthreads();
        s[l] += v;
        __syncthreads();
    }
    g_Acs[((b * NHEADS + h) * NCHUNK + c) * CHUNKL + l] = s[l];
}

// ---------------- split converts for SSM operands ----------------
// B, C natural layout: [b*SEQL + t][128]
__global__ void cvt_cb_kernel()
{
    int idx = blockIdx.x * 256 + threadIdx.x;          // over B_SZ*SEQL*64
    int bt = idx >> 6, j2 = (idx & 63) << 1;
    const float* src = g_xBC + (size_t)bt * CONV_DIM + DINNER;
    size_t o = (size_t)bt * DSTATE + j2;
    split_store2(g_Bh, g_Bl, o, src[j2], src[j2 + 1]);
    split_store2(g_Ch, g_Cl, o, src[DSTATE + j2], src[DSTATE + j2 + 1]);
}

// B^T: [b][n][t]
__global__ void cvt_bt_kernel()
{
    __shared__ float tile[32][33];
    int b = blockIdx.z, n0 = blockIdx.y * 32, t0 = blockIdx.x * 32;
    int tid = threadIdx.x;
#pragma unroll
    for (int it = 0; it < 4; it++) {
        int v = tid + it * 256;
        int t = v >> 5, n = v & 31;
        tile[t][n] = g_xBC[(size_t)(b * SEQL + t0 + t) * CONV_DIM + DINNER + n0 + n];
    }
    __syncthreads();
#pragma unroll
    for (int it = 0; it < 2; it++) {
        int v = tid + it * 256;
        int n = v >> 4, tc = (v & 15) << 1;
        size_t o = (size_t)(b * DSTATE + n0 + n) * SEQL + t0 + tc;
        split_store2(g_BTh, g_BTl, o, tile[tc][n], tile[tc + 1][n]);
    }
}

// XdT = (x_ssm * dt)^T, XdecT = (x_ssm * dt * dec)^T : [b][h][p][t]
__global__ void cvt_xdt_kernel()
{
    __shared__ float xs[64][65];
    __shared__ float dts[64], dec[64];
    int b = blockIdx.z, h = blockIdx.y, tt = blockIdx.x;
    int t0 = tt * 64, tid = threadIdx.x;
    int c = t0 >> 8;
    const float* acs = g_Acs + ((b * NHEADS + h) * NCHUNK + c) * CHUNKL;
    if (tid < 64) {
        int tl = (t0 & 255) + tid;
        dts[tid] = g_dt[(size_t)(b * SEQL + t0 + tid) * NHEADS + h];
        dec[tid] = expf(acs[CHUNKL - 1] - acs[tl]);
    }
#pragma unroll
    for (int it = 0; it < 16; it++) {
        int v = tid + it * 256;
        int t = v >> 6, p = v & 63;
        xs[t][p] = g_xBC[(size_t)(b * SEQL + t0 + t) * CONV_DIM + h * HEADDIM + p];
    }
    __syncthreads();
#pragma unroll
    for (int it = 0; it < 8; it++) {
        int v = tid + it * 256;
        int p = v >> 5, tc = (v & 31) << 1;
        size_t o = ((size_t)((b * NHEADS + h) * HEADDIM) + p) * SEQL + t0 + tc;
        float x0 = xs[tc][p] * dts[tc];
        float x1 = xs[tc + 1][p] * dts[tc + 1];
        split_store2(g_XdTh, g_XdTl, o, x0, x1);
        split_store2(g_XdecTh, g_XdecTl, o, x0 * dec[tc], x1 * dec[tc + 1]);
    }
}

// ---------------- states via split HMMA: states[p][n] = sum_l Xdec^T[p][l]*B^T[n][l] ----------------
#define S_AH_O 0
#define S_AL_O 2304
#define S_BH_O 4608
#define S_BL_O 9216
#define S_STG  13824
#define S_SMEM_BYTES (2 * S_STG * 4)

__global__ __launch_bounds__(256, 2) void states_hmma()
{
    extern __shared__ uint32_t sw[];
    const uint32_t sb = smem_u32(sw);
    int bid = blockIdx.x;
    int h = bid & 63, cc = (bid >> 6) & 7, b = bid >> 9;
    int tid = threadIdx.x, wid = tid >> 5, lane = tid & 31;
    int warp_m = wid >> 2, warp_n = wid & 3;
    const __half* Ah = g_XdecTh + (size_t)((b * NHEADS + h) * HEADDIM) * SEQL + cc * CHUNKL;
    const __half* Al = g_XdecTl + (size_t)((b * NHEADS + h) * HEADDIM) * SEQL + cc * CHUNKL;
    const __half* Bh = g_BTh + (size_t)(b * DSTATE) * SEQL + cc * CHUNKL;
    const __half* Bl = g_BTl + (size_t)(b * DSTATE) * SEQL + cc * CHUNKL;

    float acc[2][4][4];
#pragma unroll
    for (int i = 0; i < 2; i++)
#pragma unroll
        for (int j = 0; j < 4; j++)
#pragma unroll
            for (int q = 0; q < 4; q++) acc[i][j][q] = 0.f;

    // stage loader
    auto load_stage = [&](int kc, int buf) {
        uint32_t base = (uint32_t)buf * S_STG;
        int koff = kc * 64;
#pragma unroll
        for (int it = 0; it < 2; it++) {
            int v = tid + (it << 8);
            int r = v >> 3, ch = v & 7;
            cp16(sb + (base + S_AH_O + r * 36 + ch * 4) * 4, Ah + (size_t)r * SEQL + koff + ch * 8);
            cp16(sb + (base + S_AL_O + r * 36 + ch * 4) * 4, Al + (size_t)r * SEQL + koff + ch * 8);
        }
#pragma unroll
        for (int it = 0; it < 4; it++) {
            int v = tid + (it << 8);
            int r = v >> 3, ch = v & 7;
            cp16(sb + (base + S_BH_O + r * 36 + ch * 4) * 4, Bh + (size_t)r * SEQL + koff + ch * 8);
            cp16(sb + (base + S_BL_O + r * 36 + ch * 4) * 4, Bl + (size_t)r * SEQL + koff + ch * 8);
        }
        asm volatile("cp.async.commit_group;" ::: "memory");
    };

    load_stage(0, 0);
    load_stage(1, 1);

    const int arow = warp_m * 32 + ((lane >> 3) & 1) * 8 + (lane & 7);
    const int akw = (lane >> 4) << 2;
    const int brl = ((lane >> 4) & 1) * 8 + (lane & 7);
    const int bkw = ((lane >> 3) & 1) << 2;

    for (int kc = 0; kc < 4; kc++) {
        if (kc < 3) asm volatile("cp.async.wait_group 1;" ::: "memory");
        else        asm volatile("cp.async.wait_group 0;" ::: "memory");
        __syncthreads();
        uint32_t base = (uint32_t)(kc & 1) * S_STG;
#pragma unroll
        for (int kk = 0; kk < 4; kk++) {
            uint32_t ah[2][4], al[2][4];
#pragma unroll
            for (int mi = 0; mi < 2; mi++) {
                uint32_t w = base + S_AH_O + (arow + mi * 16) * 36 + kk * 8 + akw;
                ldsm4(ah[mi], sb + w * 4);
                ldsm4(al[mi], sb + (w + (S_AL_O - S_AH_O)) * 4);
            }
#pragma unroll
            for (int np = 0; np < 2; np++) {
                uint32_t bfh[4], bfl[4];
                int rb = warp_n * 32 + np * 16 + brl;
                uint32_t w = base + S_BH_O + rb * 36 + kk * 8 + bkw;
                ldsm4(bfh, sb + w * 4);
                ldsm4(bfl, sb + (w + (S_BL_O - S_BH_O)) * 4);
#pragma unroll
                for (int mi = 0; mi < 2; mi++) {
                    mma_fp16(acc[mi][2 * np], ah[mi], bfh);
                    mma_fp16(acc[mi][2 * np], ah[mi], bfl);
                    mma_fp16(acc[mi][2 * np], al[mi], bfh);
                    mma_fp16(acc[mi][2 * np + 1], ah[mi], bfh + 2);
                    mma_fp16(acc[mi][2 * np + 1], ah[mi], bfl + 2);
                    mma_fp16(acc[mi][2 * np + 1], al[mi], bfh + 2);
                }
            }
        }
        __syncthreads();
        if (kc + 2 < 4) load_stage(kc + 2, kc & 1);
    }

    float* out = g_states + (size_t)((b * NCHUNK + cc) * NHEADS + h) * HEADDIM * DSTATE;
#pragma unroll
    for (int mi = 0; mi < 2; mi++) {
        int r0 = warp_m * 32 + mi * 16 + (lane >> 2);
#pragma unroll
        for (int ni = 0; ni < 4; ni++) {
            int col = warp_n * 32 + ni * 8 + 2 * (lane & 3);
            *(float2*)(out + (size_t)r0 * DSTATE + col) = make_float2(acc[mi][ni][0], acc[mi][ni][1]);
            *(float2*)(out + (size_t)(r0 + 8) * DSTATE + col) = make_float2(acc[mi][ni][2], acc[mi][ni][3]);
        }
    }
}

// ---------------- inter-chunk recurrence (fp32 states -> fp16 prev hi/lo) ----------------
__global__ __launch_bounds__(256) void prev_kernel()
{
    int b = blockIdx.x >> 6;
    int h = blockIdx.x & 63;
    int tid = threadIdx.x;
    float P[32];
#pragma unroll
    for (int i = 0; i < 32; i++) P[i] = 0.f;
    for (int c = 0; c < NCHUNK; c++) {
        float decay = expf(g_Acs[((b * NHEADS + h) * NCHUNK + c) * CHUNKL + CHUNKL - 1]);
        size_t base = (size_t)((b * NCHUNK + c) * NHEADS + h) * HEADDIM * DSTATE;
#pragma unroll
        for (int i = 0; i < 32; i++) {
            int e = i * 256 + tid;
            float v = P[i];
            __half hh = __float2half_rn(v);
            g_prevh[base + e] = hh;
            g_prevl[base + e] = __float2half_rn(v - __half2float(hh));
            P[i] = v * decay + g_states[base + e];
        }
    }
}

// ---------------- Y via split HMMA ----------------
#define Y_ACS_O 0
#define Y_CH_O 256
#define Y_CL_O (Y_CH_O + 4352)
#define Y_PBH_O (Y_CL_O + 4352)
#define Y_PBL_O (Y_PBH_O + 4352)
#define Y_XDH_O (Y_PBL_O + 4352)
#define Y_XDL_O (Y_XDH_O + 2304)
#define Y_SH_O  (Y_XDL_O + 2304)
#define Y_SL_O  (Y_SH_O + 2304)
#define Y_SMEM_BYTES ((Y_SL_O + 2304) * 4)

__global__ __launch_bounds__(256, 2) void y_hmma(const float* __restrict__ Dp)
{
    extern __shared__ uint32_t sw[];
    const uint32_t sb = smem_u32(sw);
    float* acs_s = (float*)(sw + Y_ACS_O);
    int bid = blockIdx.x;
    int lt = bid & 3, h = (bid >> 2) & 63, c = (bid >> 8) & 7, b = bid >> 11;
    int tid = threadIdx.x, wid = tid >> 5, lane = tid & 31;
    int warp_m = wid >> 2, warp_n = wid & 3;
    int l0 = lt * 64;
    const int bt0 = b * SEQL + c * CHUNKL;

    acs_s[tid] = g_Acs[((b * NHEADS + h) * NCHUNK + c) * CHUNKL + tid];

    // prologue: C hi/lo (rows l0..l0+63), prev hi/lo
    {
        const __half* sCh = g_Ch + (size_t)(bt0 + l0) * DSTATE;
        const __half* sCl = g_Cl + (size_t)(bt0 + l0) * DSTATE;
        size_t pb = (size_t)((b * NCHUNK + c) * NHEADS + h) * HEADDIM * DSTATE;
        const __half* sPh = g_prevh + pb;
        const __half* sPl = g_prevl + pb;
#pragma unroll
        for (int it = 0; it < 4; it++) {
            int v = tid + (it << 8);
            int r = v >> 4, ch = v & 15;
            cp16(sb + (Y_CH_O + r * 68 + ch * 4) * 4, sCh + (size_t)r * DSTATE + ch * 8);
            cp16(sb + (Y_CL_O + r * 68 + ch * 4) * 4, sCl + (size_t)r * DSTATE + ch * 8);
            cp16(sb + (Y_PBH_O + r * 68 + ch * 4) * 4, sPh + (size_t)r * DSTATE + ch * 8);
            cp16(sb + (Y_PBL_O + r * 68 + ch * 4) * 4, sPl + (size_t)r * DSTATE + ch * 8);
        }
        asm volatile("cp.async.commit_group;" ::: "memory");
        asm volatile("cp.async.wait_group 0;" ::: "memory");
    }
    __syncthreads();

    float Yacc[2][2][4];
#pragma unroll
    for (int i = 0; i < 2; i++)
#pragma unroll
        for (int j = 0; j < 2; j++)
#pragma unroll
            for (int q = 0; q < 4; q++) Yacc[i][j][q] = 0.f;

    const int arow = warp_m * 32 + ((lane >> 3) & 1) * 8 + (lane & 7);
    const int akw  = (lane >> 4) << 2;
    const int brow = warp_n * 16 + ((lane >> 4) & 1) * 8 + (lane & 7);
    const int bkw  = ((lane >> 3) & 1) << 2;

    // Y_off = C * prev^T  (K = 128)
#pragma unroll
    for (int kk = 0; kk < 8; kk++) {
        uint32_t ah[2][4], al[2][4], bh[4], bl[4];
#pragma unroll
        for (int mi = 0; mi < 2; mi++) {
            uint32_t w = Y_CH_O + (arow + mi * 16) * 68 + kk * 8 + akw;
            ldsm4(ah[mi], sb + w * 4);
            ldsm4(al[mi], sb + (w + (Y_CL_O - Y_CH_O)) * 4);
        }
        {
            uint32_t w = Y_PBH_O + brow * 68 + kk * 8 + bkw;
            ldsm4(bh, sb + w * 4);
            ldsm4(bl, sb + (w + (Y_PBL_O - Y_PBH_O)) * 4);
        }
#pragma unroll
        for (int mi = 0; mi < 2; mi++) {
            mma_fp16(Yacc[mi][0], ah[mi], bh);
            mma_fp16(Yacc[mi][0], ah[mi], bl);
            mma_fp16(Yacc[mi][0], al[mi], bh);
            mma_fp16(Yacc[mi][1], ah[mi], bh + 2);
            mma_fp16(Yacc[mi][1], ah[mi], bl + 2);
            mma_fp16(Yacc[mi][1], al[mi], bh + 2);
        }
    }
    // scale Y_off rows by exp(acs[l])
#pragma unroll
    for (int mi = 0; mi < 2; mi++) {
        int r0 = l0 + warp_m * 32 + mi * 16 + (lane >> 2);
        float e0 = expf(acs_s[r0]);
        float e1 = expf(acs_s[r0 + 8]);
#pragma unroll
        for (int ni = 0; ni < 2; ni++) {
            Yacc[mi][ni][0] *= e0; Yacc[mi][ni][1] *= e0;
            Yacc[mi][ni][2] *= e1; Yacc[mi][ni][3] *= e1;
        }
    }

    for (int st = 0; st <= lt; st++) {
        int s0 = st * 64;
        __syncthreads();   // prior reads of PB/XD/S16 complete
        {
            const __half* sBh = g_Bh + (size_t)(bt0 + s0) * DSTATE;
            const __half* sBl = g_Bl + (size_t)(bt0 + s0) * DSTATE;
            const __half* sXh = g_XdTh + (size_t)((b * NHEADS + h) * HEADDIM) * SEQL + c * CHUNKL + s0;
            const __half* sXl = g_XdTl + (size_t)((b * NHEADS + h) * HEADDIM) * SEQL + c * CHUNKL + s0;
#pragma unroll
            for (int it = 0; it < 4; it++) {
                int v = tid + (it << 8);
                int r = v >> 4, ch = v & 15;
                cp16(sb + (Y_PBH_O + r * 68 + ch * 4) * 4, sBh + (size_t)r * DSTATE + ch * 8);
                cp16(sb + (Y_PBL_O + r * 68 + ch * 4) * 4, sBl + (size_t)r * DSTATE + ch * 8);
            }
#pragma unroll
            for (int it = 0; it < 2; it++) {
                int v = tid + (it << 8);
                int r = v >> 3, ch = v & 7;
                cp16(sb + (Y_XDH_O + r * 36 + ch * 4) * 4, sXh + (size_t)r * SEQL + ch * 8);
                cp16(sb + (Y_XDL_O + r * 36 + ch * 4) * 4, sXl + (size_t)r * SEQL + ch * 8);
            }
            asm volatile("cp.async.commit_group;" ::: "memory");
            asm volatile("cp.async.wait_group 0;" ::: "memory");
        }
        __syncthreads();

        // S = C * B^T (K=128)
        float sacc[2][2][4];
#pragma unroll
        for (int i = 0; i < 2; i++)
#pragma unroll
            for (int j = 0; j < 2; j++)
#pragma unroll
                for (int q = 0; q < 4; q++) sacc[i][j][q] = 0.f;
#pragma unroll
        for (int kk = 0; kk < 8; kk++) {
            uint32_t ah[2][4], al[2][4], bh[4], bl[4];
#pragma unroll
            for (int mi = 0; mi < 2; mi++) {
                uint32_t w = Y_CH_O + (arow + mi * 16) * 68 + kk * 8 + akw;
                ldsm4(ah[mi], sb + w * 4);
                ldsm4(al[mi], sb + (w + (Y_CL_O - Y_CH_O)) * 4);
            }
            {
                uint32_t w = Y_PBH_O + brow * 68 + kk * 8 + bkw;
                ldsm4(bh, sb + w * 4);
                ldsm4(bl, sb + (w + (Y_PBL_O - Y_PBH_O)) * 4);
            }
#pragma unroll
            for (int mi = 0; mi < 2; mi++) {
                mma_fp16(sacc[mi][0], ah[mi], bh);
                mma_fp16(sacc[mi][0], ah[mi], bl);
                mma_fp16(sacc[mi][0], al[mi], bh);
                mma_fp16(sacc[mi][1], ah[mi], bh + 2);
                mma_fp16(sacc[mi][1], ah[mi], bl + 2);
                mma_fp16(sacc[mi][1], al[mi], bh + 2);
            }
        }
        // mask + decay + hi/lo split -> S16 smem
#pragma unroll
        for (int mi = 0; mi < 2; mi++) {
            int rr0 = warp_m * 32 + mi * 16 + (lane >> 2);
            int lg0 = l0 + rr0, lg1 = lg0 + 8;
            float a0 = acs_s[lg0], a1 = acs_s[lg1];
#pragma unroll
            for (int ni = 0; ni < 2; ni++) {
                int ccc = warp_n * 16 + ni * 8 + 2 * (lane & 3);
                int sg = s0 + ccc;
                float as0 = acs_s[sg], as1 = acs_s[sg + 1];
                float v00 = (sg     <= lg0) ? sacc[mi][ni][0] * expf(a0 - as0) : 0.f;
                float v01 = (sg + 1 <= lg0) ? sacc[mi][ni][1] * expf(a0 - as1) : 0.f;
                float v10 = (sg     <= lg1) ? sacc[mi][ni][2] * expf(a1 - as0) : 0.f;
                float v11 = (sg + 1 <= lg1) ? sacc[mi][ni][3] * expf(a1 - as1) : 0.f;
                __half h00 = __float2half_rn(v00), h01 = __float2half_rn(v01);
                __half h10 = __float2half_rn(v10), h11 = __float2half_rn(v11);
                sw[Y_SH_O + rr0 * 36 + (ccc >> 1)] = packh2(h00, h01);
                sw[Y_SH_O + (rr0 + 8) * 36 + (ccc >> 1)] = packh2(h10, h11);
                sw[Y_SL_O + rr0 * 36 + (ccc >> 1)] =
                    packh2(__float2half_rn(v00 - __half2float(h00)), __float2half_rn(v01 - __half2float(h01)));
                sw[Y_SL_O + (rr0 + 8) * 36 + (ccc >> 1)] =
                    packh2(__float2half_rn(v10 - __half2float(h10)), __float2half_rn(v11 - __half2float(h11)));
            }
        }
        __syncthreads();
        // Y += S * Xd^T  (K = 64)
#pragma unroll
        for (int kk = 0; kk < 4; kk++) {
            uint32_t ah[2][4], al[2][4], bh[4], bl[4];
#pragma unroll
            for (int mi = 0; mi < 2; mi++) {
                uint32_t w = Y_SH_O + (arow + mi * 16) * 36 + kk * 8 + akw;
                ldsm4(ah[mi], sb + w * 4);
                ldsm4(al[mi], sb + (w + (Y_SL_O - Y_SH_O)) * 4);
            }
            {
                uint32_t w = Y_XDH_O + brow * 36 + kk * 8 + bkw;
                ldsm4(bh, sb + w * 4);
                ldsm4(bl, sb + (w + (Y_XDL_O - Y_XDH_O)) * 4);
            }
#pragma unroll
            for (int mi = 0; mi < 2; mi++) {
                mma_fp16(Yacc[mi][0], ah[mi], bh);
                mma_fp16(Yacc[mi][0], ah[mi], bl);
                mma_fp16(Yacc[mi][0], al[mi], bh);
                mma_fp16(Yacc[mi][1], ah[mi], bh + 2);
                mma_fp16(Yacc[mi][1], ah[mi], bl + 2);
                mma_fp16(Yacc[mi][1], al[mi], bh + 2);
            }
        }
    }

    // epilogue: + D*x_ssm, gate with silu(z)
    float Dh = Dp[h];
#pragma unroll
    for (int mi = 0; mi < 2; mi++) {
#pragma unroll
        for (int q = 0; q < 2; q++) {
            int rr = warp_m * 32 + mi * 16 + (lane >> 2) + q * 8;
            int t = bt0 + l0 + rr;
#pragma unroll
            for (int ni = 0; ni < 2; ni++) {
                int pp = warp_n * 16 + ni * 8 + 2 * (lane & 3);
                float2 xs = *(const float2*)(g_xBC + (size_t)t * CONV_DIM + h * HEADDIM + pp);
                float2 zz = *(const float2*)(g_zx + (size_t)t * D_IN_PROJ + h * HEADDIM + pp);
                float y0 = Yacc[mi][ni][q * 2 + 0] + xs.x * Dh;
                float y1 = Yacc[mi][ni][q * 2 + 1] + xs.y * Dh;
                float2 o = make_float2(y0 * siluf(zz.x), y1 * siluf(zz.y));
                *(float2*)(g_yg + (size_t)t * DINNER + h * HEADDIM + pp) = o;
            }
        }
    }
}

// ---------------- RMSNorm -> fp16 ----------------
__global__ __launch_bounds__(256) void rmsnorm_kernel(const float* __restrict__ w)
{
    int row = blockIdx.x;
    const float* y = g_yg + (size_t)row * DINNER;
    __half* oh = g_ynh + (size_t)row * DINNER;
    int tid = threadIdx.x;
    float ss = 0.f;
#pragma unroll
    for (int it = 0; it < 4; it++) {
        float4 v = *(const float4*)(y + it * 1024 + tid * 4);
        ss += v.x * v.x + v.y * v.y + v.z * v.z + v.w * v.w;
    }
#pragma unroll
    for (int off = 16; off; off >>= 1) ss += __shfl_xor_sync(0xFFFFFFFFu, ss, off);
    __shared__ float red[8];
    if ((tid & 31) == 0) red[tid >> 5] = ss;
    __syncthreads();
    float tot = 0.f;
#pragma unroll
    for (int i = 0; i < 8; i++) tot += red[i];
    float scale = rsqrtf(tot / (float)DINNER + EPSV);
#pragma unroll
    for (int it = 0; it < 4; it++) {
        int i = it * 1024 + tid * 4;
        float4 v = *(const float4*)(y + i);
        float4 wv = *(const float4*)(w + i);
        __half2* hp = (__half2*)(oh + i);
        hp[0] = __floats2half2_rn(v.x * scale * wv.x, v.y * scale * wv.y);
        hp[1] = __floats2half2_rn(v.z * scale * wv.z, v.w * scale * wv.w);
    }
}

// ---------------- launch ----------------
extern "C" void kernel_launch(void* const* d_in, const int* in_sizes, int n_in,
                              void* d_out, int out_size)
{
    const float* x          = (const float*)d_in[0];
    const float* in_proj_w  = (const float*)d_in[1];
    const float* conv_w     = (const float*)d_in[2];
    const float* conv_b     = (const float*)d_in[3];
    const float* dt_bias    = (const float*)d_in[4];
    const float* A_log      = (const float*)d_in[5];
    const float* Dp         = (const float*)d_in[6];
    const float* norm_w     = (const float*)d_in[7];
    const float* out_proj_w = (const float*)d_in[8];
    float* out = (float*)d_out;

    float *zx_p = nullptr;
    __half *xh_p, *wih_p, *ynh_p, *owh_p;
    cudaGetSymbolAddress((void**)&zx_p, g_zx);
    cudaGetSymbolAddress((void**)&xh_p, g_xh);
    cudaGetSymbolAddress((void**)&wih_p, g_wih);
    cudaGetSymbolAddress((void**)&ynh_p, g_ynh);
    cudaGetSymbolAddress((void**)&owh_p, g_owh);

    static bool attr_set = false;
    if (!attr_set) {
        cudaFuncSetAttribute(gemm_hmma_fp16, cudaFuncAttributeMaxDynamicSharedMemorySize, GEMM1_SMEM);
        cudaFuncSetAttribute(states_hmma, cudaFuncAttributeMaxDynamicSharedMemorySize, S_SMEM_BYTES);
        cudaFuncSetAttribute(y_hmma, cudaFuncAttributeMaxDynamicSharedMemorySize, Y_SMEM_BYTES);
        attr_set = true;
    }

    const int M = B_SZ * SEQL; // 4096

    // converts (projections)
    {
        long n = (long)M * DMODEL;
        cvt_half<<<(unsigned)((n / 4 + 255) / 256), 256>>>(x, xh_p, n, n);
    }
    {
        long ns = (long)D_IN_PROJ * DMODEL, nt = (long)DIP_PAD * DMODEL;
        cvt_half<<<(unsigned)((nt / 4 + 255) / 256), 256>>>(in_proj_w, wih_p, ns, nt);
    }
    {
        long n = (long)DMODEL * DINNER;
        cvt_half<<<(unsigned)((n / 4 + 255) / 256), 256>>>(out_proj_w, owh_p, n, n);
    }

    // 1) in_proj GEMM
    gemm_hmma_fp16<<<dim3(DIP_PAD / 128, M / 128), 256, GEMM1_SMEM>>>(
        xh_p, wih_p, zx_p, M, D_IN_PROJ, DMODEL);

    // 2) conv + silu
    conv_silu_kernel<<<dim3(CONV_DIM / 128, B_SZ, SEQL / 256), 128>>>(conv_w, conv_b);

    // 3) dt softplus + cumsum
    dt_scan_kernel<<<B_SZ * NHEADS * NCHUNK, CHUNKL>>>(dt_bias, A_log);

    // 4) SSM operand converts
    cvt_cb_kernel<<<(B_SZ * SEQL * 64) / 256, 256>>>();
    cvt_bt_kernel<<<dim3(SEQL / 32, DSTATE / 32, B_SZ), 256>>>();
    cvt_xdt_kernel<<<dim3(SEQL / 64, NHEADS, B_SZ), 256>>>();

    // 5) states (split HMMA)
    states_hmma<<<B_SZ * NCHUNK * NHEADS, 256, S_SMEM_BYTES>>>();

    // 6) recurrence -> prev fp16 hi/lo
    prev_kernel<<<B_SZ * NHEADS, 256>>>();

    // 7) Y (split HMMA) + gate
    y_hmma<<<B_SZ * NCHUNK * NHEADS * 4, 256, Y_SMEM_BYTES>>>(Dp);

    // 8) RMSNorm -> fp16
    rmsnorm_kernel<<<B_SZ * SEQL, 256>>>(norm_w);

    // 9) out_proj GEMM
    gemm_hmma_fp16<<<dim3(DMODEL / 128, M / 128), 256, GEMM1_SMEM>>>(
        ynh_p, owh_p, out, M, DMODEL, DINNER);

    (void)in_sizes; (void)n_in; (void)out_size;
}

// round 9
// speedup vs baseline: 5.9813x; 1.1785x over previous
#include <cuda_runtime.h>
#include <cuda_bf16.h>
#include <cuda_fp16.h>
#include <cstdint>
#include <cstring>

#define B_SZ 2
#define SEQL 2048
#define DMODEL 2048
#define DINNER 4096
#define DSTATE 128
#define HEADDIM 64
#define NHEADS 64
#define CHUNKL 256
#define NCHUNK 8
#define CONV_DIM 4352     // DINNER + 2*DSTATE
#define D_IN_PROJ 8512    // 2*DINNER + 2*DSTATE + NHEADS
#define DIP_PAD 8576      // 67*128
#define EPSV 1e-5f

// ---------------- scratch ----------------
__device__ float g_zx[B_SZ*SEQL*D_IN_PROJ];
__device__ float g_xBC[B_SZ*SEQL*CONV_DIM];
__device__ float g_dt[B_SZ*SEQL*NHEADS];
__device__ float g_Acs[B_SZ*NHEADS*NCHUNK*CHUNKL];
__device__ float g_states[(size_t)B_SZ*NCHUNK*NHEADS*HEADDIM*DSTATE];
__device__ float g_yg[B_SZ*SEQL*DINNER];
// fp16 gemm operands
__device__ __half g_xh[B_SZ*SEQL*DMODEL];
__device__ __half g_wih[(size_t)DIP_PAD*DMODEL];
__device__ __half g_ynh[B_SZ*SEQL*DINNER];
__device__ __half g_owh[(size_t)DMODEL*DINNER];
// SSM operands
__device__ __half g_Bh[B_SZ*SEQL*DSTATE],  g_Bl[B_SZ*SEQL*DSTATE];     // split (Y path)
__device__ __half g_Ch[B_SZ*SEQL*DSTATE],  g_Cl[B_SZ*SEQL*DSTATE];     // split (Y path)
__device__ __half g_BT[B_SZ*DSTATE*SEQL];                               // single (states)
__device__ __half g_XdT[(size_t)B_SZ*NHEADS*HEADDIM*SEQL];              // single (Y SXd)
__device__ __half g_XdecT[(size_t)B_SZ*NHEADS*HEADDIM*SEQL];            // single (states)
__device__ __half g_prevh[(size_t)B_SZ*NCHUNK*NHEADS*HEADDIM*DSTATE];   // split (Y_off)
__device__ __half g_prevl[(size_t)B_SZ*NCHUNK*NHEADS*HEADDIM*DSTATE];

__device__ __forceinline__ float siluf(float a) { return a / (1.f + expf(-a)); }

// ================= common HMMA helpers =================
__device__ __forceinline__ void mma_fp16(float* c, const uint32_t* a, const uint32_t* b) {
    asm volatile(
        "mma.sync.aligned.m16n8k16.row.col.f32.f16.f16.f32 "
        "{%0,%1,%2,%3}, {%4,%5,%6,%7}, {%8,%9}, {%0,%1,%2,%3};"
        : "+f"(c[0]), "+f"(c[1]), "+f"(c[2]), "+f"(c[3])
        : "r"(a[0]), "r"(a[1]), "r"(a[2]), "r"(a[3]), "r"(b[0]), "r"(b[1]));
}
__device__ __forceinline__ void ldsm4(uint32_t* r, uint32_t addr) {
    asm volatile("ldmatrix.sync.aligned.m8n8.x4.shared.b16 {%0,%1,%2,%3}, [%4];"
        : "=r"(r[0]), "=r"(r[1]), "=r"(r[2]), "=r"(r[3]) : "r"(addr));
}
__device__ __forceinline__ void cp16(uint32_t dst, const void* src) {
    asm volatile("cp.async.cg.shared.global [%0], [%1], 16;" :: "r"(dst), "l"(src));
}
__device__ __forceinline__ uint32_t smem_u32(const void* p) {
    uint32_t a;
    asm("{ .reg .u64 t; cvta.to.shared.u64 t, %1; cvt.u32.u64 %0, t; }" : "=r"(a) : "l"(p));
    return a;
}
__device__ __forceinline__ uint32_t packh2(__half a, __half b) {
    __half2 h = __halves2half2(a, b);
    uint32_t u; memcpy(&u, &h, 4); return u;
}
__device__ __forceinline__ void split_store2(__half* hi, __half* lo, size_t o, float a, float b) {
    __half ha = __float2half_rn(a), hb = __float2half_rn(b);
    *(__half2*)(hi + o) = __halves2half2(ha, hb);
    *(__half2*)(lo + o) = __halves2half2(__float2half_rn(a - __half2float(ha)),
                                         __float2half_rn(b - __half2float(hb)));
}

// ================= fp16 HMMA GEMM, BK=64, 3 stages =================
#define OPW64 4096                        // words per 128x64 operand tile
#define STG64 (2 * OPW64)                 // A+B stage, 32 KB
#define GEMM1_SMEM (3 * STG64 * 4)        // 98304 B

// 128 rows x 64 halfs, row = 32 words, swizzle: chunk ^= (r&7)
__device__ __forceinline__ void load_op64(uint32_t sbase_b, const __half* g, int ldk, int tid) {
#pragma unroll
    for (int it = 0; it < 4; it++) {
        int v = tid + (it << 8);
        int r = v >> 3, ch = v & 7;
        int sch = ch ^ (r & 7);
        cp16(sbase_b + (r * 32 + (sch << 2)) * 4, g + (size_t)r * ldk + (ch << 3));
    }
}

__global__ __launch_bounds__(256, 2) void gemm_hmma_fp16(
    const __half* __restrict__ A, const __half* __restrict__ B,
    float* __restrict__ C, int M, int Nreal, int K)
{
    extern __shared__ uint32_t sw[];
    const uint32_t sb = smem_u32(sw);
    const int tid = threadIdx.x, wid = tid >> 5, lane = tid & 31;
    const int warp_m = wid & 1, warp_n = wid >> 1;
    const int m0 = blockIdx.y << 7, n0 = blockIdx.x << 7;
    const int KT = K >> 6;

    const __half* Ab = A + (size_t)m0 * K;
    const __half* Bb = B + (size_t)n0 * K;

    float acc[4][4][4];
#pragma unroll
    for (int i = 0; i < 4; i++)
#pragma unroll
        for (int j = 0; j < 4; j++)
#pragma unroll
            for (int q = 0; q < 4; q++) acc[i][j][q] = 0.f;

    // prologue: stages 0,1
#pragma unroll
    for (int s = 0; s < 2; s++) {
        int koff = s << 6;
        load_op64(sb + (s * STG64) * 4, Ab + koff, K, tid);
        load_op64(sb + (s * STG64 + OPW64) * 4, Bb + koff, K, tid);
        asm volatile("cp.async.commit_group;" ::: "memory");
    }

    const int rowA = warp_m * 64 + ((lane >> 3) & 1) * 8 + (lane & 7);
    const int cA0  = lane >> 4;
    const int rowB = warp_n * 32 + ((lane >> 4) & 1) * 8 + (lane & 7);
    const int cB0  = (lane >> 3) & 1;

    int buf = 0;
    for (int kt = 0; kt < KT; kt++) {
        if (kt + 1 < KT) asm volatile("cp.async.wait_group 1;" ::: "memory");
        else             asm volatile("cp.async.wait_group 0;" ::: "memory");
        __syncthreads();
        if (kt + 2 < KT) {
            int s = buf + 2; if (s >= 3) s -= 3;
            int koff = (kt + 2) << 6;
            load_op64(sb + (s * STG64) * 4, Ab + koff, K, tid);
            load_op64(sb + (s * STG64 + OPW64) * 4, Bb + koff, K, tid);
            asm volatile("cp.async.commit_group;" ::: "memory");
        }

        const uint32_t sA = sb + (uint32_t)buf * STG64 * 4u;
        const uint32_t sB = sA + OPW64 * 4u;

#pragma unroll
        for (int kk = 0; kk < 4; kk++) {
            uint32_t a[4][4];
#pragma unroll
            for (int mi = 0; mi < 4; mi++) {
                int r = rowA + mi * 16;
                uint32_t off = (r * 32 + ((((kk << 1) + cA0) ^ (r & 7)) << 2)) * 4u;
                ldsm4(a[mi], sA + off);
            }
#pragma unroll
            for (int np = 0; np < 2; np++) {
                int r = rowB + np * 16;
                uint32_t boff = (r * 32 + ((((kk << 1) + cB0) ^ (r & 7)) << 2)) * 4u;
                uint32_t b[4];
                ldsm4(b, sB + boff);
#pragma unroll
                for (int mi = 0; mi < 4; mi++) {
                    mma_fp16(acc[mi][2 * np], a[mi], b);
                    mma_fp16(acc[mi][2 * np + 1], a[mi], b + 2);
                }
            }
        }
        __syncthreads();
        buf++; if (buf == 3) buf = 0;
    }

#pragma unroll
    for (int mi = 0; mi < 4; mi++) {
        int rg0 = m0 + warp_m * 64 + mi * 16 + (lane >> 2);
#pragma unroll
        for (int ni = 0; ni < 4; ni++) {
            int cg = n0 + warp_n * 32 + ni * 8 + ((lane & 3) << 1);
            if (cg < Nreal) {
                *(float2*)(C + (size_t)rg0 * Nreal + cg) =
                    make_float2(acc[mi][ni][0], acc[mi][ni][1]);
                *(float2*)(C + (size_t)(rg0 + 8) * Nreal + cg) =
                    make_float2(acc[mi][ni][2], acc[mi][ni][3]);
            }
        }
    }
}

// ---------------- fp32 -> fp16 (with zero-pad tail) ----------------
__global__ void cvt_half(const float* __restrict__ src, __half* __restrict__ dst,
                         long n_src, long n_tot)
{
    long i = ((long)blockIdx.x * 256 + threadIdx.x) * 4;
    if (i >= n_tot) return;
    float4 v = (i < n_src) ? *(const float4*)(src + i) : make_float4(0.f, 0.f, 0.f, 0.f);
    __half2* dp = (__half2*)(dst + i);
    dp[0] = __floats2half2_rn(v.x, v.y);
    dp[1] = __floats2half2_rn(v.z, v.w);
}

// ---------------- causal depthwise conv (width 4) + silu ----------------
__global__ void conv_silu_kernel(const float* __restrict__ conv_w,
                                 const float* __restrict__ conv_b)
{
    int c = blockIdx.x * 128 + threadIdx.x;
    int b = blockIdx.y;
    int t0 = blockIdx.z * 256;
    float w0 = conv_w[c * 4 + 0], w1 = conv_w[c * 4 + 1];
    float w2 = conv_w[c * 4 + 2], w3 = conv_w[c * 4 + 3];
    float bias = conv_b[c];
    const float* src = g_zx + (size_t)b * SEQL * D_IN_PROJ + DINNER + c;
    float* dst = g_xBC + (size_t)b * SEQL * CONV_DIM + c;
    float x0 = (t0 >= 3) ? src[(size_t)(t0 - 3) * D_IN_PROJ] : 0.f;
    float x1 = (t0 >= 2) ? src[(size_t)(t0 - 2) * D_IN_PROJ] : 0.f;
    float x2 = (t0 >= 1) ? src[(size_t)(t0 - 1) * D_IN_PROJ] : 0.f;
    for (int t = t0; t < t0 + 256; t++) {
        float x3 = src[(size_t)t * D_IN_PROJ];
        float a = bias + w0 * x0 + w1 * x1 + w2 * x2 + w3 * x3;
        dst[(size_t)t * CONV_DIM] = siluf(a);
        x0 = x1; x1 = x2; x2 = x3;
    }
}

// ---------------- dt softplus + per-chunk cumsum of dA ----------------
__global__ void dt_scan_kernel(const float* __restrict__ dt_bias,
                               const float* __restrict__ A_log)
{
    int idx = blockIdx.x;
    int c = idx % NCHUNK; idx /= NCHUNK;
    int h = idx % NHEADS;
    int b = idx / NHEADS;
    int l = threadIdx.x;
    int t = c * CHUNKL + l;
    float raw = g_zx[(size_t)(b * SEQL + t) * D_IN_PROJ + DINNER + CONV_DIM + h];
    float xv = raw + dt_bias[h];
    float dt = (xv > 20.f) ? xv : log1pf(expf(xv));
    g_dt[(b * SEQL + t) * NHEADS + h] = dt;
    float dA = dt * (-expf(A_log[h]));
    __shared__ float s[CHUNKL];
    s[l] = dA;
    __syncthreads();
    for (int off = 1; off < CHUNKL; off <<= 1) {
        float v = (l >= off) ? s[l - off] : 0.f;
        __syncthreads();
        s[l] += v;
        __syncthreads();
    }
    g_Acs[((b * NHEADS + h) * NCHUNK + c) * CHUNKL + l] = s[l];
}

// ---------------- SSM operand converts ----------------
// B, C split natural layout: [b*SEQL + t][128]
__global__ void cvt_cb_kernel()
{
    int idx = blockIdx.x * 256 + threadIdx.x;          // over B_SZ*SEQL*64
    int bt = idx >> 6, j2 = (idx & 63) << 1;
    const float* src = g_xBC + (size_t)bt * CONV_DIM + DINNER;
    size_t o = (size_t)bt * DSTATE + j2;
    split_store2(g_Bh, g_Bl, o, src[j2], src[j2 + 1]);
    split_store2(g_Ch, g_Cl, o, src[DSTATE + j2], src[DSTATE + j2 + 1]);
}

// B^T single: [b][n][t]
__global__ void cvt_bt_kernel()
{
    __shared__ float tile[32][33];
    int b = blockIdx.z, n0 = blockIdx.y * 32, t0 = blockIdx.x * 32;
    int tid = threadIdx.x;
#pragma unroll
    for (int it = 0; it < 4; it++) {
        int v = tid + it * 256;
        int t = v >> 5, n = v & 31;
        tile[t][n] = g_xBC[(size_t)(b * SEQL + t0 + t) * CONV_DIM + DINNER + n0 + n];
    }
    __syncthreads();
#pragma unroll
    for (int it = 0; it < 2; it++) {
        int v = tid + it * 256;
        int n = v >> 4, tc = (v & 15) << 1;
        size_t o = (size_t)(b * DSTATE + n0 + n) * SEQL + t0 + tc;
        *(__half2*)(g_BT + o) = __floats2half2_rn(tile[tc][n], tile[tc + 1][n]);
    }
}

// XdT = (x_ssm*dt)^T single, XdecT = (x_ssm*dt*dec)^T single : [b][h][p][t]
__global__ void cvt_xdt_kernel()
{
    __shared__ float xs[64][65];
    __shared__ float dts[64], dec[64];
    int b = blockIdx.z, h = blockIdx.y, tt = blockIdx.x;
    int t0 = tt * 64, tid = threadIdx.x;
    int c = t0 >> 8;
    const float* acs = g_Acs + ((b * NHEADS + h) * NCHUNK + c) * CHUNKL;
    if (tid < 64) {
        int tl = (t0 & 255) + tid;
        dts[tid] = g_dt[(size_t)(b * SEQL + t0 + tid) * NHEADS + h];
        dec[tid] = __expf(acs[CHUNKL - 1] - acs[tl]);
    }
#pragma unroll
    for (int it = 0; it < 16; it++) {
        int v = tid + it * 256;
        int t = v >> 6, p = v & 63;
        xs[t][p] = g_xBC[(size_t)(b * SEQL + t0 + t) * CONV_DIM + h * HEADDIM + p];
    }
    __syncthreads();
#pragma unroll
    for (int it = 0; it < 8; it++) {
        int v = tid + it * 256;
        int p = v >> 5, tc = (v & 31) << 1;
        size_t o = ((size_t)((b * NHEADS + h) * HEADDIM) + p) * SEQL + t0 + tc;
        float x0 = xs[tc][p] * dts[tc];
        float x1 = xs[tc + 1][p] * dts[tc + 1];
        *(__half2*)(g_XdT + o)   = __floats2half2_rn(x0, x1);
        *(__half2*)(g_XdecT + o) = __floats2half2_rn(x0 * dec[tc], x1 * dec[tc + 1]);
    }
}

// ---------------- states (single fp16 HMMA): states[p][n] = sum_l XdecT[p][l]*BT[n][l] ----------------
#define S_A_O 0
#define S_B_O 2048
#define S_STG 6144
#define S_SMEM_BYTES (2 * S_STG * 4)    // 49152

__global__ __launch_bounds__(256, 2) void states_hmma()
{
    extern __shared__ uint32_t sw[];
    const uint32_t sb = smem_u32(sw);
    int bid = blockIdx.x;
    int h = bid & 63, cc = (bid >> 6) & 7, b = bid >> 9;
    int tid = threadIdx.x, wid = tid >> 5, lane = tid & 31;
    int warp_m = wid >> 2, warp_n = wid & 3;
    const __half* A = g_XdecT + (size_t)((b * NHEADS + h) * HEADDIM) * SEQL + cc * CHUNKL;
    const __half* B = g_BT + (size_t)(b * DSTATE) * SEQL + cc * CHUNKL;

    float acc[2][4][4];
#pragma unroll
    for (int i = 0; i < 2; i++)
#pragma unroll
        for (int j = 0; j < 4; j++)
#pragma unroll
            for (int q = 0; q < 4; q++) acc[i][j][q] = 0.f;

    auto load_stage = [&](int kc, int buf) {
        uint32_t base = (uint32_t)buf * S_STG;
        int koff = kc * 64;
#pragma unroll
        for (int it = 0; it < 2; it++) {
            int v = tid + (it << 8);
            int r = v >> 3, ch = v & 7;
            int sch = ch ^ (r & 7);
            cp16(sb + (base + S_A_O + r * 32 + sch * 4) * 4, A + (size_t)r * SEQL + koff + ch * 8);
        }
#pragma unroll
        for (int it = 0; it < 4; it++) {
            int v = tid + (it << 8);
            int r = v >> 3, ch = v & 7;
            int sch = ch ^ (r & 7);
            cp16(sb + (base + S_B_O + r * 32 + sch * 4) * 4, B + (size_t)r * SEQL + koff + ch * 8);
        }
        asm volatile("cp.async.commit_group;" ::: "memory");
    };

    load_stage(0, 0);
    load_stage(1, 1);

    const int arow = warp_m * 32 + ((lane >> 3) & 1) * 8 + (lane & 7);
    const int cA0 = lane >> 4;
    const int brl = ((lane >> 4) & 1) * 8 + (lane & 7);
    const int cB0 = (lane >> 3) & 1;

    for (int kc = 0; kc < 4; kc++) {
        if (kc < 3) asm volatile("cp.async.wait_group 1;" ::: "memory");
        else        asm volatile("cp.async.wait_group 0;" ::: "memory");
        __syncthreads();
        uint32_t base = (uint32_t)(kc & 1) * S_STG;
#pragma unroll
        for (int kk = 0; kk < 4; kk++) {
            uint32_t a[2][4];
#pragma unroll
            for (int mi = 0; mi < 2; mi++) {
                int r = arow + mi * 16;
                uint32_t w = base + S_A_O + r * 32 + ((((kk << 1) + cA0) ^ (r & 7)) << 2);
                ldsm4(a[mi], sb + w * 4);
            }
#pragma unroll
            for (int np = 0; np < 2; np++) {
                int rb = warp_n * 32 + np * 16 + brl;
                uint32_t w = base + S_B_O + rb * 32 + ((((kk << 1) + cB0) ^ (rb & 7)) << 2);
                uint32_t bf[4];
                ldsm4(bf, sb + w * 4);
#pragma unroll
                for (int mi = 0; mi < 2; mi++) {
                    mma_fp16(acc[mi][2 * np], a[mi], bf);
                    mma_fp16(acc[mi][2 * np + 1], a[mi], bf + 2);
                }
            }
        }
        __syncthreads();
        if (kc + 2 < 4) load_stage(kc + 2, kc & 1);
    }

    float* out = g_states + (size_t)((b * NCHUNK + cc) * NHEADS + h) * HEADDIM * DSTATE;
#pragma unroll
    for (int mi = 0; mi < 2; mi++) {
        int r0 = warp_m * 32 + mi * 16 + (lane >> 2);
#pragma unroll
        for (int ni = 0; ni < 4; ni++) {
            int col = warp_n * 32 + ni * 8 + 2 * (lane & 3);
            *(float2*)(out + (size_t)r0 * DSTATE + col) = make_float2(acc[mi][ni][0], acc[mi][ni][1]);
            *(float2*)(out + (size_t)(r0 + 8) * DSTATE + col) = make_float2(acc[mi][ni][2], acc[mi][ni][3]);
        }
    }
}

// ---------------- inter-chunk recurrence (fp32 states -> fp16 prev hi/lo) ----------------
__global__ __launch_bounds__(1024) void prev_kernel()
{
    int b = blockIdx.x >> 6;
    int h = blockIdx.x & 63;
    int tid = threadIdx.x;
    float P[8];
#pragma unroll
    for (int i = 0; i < 8; i++) P[i] = 0.f;
    for (int c = 0; c < NCHUNK; c++) {
        float decay = __expf(g_Acs[((b * NHEADS + h) * NCHUNK + c) * CHUNKL + CHUNKL - 1]);
        size_t base = (size_t)((b * NCHUNK + c) * NHEADS + h) * HEADDIM * DSTATE;
#pragma unroll
        for (int i = 0; i < 8; i++) {
            int e = i * 1024 + tid;
            float v = P[i];
            __half hh = __float2half_rn(v);
            g_prevh[base + e] = hh;
            g_prevl[base + e] = __float2half_rn(v - __half2float(hh));
            P[i] = v * decay + g_states[base + e];
        }
    }
}

// ---------------- Y via HMMA (C/B/prev split; S, Xd single) ----------------
#define Y_ACS_O 0
#define Y_CH_O 256
#define Y_CL_O (Y_CH_O + 4352)
#define Y_PBH_O (Y_CL_O + 4352)
#define Y_PBL_O (Y_PBH_O + 4352)
#define Y_XD_O (Y_PBL_O + 4352)
#define Y_S_O  (Y_XD_O + 2304)
#define Y_SMEM_BYTES ((Y_S_O + 2304) * 4)    // 89088

__global__ __launch_bounds__(256, 2) void y_hmma(const float* __restrict__ Dp)
{
    extern __shared__ uint32_t sw[];
    const uint32_t sb = smem_u32(sw);
    float* acs_s = (float*)(sw + Y_ACS_O);
    int bid = blockIdx.x;
    int lt = bid & 3, h = (bid >> 2) & 63, c = (bid >> 8) & 7, b = bid >> 11;
    int tid = threadIdx.x, wid = tid >> 5, lane = tid & 31;
    int warp_m = wid >> 2, warp_n = wid & 3;
    int l0 = lt * 64;
    const int bt0 = b * SEQL + c * CHUNKL;

    acs_s[tid] = g_Acs[((b * NHEADS + h) * NCHUNK + c) * CHUNKL + tid];

    // prologue: C hi/lo (rows l0..l0+63), prev hi/lo
    {
        const __half* sCh = g_Ch + (size_t)(bt0 + l0) * DSTATE;
        const __half* sCl = g_Cl + (size_t)(bt0 + l0) * DSTATE;
        size_t pb = (size_t)((b * NCHUNK + c) * NHEADS + h) * HEADDIM * DSTATE;
        const __half* sPh = g_prevh + pb;
        const __half* sPl = g_prevl + pb;
#pragma unroll
        for (int it = 0; it < 4; it++) {
            int v = tid + (it << 8);
            int r = v >> 4, ch = v & 15;
            cp16(sb + (Y_CH_O + r * 68 + ch * 4) * 4, sCh + (size_t)r * DSTATE + ch * 8);
            cp16(sb + (Y_CL_O + r * 68 + ch * 4) * 4, sCl + (size_t)r * DSTATE + ch * 8);
            cp16(sb + (Y_PBH_O + r * 68 + ch * 4) * 4, sPh + (size_t)r * DSTATE + ch * 8);
            cp16(sb + (Y_PBL_O + r * 68 + ch * 4) * 4, sPl + (size_t)r * DSTATE + ch * 8);
        }
        asm volatile("cp.async.commit_group;" ::: "memory");
        asm volatile("cp.async.wait_group 0;" ::: "memory");
    }
    __syncthreads();

    float Yacc[2][2][4];
#pragma unroll
    for (int i = 0; i < 2; i++)
#pragma unroll
        for (int j = 0; j < 2; j++)
#pragma unroll
            for (int q = 0; q < 4; q++) Yacc[i][j][q] = 0.f;

    const int arow = warp_m * 32 + ((lane >> 3) & 1) * 8 + (lane & 7);
    const int akw  = (lane >> 4) << 2;
    const int brow = warp_n * 16 + ((lane >> 4) & 1) * 8 + (lane & 7);
    const int bkw  = ((lane >> 3) & 1) << 2;

    // Y_off = C * prev^T  (K = 128, split)
#pragma unroll
    for (int kk = 0; kk < 8; kk++) {
        uint32_t ah[2][4], al[2][4], bh[4], bl[4];
#pragma unroll
        for (int mi = 0; mi < 2; mi++) {
            uint32_t w = Y_CH_O + (arow + mi * 16) * 68 + kk * 8 + akw;
            ldsm4(ah[mi], sb + w * 4);
            ldsm4(al[mi], sb + (w + (Y_CL_O - Y_CH_O)) * 4);
        }
        {
            uint32_t w = Y_PBH_O + brow * 68 + kk * 8 + bkw;
            ldsm4(bh, sb + w * 4);
            ldsm4(bl, sb + (w + (Y_PBL_O - Y_PBH_O)) * 4);
        }
#pragma unroll
        for (int mi = 0; mi < 2; mi++) {
            mma_fp16(Yacc[mi][0], ah[mi], bh);
            mma_fp16(Yacc[mi][0], ah[mi], bl);
            mma_fp16(Yacc[mi][0], al[mi], bh);
            mma_fp16(Yacc[mi][1], ah[mi], bh + 2);
            mma_fp16(Yacc[mi][1], ah[mi], bl + 2);
            mma_fp16(Yacc[mi][1], al[mi], bh + 2);
        }
    }
    // scale Y_off rows by exp(acs[l])
#pragma unroll
    for (int mi = 0; mi < 2; mi++) {
        int r0 = l0 + warp_m * 32 + mi * 16 + (lane >> 2);
        float e0 = __expf(acs_s[r0]);
        float e1 = __expf(acs_s[r0 + 8]);
#pragma unroll
        for (int ni = 0; ni < 2; ni++) {
            Yacc[mi][ni][0] *= e0; Yacc[mi][ni][1] *= e0;
            Yacc[mi][ni][2] *= e1; Yacc[mi][ni][3] *= e1;
        }
    }

    for (int st = 0; st <= lt; st++) {
        int s0 = st * 64;
        __syncthreads();
        {
            const __half* sBh = g_Bh + (size_t)(bt0 + s0) * DSTATE;
            const __half* sBl = g_Bl + (size_t)(bt0 + s0) * DSTATE;
            const __half* sXh = g_XdT + (size_t)((b * NHEADS + h) * HEADDIM) * SEQL + c * CHUNKL + s0;
#pragma unroll
            for (int it = 0; it < 4; it++) {
                int v = tid + (it << 8);
                int r = v >> 4, ch = v & 15;
                cp16(sb + (Y_PBH_O + r * 68 + ch * 4) * 4, sBh + (size_t)r * DSTATE + ch * 8);
                cp16(sb + (Y_PBL_O + r * 68 + ch * 4) * 4, sBl + (size_t)r * DSTATE + ch * 8);
            }
#pragma unroll
            for (int it = 0; it < 2; it++) {
                int v = tid + (it << 8);
                int r = v >> 3, ch = v & 7;
                cp16(sb + (Y_XD_O + r * 36 + ch * 4) * 4, sXh + (size_t)r * SEQL + ch * 8);
            }
            asm volatile("cp.async.commit_group;" ::: "memory");
            asm volatile("cp.async.wait_group 0;" ::: "memory");
        }
        __syncthreads();

        // S = C * B^T (K=128, split)
        float sacc[2][2][4];
#pragma unroll
        for (int i = 0; i < 2; i++)
#pragma unroll
            for (int j = 0; j < 2; j++)
#pragma unroll
                for (int q = 0; q < 4; q++) sacc[i][j][q] = 0.f;
#pragma unroll
        for (int kk = 0; kk < 8; kk++) {
            uint32_t ah[2][4], al[2][4], bh[4], bl[4];
#pragma unroll
            for (int mi = 0; mi < 2; mi++) {
                uint32_t w = Y_CH_O + (arow + mi * 16) * 68 + kk * 8 + akw;
                ldsm4(ah[mi], sb + w * 4);
                ldsm4(al[mi], sb + (w + (Y_CL_O - Y_CH_O)) * 4);
            }
            {
                uint32_t w = Y_PBH_O + brow * 68 + kk * 8 + bkw;
                ldsm4(bh, sb + w * 4);
                ldsm4(bl, sb + (w + (Y_PBL_O - Y_PBH_O)) * 4);
            }
#pragma unroll
            for (int mi = 0; mi < 2; mi++) {
                mma_fp16(sacc[mi][0], ah[mi], bh);
                mma_fp16(sacc[mi][0], ah[mi], bl);
                mma_fp16(sacc[mi][0], al[mi], bh);
                mma_fp16(sacc[mi][1], ah[mi], bh + 2);
                mma_fp16(sacc[mi][1], ah[mi], bl + 2);
                mma_fp16(sacc[mi][1], al[mi], bh + 2);
            }
        }
        // mask + decay -> S single in smem
#pragma unroll
        for (int mi = 0; mi < 2; mi++) {
            int rr0 = warp_m * 32 + mi * 16 + (lane >> 2);
            int lg0 = l0 + rr0, lg1 = lg0 + 8;
            float a0 = acs_s[lg0], a1 = acs_s[lg1];
#pragma unroll
            for (int ni = 0; ni < 2; ni++) {
                int ccc = warp_n * 16 + ni * 8 + 2 * (lane & 3);
                int sg = s0 + ccc;
                float as0 = acs_s[sg], as1 = acs_s[sg + 1];
                float v00 = (sg     <= lg0) ? sacc[mi][ni][0] * __expf(a0 - as0) : 0.f;
                float v01 = (sg + 1 <= lg0) ? sacc[mi][ni][1] * __expf(a0 - as1) : 0.f;
                float v10 = (sg     <= lg1) ? sacc[mi][ni][2] * __expf(a1 - as0) : 0.f;
                float v11 = (sg + 1 <= lg1) ? sacc[mi][ni][3] * __expf(a1 - as1) : 0.f;
                sw[Y_S_O + rr0 * 36 + (ccc >> 1)] =
                    packh2(__float2half_rn(v00), __float2half_rn(v01));
                sw[Y_S_O + (rr0 + 8) * 36 + (ccc >> 1)] =
                    packh2(__float2half_rn(v10), __float2half_rn(v11));
            }
        }
        __syncthreads();
        // Y += S * Xd^T  (K = 64, single)
#pragma unroll
        for (int kk = 0; kk < 4; kk++) {
            uint32_t a[2][4], bf[4];
#pragma unroll
            for (int mi = 0; mi < 2; mi++) {
                uint32_t w = Y_S_O + (arow + mi * 16) * 36 + kk * 8 + akw;
                ldsm4(a[mi], sb + w * 4);
            }
            {
                uint32_t w = Y_XD_O + brow * 36 + kk * 8 + bkw;
                ldsm4(bf, sb + w * 4);
            }
#pragma unroll
            for (int mi = 0; mi < 2; mi++) {
                mma_fp16(Yacc[mi][0], a[mi], bf);
                mma_fp16(Yacc[mi][1], a[mi], bf + 2);
            }
        }
    }

    // epilogue: + D*x_ssm, gate with silu(z)
    float Dh = Dp[h];
#pragma unroll
    for (int mi = 0; mi < 2; mi++) {
#pragma unroll
        for (int q = 0; q < 2; q++) {
            int rr = warp_m * 32 + mi * 16 + (lane >> 2) + q * 8;
            int t = bt0 + l0 + rr;
#pragma unroll
            for (int ni = 0; ni < 2; ni++) {
                int pp = warp_n * 16 + ni * 8 + 2 * (lane & 3);
                float2 xs = *(const float2*)(g_xBC + (size_t)t * CONV_DIM + h * HEADDIM + pp);
                float2 zz = *(const float2*)(g_zx + (size_t)t * D_IN_PROJ + h * HEADDIM + pp);
                float y0 = Yacc[mi][ni][q * 2 + 0] + xs.x * Dh;
                float y1 = Yacc[mi][ni][q * 2 + 1] + xs.y * Dh;
                float2 o = make_float2(y0 * siluf(zz.x), y1 * siluf(zz.y));
                *(float2*)(g_yg + (size_t)t * DINNER + h * HEADDIM + pp) = o;
            }
        }
    }
}

// ---------------- RMSNorm -> fp16 ----------------
__global__ __launch_bounds__(256) void rmsnorm_kernel(const float* __restrict__ w)
{
    int row = blockIdx.x;
    const float* y = g_yg + (size_t)row * DINNER;
    __half* oh = g_ynh + (size_t)row * DINNER;
    int tid = threadIdx.x;
    float ss = 0.f;
#pragma unroll
    for (int it = 0; it < 4; it++) {
        float4 v = *(const float4*)(y + it * 1024 + tid * 4);
        ss += v.x * v.x + v.y * v.y + v.z * v.z + v.w * v.w;
    }
#pragma unroll
    for (int off = 16; off; off >>= 1) ss += __shfl_xor_sync(0xFFFFFFFFu, ss, off);
    __shared__ float red[8];
    if ((tid & 31) == 0) red[tid >> 5] = ss;
    __syncthreads();
    float tot = 0.f;
#pragma unroll
    for (int i = 0; i < 8; i++) tot += red[i];
    float scale = rsqrtf(tot / (float)DINNER + EPSV);
#pragma unroll
    for (int it = 0; it < 4; it++) {
        int i = it * 1024 + tid * 4;
        float4 v = *(const float4*)(y + i);
        float4 wv = *(const float4*)(w + i);
        __half2* hp = (__half2*)(oh + i);
        hp[0] = __floats2half2_rn(v.x * scale * wv.x, v.y * scale * wv.y);
        hp[1] = __floats2half2_rn(v.z * scale * wv.z, v.w * scale * wv.w);
    }
}

// ---------------- launch ----------------
extern "C" void kernel_launch(void* const* d_in, const int* in_sizes, int n_in,
                              void* d_out, int out_size)
{
    const float* x          = (const float*)d_in[0];
    const float* in_proj_w  = (const float*)d_in[1];
    const float* conv_w     = (const float*)d_in[2];
    const float* conv_b     = (const float*)d_in[3];
    const float* dt_bias    = (const float*)d_in[4];
    const float* A_log      = (const float*)d_in[5];
    const float* Dp         = (const float*)d_in[6];
    const float* norm_w     = (const float*)d_in[7];
    const float* out_proj_w = (const float*)d_in[8];
    float* out = (float*)d_out;

    float *zx_p = nullptr;
    __half *xh_p, *wih_p, *ynh_p, *owh_p;
    cudaGetSymbolAddress((void**)&zx_p, g_zx);
    cudaGetSymbolAddress((void**)&xh_p, g_xh);
    cudaGetSymbolAddress((void**)&wih_p, g_wih);
    cudaGetSymbolAddress((void**)&ynh_p, g_ynh);
    cudaGetSymbolAddress((void**)&owh_p, g_owh);

    static bool attr_set = false;
    if (!attr_set) {
        cudaFuncSetAttribute(gemm_hmma_fp16, cudaFuncAttributeMaxDynamicSharedMemorySize, GEMM1_SMEM);
        cudaFuncSetAttribute(states_hmma, cudaFuncAttributeMaxDynamicSharedMemorySize, S_SMEM_BYTES);
        cudaFuncSetAttribute(y_hmma, cudaFuncAttributeMaxDynamicSharedMemorySize, Y_SMEM_BYTES);
        attr_set = true;
    }

    const int M = B_SZ * SEQL; // 4096

    // converts (projections)
    {
        long n = (long)M * DMODEL;
        cvt_half<<<(unsigned)((n / 4 + 255) / 256), 256>>>(x, xh_p, n, n);
    }
    {
        long ns = (long)D_IN_PROJ * DMODEL, nt = (long)DIP_PAD * DMODEL;
        cvt_half<<<(unsigned)((nt / 4 + 255) / 256), 256>>>(in_proj_w, wih_p, ns, nt);
    }
    {
        long n = (long)DMODEL * DINNER;
        cvt_half<<<(unsigned)((n / 4 + 255) / 256), 256>>>(out_proj_w, owh_p, n, n);
    }

    // 1) in_proj GEMM
    gemm_hmma_fp16<<<dim3(DIP_PAD / 128, M / 128), 256, GEMM1_SMEM>>>(
        xh_p, wih_p, zx_p, M, D_IN_PROJ, DMODEL);

    // 2) conv + silu
    conv_silu_kernel<<<dim3(CONV_DIM / 128, B_SZ, SEQL / 256), 128>>>(conv_w, conv_b);

    // 3) dt softplus + cumsum
    dt_scan_kernel<<<B_SZ * NHEADS * NCHUNK, CHUNKL>>>(dt_bias, A_log);

    // 4) SSM operand converts
    cvt_cb_kernel<<<(B_SZ * SEQL * 64) / 256, 256>>>();
    cvt_bt_kernel<<<dim3(SEQL / 32, DSTATE / 32, B_SZ), 256>>>();
    cvt_xdt_kernel<<<dim3(SEQL / 64, NHEADS, B_SZ), 256>>>();

    // 5) states (single fp16 HMMA)
    states_hmma<<<B_SZ * NCHUNK * NHEADS, 256, S_SMEM_BYTES>>>();

    // 6) recurrence -> prev fp16 hi/lo
    prev_kernel<<<B_SZ * NHEADS, 1024>>>();

    // 7) Y (HMMA) + gate
    y_hmma<<<B_SZ * NCHUNK * NHEADS * 4, 256, Y_SMEM_BYTES>>>(Dp);

    // 8) RMSNorm -> fp16
    rmsnorm_kernel<<<B_SZ * SEQL, 256>>>(norm_w);

    // 9) out_proj GEMM
    gemm_hmma_fp16<<<dim3(DMODEL / 128, M / 128), 256, GEMM1_SMEM>>>(
        ynh_p, owh_p, out, M, DMODEL, DINNER);

    (void)in_sizes; (void)n_in; (void)out_size;
}

// round 10
// speedup vs baseline: 6.5599x; 1.0967x over previous
#include <cuda_runtime.h>
#include <cuda_bf16.h>
#include <cuda_fp16.h>
#include <cstdint>
#include <cstring>

#define B_SZ 2
#define SEQL 2048
#define DMODEL 2048
#define DINNER 4096
#define DSTATE 128
#define HEADDIM 64
#define NHEADS 64
#define CHUNKL 256
#define NCHUNK 8
#define CONV_DIM 4352     // DINNER + 2*DSTATE
#define D_IN_PROJ 8512    // 2*DINNER + 2*DSTATE + NHEADS
#define DIP_PAD 8576      // 67*128
#define EPSV 1e-5f

// ---------------- scratch ----------------
__device__ float g_zx[B_SZ*SEQL*D_IN_PROJ];
__device__ float g_xBC[B_SZ*SEQL*CONV_DIM];
__device__ float g_dt[B_SZ*SEQL*NHEADS];
__device__ float g_Acs[B_SZ*NHEADS*NCHUNK*CHUNKL];
__device__ float g_states[(size_t)B_SZ*NCHUNK*NHEADS*HEADDIM*DSTATE];
__device__ float g_yg[B_SZ*SEQL*DINNER];
// fp16 gemm operands
__device__ __half g_xh[B_SZ*SEQL*DMODEL];
__device__ __half g_wih[(size_t)DIP_PAD*DMODEL];
__device__ __half g_ynh[B_SZ*SEQL*DINNER];
__device__ __half g_owh[(size_t)DMODEL*DINNER];
// SSM operands (all single fp16)
__device__ __half g_B[B_SZ*SEQL*DSTATE];
__device__ __half g_C[B_SZ*SEQL*DSTATE];
__device__ __half g_BT[B_SZ*DSTATE*SEQL];
__device__ __half g_XdT[(size_t)B_SZ*NHEADS*HEADDIM*SEQL];
__device__ __half g_XdecT[(size_t)B_SZ*NHEADS*HEADDIM*SEQL];
__device__ __half g_prev[(size_t)B_SZ*NCHUNK*NHEADS*HEADDIM*DSTATE];

__device__ __forceinline__ float siluf(float a) { return a / (1.f + expf(-a)); }

// ================= common HMMA helpers =================
__device__ __forceinline__ void mma_fp16(float* c, const uint32_t* a, const uint32_t* b) {
    asm volatile(
        "mma.sync.aligned.m16n8k16.row.col.f32.f16.f16.f32 "
        "{%0,%1,%2,%3}, {%4,%5,%6,%7}, {%8,%9}, {%0,%1,%2,%3};"
        : "+f"(c[0]), "+f"(c[1]), "+f"(c[2]), "+f"(c[3])
        : "r"(a[0]), "r"(a[1]), "r"(a[2]), "r"(a[3]), "r"(b[0]), "r"(b[1]));
}
__device__ __forceinline__ void ldsm4(uint32_t* r, uint32_t addr) {
    asm volatile("ldmatrix.sync.aligned.m8n8.x4.shared.b16 {%0,%1,%2,%3}, [%4];"
        : "=r"(r[0]), "=r"(r[1]), "=r"(r[2]), "=r"(r[3]) : "r"(addr));
}
__device__ __forceinline__ void cp16(uint32_t dst, const void* src) {
    asm volatile("cp.async.cg.shared.global [%0], [%1], 16;" :: "r"(dst), "l"(src));
}
__device__ __forceinline__ uint32_t smem_u32(const void* p) {
    uint32_t a;
    asm("{ .reg .u64 t; cvta.to.shared.u64 t, %1; cvt.u32.u64 %0, t; }" : "=r"(a) : "l"(p));
    return a;
}
__device__ __forceinline__ uint32_t packh2(__half a, __half b) {
    __half2 h = __halves2half2(a, b);
    uint32_t u; memcpy(&u, &h, 4); return u;
}

// ================= fp16 HMMA GEMM, BK=64, 3 stages =================
#define OPW64 4096                        // words per 128x64 operand tile
#define STG64 (2 * OPW64)                 // A+B stage, 32 KB
#define GEMM1_SMEM (3 * STG64 * 4)        // 98304 B

// 128 rows x 64 halfs, row = 32 words, swizzle: chunk ^= (r&7)
__device__ __forceinline__ void load_op64(uint32_t sbase_b, const __half* g, int ldk, int tid) {
#pragma unroll
    for (int it = 0; it < 4; it++) {
        int v = tid + (it << 8);
        int r = v >> 3, ch = v & 7;
        int sch = ch ^ (r & 7);
        cp16(sbase_b + (r * 32 + (sch << 2)) * 4, g + (size_t)r * ldk + (ch << 3));
    }
}

__global__ __launch_bounds__(256, 2) void gemm_hmma_fp16(
    const __half* __restrict__ A, const __half* __restrict__ B,
    float* __restrict__ C, int M, int Nreal, int K)
{
    extern __shared__ uint32_t sw[];
    const uint32_t sb = smem_u32(sw);
    const int tid = threadIdx.x, wid = tid >> 5, lane = tid & 31;
    const int warp_m = wid & 1, warp_n = wid >> 1;
    const int m0 = blockIdx.y << 7, n0 = blockIdx.x << 7;
    const int KT = K >> 6;

    const __half* Ab = A + (size_t)m0 * K;
    const __half* Bb = B + (size_t)n0 * K;

    float acc[4][4][4];
#pragma unroll
    for (int i = 0; i < 4; i++)
#pragma unroll
        for (int j = 0; j < 4; j++)
#pragma unroll
            for (int q = 0; q < 4; q++) acc[i][j][q] = 0.f;

    // prologue: stages 0,1
#pragma unroll
    for (int s = 0; s < 2; s++) {
        int koff = s << 6;
        load_op64(sb + (s * STG64) * 4, Ab + koff, K, tid);
        load_op64(sb + (s * STG64 + OPW64) * 4, Bb + koff, K, tid);
        asm volatile("cp.async.commit_group;" ::: "memory");
    }

    const int rowA = warp_m * 64 + ((lane >> 3) & 1) * 8 + (lane & 7);
    const int cA0  = lane >> 4;
    const int rowB = warp_n * 32 + ((lane >> 4) & 1) * 8 + (lane & 7);
    const int cB0  = (lane >> 3) & 1;

    int buf = 0;
    for (int kt = 0; kt < KT; kt++) {
        if (kt + 1 < KT) asm volatile("cp.async.wait_group 1;" ::: "memory");
        else             asm volatile("cp.async.wait_group 0;" ::: "memory");
        __syncthreads();
        if (kt + 2 < KT) {
            int s = buf + 2; if (s >= 3) s -= 3;
            int koff = (kt + 2) << 6;
            load_op64(sb + (s * STG64) * 4, Ab + koff, K, tid);
            load_op64(sb + (s * STG64 + OPW64) * 4, Bb + koff, K, tid);
            asm volatile("cp.async.commit_group;" ::: "memory");
        }

        const uint32_t sA = sb + (uint32_t)buf * STG64 * 4u;
        const uint32_t sB = sA + OPW64 * 4u;

#pragma unroll
        for (int kk = 0; kk < 4; kk++) {
            uint32_t a[4][4];
#pragma unroll
            for (int mi = 0; mi < 4; mi++) {
                int r = rowA + mi * 16;
                uint32_t off = (r * 32 + ((((kk << 1) + cA0) ^ (r & 7)) << 2)) * 4u;
                ldsm4(a[mi], sA + off);
            }
#pragma unroll
            for (int np = 0; np < 2; np++) {
                int r = rowB + np * 16;
                uint32_t boff = (r * 32 + ((((kk << 1) + cB0) ^ (r & 7)) << 2)) * 4u;
                uint32_t b[4];
                ldsm4(b, sB + boff);
#pragma unroll
                for (int mi = 0; mi < 4; mi++) {
                    mma_fp16(acc[mi][2 * np], a[mi], b);
                    mma_fp16(acc[mi][2 * np + 1], a[mi], b + 2);
                }
            }
        }
        buf++; if (buf == 3) buf = 0;
    }

#pragma unroll
    for (int mi = 0; mi < 4; mi++) {
        int rg0 = m0 + warp_m * 64 + mi * 16 + (lane >> 2);
#pragma unroll
        for (int ni = 0; ni < 4; ni++) {
            int cg = n0 + warp_n * 32 + ni * 8 + ((lane & 3) << 1);
            if (cg < Nreal) {
                *(float2*)(C + (size_t)rg0 * Nreal + cg) =
                    make_float2(acc[mi][ni][0], acc[mi][ni][1]);
                *(float2*)(C + (size_t)(rg0 + 8) * Nreal + cg) =
                    make_float2(acc[mi][ni][2], acc[mi][ni][3]);
            }
        }
    }
}

// ---------------- fp32 -> fp16 (with zero-pad tail) ----------------
__global__ void cvt_half(const float* __restrict__ src, __half* __restrict__ dst,
                         long n_src, long n_tot)
{
    long i = ((long)blockIdx.x * 256 + threadIdx.x) * 4;
    if (i >= n_tot) return;
    float4 v = (i < n_src) ? *(const float4*)(src + i) : make_float4(0.f, 0.f, 0.f, 0.f);
    __half2* dp = (__half2*)(dst + i);
    dp[0] = __floats2half2_rn(v.x, v.y);
    dp[1] = __floats2half2_rn(v.z, v.w);
}

// ---------------- causal depthwise conv (width 4) + silu ----------------
__global__ void conv_silu_kernel(const float* __restrict__ conv_w,
                                 const float* __restrict__ conv_b)
{
    int c = blockIdx.x * 128 + threadIdx.x;
    int b = blockIdx.y;
    int t0 = blockIdx.z * 256;
    float w0 = conv_w[c * 4 + 0], w1 = conv_w[c * 4 + 1];
    float w2 = conv_w[c * 4 + 2], w3 = conv_w[c * 4 + 3];
    float bias = conv_b[c];
    const float* src = g_zx + (size_t)b * SEQL * D_IN_PROJ + DINNER + c;
    float* dst = g_xBC + (size_t)b * SEQL * CONV_DIM + c;
    float x0 = (t0 >= 3) ? src[(size_t)(t0 - 3) * D_IN_PROJ] : 0.f;
    float x1 = (t0 >= 2) ? src[(size_t)(t0 - 2) * D_IN_PROJ] : 0.f;
    float x2 = (t0 >= 1) ? src[(size_t)(t0 - 1) * D_IN_PROJ] : 0.f;
    for (int t = t0; t < t0 + 256; t++) {
        float x3 = src[(size_t)t * D_IN_PROJ];
        float a = bias + w0 * x0 + w1 * x1 + w2 * x2 + w3 * x3;
        dst[(size_t)t * CONV_DIM] = siluf(a);
        x0 = x1; x1 = x2; x2 = x3;
    }
}

// ---------------- dt softplus + per-chunk cumsum of dA ----------------
__global__ void dt_scan_kernel(const float* __restrict__ dt_bias,
                               const float* __restrict__ A_log)
{
    int idx = blockIdx.x;
    int c = idx % NCHUNK; idx /= NCHUNK;
    int h = idx % NHEADS;
    int b = idx / NHEADS;
    int l = threadIdx.x;
    int t = c * CHUNKL + l;
    float raw = g_zx[(size_t)(b * SEQL + t) * D_IN_PROJ + DINNER + CONV_DIM + h];
    float xv = raw + dt_bias[h];
    float dt = (xv > 20.f) ? xv : log1pf(expf(xv));
    g_dt[(b * SEQL + t) * NHEADS + h] = dt;
    float dA = dt * (-expf(A_log[h]));
    __shared__ float s[CHUNKL];
    s[l] = dA;
    __syncthreads();
    for (int off = 1; off < CHUNKL; off <<= 1) {
        float v = (l >= off) ? s[l - off] : 0.f;
        __syncthreads();
        s[l] += v;
        __syncthreads();
    }
    g_Acs[((b * NHEADS + h) * NCHUNK + c) * CHUNKL + l] = s[l];
}

// ---------------- SSM operand converts ----------------
// B, C single natural layout: [b*SEQL + t][128]
__global__ void cvt_cb_kernel()
{
    int idx = blockIdx.x * 256 + threadIdx.x;          // over B_SZ*SEQL*64
    int bt = idx >> 6, j2 = (idx & 63) << 1;
    const float* src = g_xBC + (size_t)bt * CONV_DIM + DINNER;
    size_t o = (size_t)bt * DSTATE + j2;
    *(__half2*)(g_B + o) = __floats2half2_rn(src[j2], src[j2 + 1]);
    *(__half2*)(g_C + o) = __floats2half2_rn(src[DSTATE + j2], src[DSTATE + j2 + 1]);
}

// B^T single: [b][n][t]
__global__ void cvt_bt_kernel()
{
    __shared__ float tile[32][33];
    int b = blockIdx.z, n0 = blockIdx.y * 32, t0 = blockIdx.x * 32;
    int tid = threadIdx.x;
#pragma unroll
    for (int it = 0; it < 4; it++) {
        int v = tid + it * 256;
        int t = v >> 5, n = v & 31;
        tile[t][n] = g_xBC[(size_t)(b * SEQL + t0 + t) * CONV_DIM + DINNER + n0 + n];
    }
    __syncthreads();
#pragma unroll
    for (int it = 0; it < 2; it++) {
        int v = tid + it * 256;
        int n = v >> 4, tc = (v & 15) << 1;
        size_t o = (size_t)(b * DSTATE + n0 + n) * SEQL + t0 + tc;
        *(__half2*)(g_BT + o) = __floats2half2_rn(tile[tc][n], tile[tc + 1][n]);
    }
}

// XdT = (x_ssm*dt)^T single, XdecT = (x_ssm*dt*dec)^T single : [b][h][p][t]
__global__ void cvt_xdt_kernel()
{
    __shared__ float xs[64][65];
    __shared__ float dts[64], dec[64];
    int b = blockIdx.z, h = blockIdx.y, tt = blockIdx.x;
    int t0 = tt * 64, tid = threadIdx.x;
    int c = t0 >> 8;
    const float* acs = g_Acs + ((b * NHEADS + h) * NCHUNK + c) * CHUNKL;
    if (tid < 64) {
        int tl = (t0 & 255) + tid;
        dts[tid] = g_dt[(size_t)(b * SEQL + t0 + tid) * NHEADS + h];
        dec[tid] = __expf(acs[CHUNKL - 1] - acs[tl]);
    }
#pragma unroll
    for (int it = 0; it < 16; it++) {
        int v = tid + it * 256;
        int t = v >> 6, p = v & 63;
        xs[t][p] = g_xBC[(size_t)(b * SEQL + t0 + t) * CONV_DIM + h * HEADDIM + p];
    }
    __syncthreads();
#pragma unroll
    for (int it = 0; it < 8; it++) {
        int v = tid + it * 256;
        int p = v >> 5, tc = (v & 31) << 1;
        size_t o = ((size_t)((b * NHEADS + h) * HEADDIM) + p) * SEQL + t0 + tc;
        float x0 = xs[tc][p] * dts[tc];
        float x1 = xs[tc + 1][p] * dts[tc + 1];
        *(__half2*)(g_XdT + o)   = __floats2half2_rn(x0, x1);
        *(__half2*)(g_XdecT + o) = __floats2half2_rn(x0 * dec[tc], x1 * dec[tc + 1]);
    }
}

// ---------------- states (single fp16 HMMA): states[p][n] = sum_l XdecT[p][l]*BT[n][l] ----------------
#define S_A_O 0
#define S_B_O 2048
#define S_STG 6144
#define S_SMEM_BYTES (2 * S_STG * 4)    // 49152

__global__ __launch_bounds__(256, 2) void states_hmma()
{
    extern __shared__ uint32_t sw[];
    const uint32_t sb = smem_u32(sw);
    int bid = blockIdx.x;
    int h = bid & 63, cc = (bid >> 6) & 7, b = bid >> 9;
    int tid = threadIdx.x, wid = tid >> 5, lane = tid & 31;
    int warp_m = wid >> 2, warp_n = wid & 3;
    const __half* A = g_XdecT + (size_t)((b * NHEADS + h) * HEADDIM) * SEQL + cc * CHUNKL;
    const __half* B = g_BT + (size_t)(b * DSTATE) * SEQL + cc * CHUNKL;

    float acc[2][4][4];
#pragma unroll
    for (int i = 0; i < 2; i++)
#pragma unroll
        for (int j = 0; j < 4; j++)
#pragma unroll
            for (int q = 0; q < 4; q++) acc[i][j][q] = 0.f;

    auto load_stage = [&](int kc, int buf) {
        uint32_t base = (uint32_t)buf * S_STG;
        int koff = kc * 64;
#pragma unroll
        for (int it = 0; it < 2; it++) {
            int v = tid + (it << 8);
            int r = v >> 3, ch = v & 7;
            int sch = ch ^ (r & 7);
            cp16(sb + (base + S_A_O + r * 32 + sch * 4) * 4, A + (size_t)r * SEQL + koff + ch * 8);
        }
#pragma unroll
        for (int it = 0; it < 4; it++) {
            int v = tid + (it << 8);
            int r = v >> 3, ch = v & 7;
            int sch = ch ^ (r & 7);
            cp16(sb + (base + S_B_O + r * 32 + sch * 4) * 4, B + (size_t)r * SEQL + koff + ch * 8);
        }
        asm volatile("cp.async.commit_group;" ::: "memory");
    };

    load_stage(0, 0);
    load_stage(1, 1);

    const int arow = warp_m * 32 + ((lane >> 3) & 1) * 8 + (lane & 7);
    const int cA0 = lane >> 4;
    const int brl = ((lane >> 4) & 1) * 8 + (lane & 7);
    const int cB0 = (lane >> 3) & 1;

    for (int kc = 0; kc < 4; kc++) {
        if (kc < 3) asm volatile("cp.async.wait_group 1;" ::: "memory");
        else        asm volatile("cp.async.wait_group 0;" ::: "memory");
        __syncthreads();
        uint32_t base = (uint32_t)(kc & 1) * S_STG;
#pragma unroll
        for (int kk = 0; kk < 4; kk++) {
            uint32_t a[2][4];
#pragma unroll
            for (int mi = 0; mi < 2; mi++) {
                int r = arow + mi * 16;
                uint32_t w = base + S_A_O + r * 32 + ((((kk << 1) + cA0) ^ (r & 7)) << 2);
                ldsm4(a[mi], sb + w * 4);
            }
#pragma unroll
            for (int np = 0; np < 2; np++) {
                int rb = warp_n * 32 + np * 16 + brl;
                uint32_t w = base + S_B_O + rb * 32 + ((((kk << 1) + cB0) ^ (rb & 7)) << 2);
                uint32_t bf[4];
                ldsm4(bf, sb + w * 4);
#pragma unroll
                for (int mi = 0; mi < 2; mi++) {
                    mma_fp16(acc[mi][2 * np], a[mi], bf);
                    mma_fp16(acc[mi][2 * np + 1], a[mi], bf + 2);
                }
            }
        }
        __syncthreads();
        if (kc + 2 < 4) load_stage(kc + 2, kc & 1);
    }

    float* out = g_states + (size_t)((b * NCHUNK + cc) * NHEADS + h) * HEADDIM * DSTATE;
#pragma unroll
    for (int mi = 0; mi < 2; mi++) {
        int r0 = warp_m * 32 + mi * 16 + (lane >> 2);
#pragma unroll
        for (int ni = 0; ni < 4; ni++) {
            int col = warp_n * 32 + ni * 8 + 2 * (lane & 3);
            *(float2*)(out + (size_t)r0 * DSTATE + col) = make_float2(acc[mi][ni][0], acc[mi][ni][1]);
            *(float2*)(out + (size_t)(r0 + 8) * DSTATE + col) = make_float2(acc[mi][ni][2], acc[mi][ni][3]);
        }
    }
}

// ---------------- inter-chunk recurrence (fp32 states -> fp16 prev single) ----------------
__global__ __launch_bounds__(1024) void prev_kernel()
{
    int b = blockIdx.x >> 6;
    int h = blockIdx.x & 63;
    int tid = threadIdx.x;
    float P[8];
#pragma unroll
    for (int i = 0; i < 8; i++) P[i] = 0.f;
    for (int c = 0; c < NCHUNK; c++) {
        float decay = __expf(g_Acs[((b * NHEADS + h) * NCHUNK + c) * CHUNKL + CHUNKL - 1]);
        size_t base = (size_t)((b * NCHUNK + c) * NHEADS + h) * HEADDIM * DSTATE;
#pragma unroll
        for (int i = 0; i < 8; i++) {
            int e = i * 1024 + tid;
            float v = P[i];
            g_prev[base + e] = __float2half_rn(v);
            P[i] = v * decay + g_states[base + e];
        }
    }
}

// ---------------- Y via single fp16 HMMA, double-buffered B/Xd tiles ----------------
#define Y_ACS_O 0
#define Y_C_O 256
#define Y_PV_O (Y_C_O + 4352)
#define Y_B0_O (Y_PV_O + 4352)
#define Y_B1_O (Y_B0_O + 4352)
#define Y_X0_O (Y_B1_O + 4352)
#define Y_X1_O (Y_X0_O + 2304)
#define Y_S_O  (Y_X1_O + 2304)
#define Y_SMEM_BYTES ((Y_S_O + 2304) * 4)   // 98304

__global__ __launch_bounds__(256, 2) void y_hmma(const float* __restrict__ Dp)
{
    extern __shared__ uint32_t sw[];
    const uint32_t sb = smem_u32(sw);
    float* acs_s = (float*)(sw + Y_ACS_O);
    int bid = blockIdx.x;
    int lt = bid & 3, h = (bid >> 2) & 63, c = (bid >> 8) & 7, b = bid >> 11;
    int tid = threadIdx.x, wid = tid >> 5, lane = tid & 31;
    int warp_m = wid >> 2, warp_n = wid & 3;
    int l0 = lt * 64;
    const int bt0 = b * SEQL + c * CHUNKL;

    acs_s[tid] = g_Acs[((b * NHEADS + h) * NCHUNK + c) * CHUNKL + tid];

    const __half* gB = g_B + (size_t)bt0 * DSTATE;
    const __half* gX = g_XdT + (size_t)((b * NHEADS + h) * HEADDIM) * SEQL + c * CHUNKL;

    auto load_bx = [&](int st, int pbuf) {
        const __half* Bp = gB + (size_t)(st * 64) * DSTATE;
        const __half* Xp = gX + st * 64;
        uint32_t bo = pbuf ? (uint32_t)Y_B1_O : (uint32_t)Y_B0_O;
        uint32_t xo = pbuf ? (uint32_t)Y_X1_O : (uint32_t)Y_X0_O;
#pragma unroll
        for (int it = 0; it < 4; it++) {
            int v = tid + (it << 8);
            int r = v >> 4, ch = v & 15;
            cp16(sb + (bo + r * 68 + ch * 4) * 4, Bp + (size_t)r * DSTATE + ch * 8);
        }
#pragma unroll
        for (int it = 0; it < 2; it++) {
            int v = tid + (it << 8);
            int r = v >> 3, ch = v & 7;
            cp16(sb + (xo + r * 36 + ch * 4) * 4, Xp + (size_t)r * SEQL + ch * 8);
        }
        asm volatile("cp.async.commit_group;" ::: "memory");
    };

    // group 0: C (rows l0..l0+63) + prev
    {
        const __half* sC = g_C + (size_t)(bt0 + l0) * DSTATE;
        size_t pb = (size_t)((b * NCHUNK + c) * NHEADS + h) * HEADDIM * DSTATE;
        const __half* sP = g_prev + pb;
#pragma unroll
        for (int it = 0; it < 4; it++) {
            int v = tid + (it << 8);
            int r = v >> 4, ch = v & 15;
            cp16(sb + (Y_C_O + r * 68 + ch * 4) * 4, sC + (size_t)r * DSTATE + ch * 8);
            cp16(sb + (Y_PV_O + r * 68 + ch * 4) * 4, sP + (size_t)r * DSTATE + ch * 8);
        }
        asm volatile("cp.async.commit_group;" ::: "memory");
    }
    // group 1: B/Xd tile for st=0
    load_bx(0, 0);

    asm volatile("cp.async.wait_group 1;" ::: "memory");  // C+prev done
    __syncthreads();

    float Yacc[2][2][4];
#pragma unroll
    for (int i = 0; i < 2; i++)
#pragma unroll
        for (int j = 0; j < 2; j++)
#pragma unroll
            for (int q = 0; q < 4; q++) Yacc[i][j][q] = 0.f;

    const int arow = warp_m * 32 + ((lane >> 3) & 1) * 8 + (lane & 7);
    const int akw  = (lane >> 4) << 2;
    const int brow = warp_n * 16 + ((lane >> 4) & 1) * 8 + (lane & 7);
    const int bkw  = ((lane >> 3) & 1) << 2;

    // Y_off = C * prev^T  (K = 128, single)
#pragma unroll
    for (int kk = 0; kk < 8; kk++) {
        uint32_t a[2][4], bf[4];
#pragma unroll
        for (int mi = 0; mi < 2; mi++)
            ldsm4(a[mi], sb + (uint32_t)(Y_C_O + (arow + mi * 16) * 68 + kk * 8 + akw) * 4);
        ldsm4(bf, sb + (uint32_t)(Y_PV_O + brow * 68 + kk * 8 + bkw) * 4);
#pragma unroll
        for (int mi = 0; mi < 2; mi++) {
            mma_fp16(Yacc[mi][0], a[mi], bf);
            mma_fp16(Yacc[mi][1], a[mi], bf + 2);
        }
    }
    // scale Y_off rows by exp(acs[l])
#pragma unroll
    for (int mi = 0; mi < 2; mi++) {
        int r0 = l0 + warp_m * 32 + mi * 16 + (lane >> 2);
        float e0 = __expf(acs_s[r0]);
        float e1 = __expf(acs_s[r0 + 8]);
#pragma unroll
        for (int ni = 0; ni < 2; ni++) {
            Yacc[mi][ni][0] *= e0; Yacc[mi][ni][1] *= e0;
            Yacc[mi][ni][2] *= e1; Yacc[mi][ni][3] *= e1;
        }
    }

    for (int st = 0; st <= lt; st++) {
        // prefetch next s-tile while computing this one
        if (st + 1 <= lt) {
            load_bx(st + 1, (st + 1) & 1);
            asm volatile("cp.async.wait_group 1;" ::: "memory");
        } else {
            asm volatile("cp.async.wait_group 0;" ::: "memory");
        }
        __syncthreads();

        const uint32_t bo = (st & 1) ? (uint32_t)Y_B1_O : (uint32_t)Y_B0_O;
        const uint32_t xo = (st & 1) ? (uint32_t)Y_X1_O : (uint32_t)Y_X0_O;
        int s0 = st * 64;

        // S = C * B^T (K=128, single)
        float sacc[2][2][4];
#pragma unroll
        for (int i = 0; i < 2; i++)
#pragma unroll
            for (int j = 0; j < 2; j++)
#pragma unroll
                for (int q = 0; q < 4; q++) sacc[i][j][q] = 0.f;
#pragma unroll
        for (int kk = 0; kk < 8; kk++) {
            uint32_t a[2][4], bf[4];
#pragma unroll
            for (int mi = 0; mi < 2; mi++)
                ldsm4(a[mi], sb + (uint32_t)(Y_C_O + (arow + mi * 16) * 68 + kk * 8 + akw) * 4);
            ldsm4(bf, sb + (bo + brow * 68 + kk * 8 + bkw) * 4);
#pragma unroll
            for (int mi = 0; mi < 2; mi++) {
                mma_fp16(sacc[mi][0], a[mi], bf);
                mma_fp16(sacc[mi][1], a[mi], bf + 2);
            }
        }
        // mask + decay -> S single in smem
#pragma unroll
        for (int mi = 0; mi < 2; mi++) {
            int rr0 = warp_m * 32 + mi * 16 + (lane >> 2);
            int lg0 = l0 + rr0, lg1 = lg0 + 8;
            float a0 = acs_s[lg0], a1 = acs_s[lg1];
#pragma unroll
            for (int ni = 0; ni < 2; ni++) {
                int ccc = warp_n * 16 + ni * 8 + 2 * (lane & 3);
                int sg = s0 + ccc;
                float as0 = acs_s[sg], as1 = acs_s[sg + 1];
                float v00 = (sg     <= lg0) ? sacc[mi][ni][0] * __expf(a0 - as0) : 0.f;
                float v01 = (sg + 1 <= lg0) ? sacc[mi][ni][1] * __expf(a0 - as1) : 0.f;
                float v10 = (sg     <= lg1) ? sacc[mi][ni][2] * __expf(a1 - as0) : 0.f;
                float v11 = (sg + 1 <= lg1) ? sacc[mi][ni][3] * __expf(a1 - as1) : 0.f;
                sw[Y_S_O + rr0 * 36 + (ccc >> 1)] =
                    packh2(__float2half_rn(v00), __float2half_rn(v01));
                sw[Y_S_O + (rr0 + 8) * 36 + (ccc >> 1)] =
                    packh2(__float2half_rn(v10), __float2half_rn(v11));
            }
        }
        __syncthreads();
        // Y += S * Xd^T  (K = 64, single)
#pragma unroll
        for (int kk = 0; kk < 4; kk++) {
            uint32_t a[2][4], bf[4];
#pragma unroll
            for (int mi = 0; mi < 2; mi++)
                ldsm4(a[mi], sb + (uint32_t)(Y_S_O + (arow + mi * 16) * 36 + kk * 8 + akw) * 4);
            ldsm4(bf, sb + (xo + brow * 36 + kk * 8 + bkw) * 4);
#pragma unroll
            for (int mi = 0; mi < 2; mi++) {
                mma_fp16(Yacc[mi][0], a[mi], bf);
                mma_fp16(Yacc[mi][1], a[mi], bf + 2);
            }
        }
        __syncthreads();
    }

    // epilogue: + D*x_ssm, gate with silu(z)
    float Dh = Dp[h];
#pragma unroll
    for (int mi = 0; mi < 2; mi++) {
#pragma unroll
        for (int q = 0; q < 2; q++) {
            int rr = warp_m * 32 + mi * 16 + (lane >> 2) + q * 8;
            int t = bt0 + l0 + rr;
#pragma unroll
            for (int ni = 0; ni < 2; ni++) {
                int pp = warp_n * 16 + ni * 8 + 2 * (lane & 3);
                float2 xs = *(const float2*)(g_xBC + (size_t)t * CONV_DIM + h * HEADDIM + pp);
                float2 zz = *(const float2*)(g_zx + (size_t)t * D_IN_PROJ + h * HEADDIM + pp);
                float y0 = Yacc[mi][ni][q * 2 + 0] + xs.x * Dh;
                float y1 = Yacc[mi][ni][q * 2 + 1] + xs.y * Dh;
                float2 o = make_float2(y0 * siluf(zz.x), y1 * siluf(zz.y));
                *(float2*)(g_yg + (size_t)t * DINNER + h * HEADDIM + pp) = o;
            }
        }
    }
}

// ---------------- RMSNorm -> fp16 ----------------
__global__ __launch_bounds__(256) void rmsnorm_kernel(const float* __restrict__ w)
{
    int row = blockIdx.x;
    const float* y = g_yg + (size_t)row * DINNER;
    __half* oh = g_ynh + (size_t)row * DINNER;
    int tid = threadIdx.x;
    float ss = 0.f;
#pragma unroll
    for (int it = 0; it < 4; it++) {
        float4 v = *(const float4*)(y + it * 1024 + tid * 4);
        ss += v.x * v.x + v.y * v.y + v.z * v.z + v.w * v.w;
    }
#pragma unroll
    for (int off = 16; off; off >>= 1) ss += __shfl_xor_sync(0xFFFFFFFFu, ss, off);
    __shared__ float red[8];
    if ((tid & 31) == 0) red[tid >> 5] = ss;
    __syncthreads();
    float tot = 0.f;
#pragma unroll
    for (int i = 0; i < 8; i++) tot += red[i];
    float scale = rsqrtf(tot / (float)DINNER + EPSV);
#pragma unroll
    for (int it = 0; it < 4; it++) {
        int i = it * 1024 + tid * 4;
        float4 v = *(const float4*)(y + i);
        float4 wv = *(const float4*)(w + i);
        __half2* hp = (__half2*)(oh + i);
        hp[0] = __floats2half2_rn(v.x * scale * wv.x, v.y * scale * wv.y);
        hp[1] = __floats2half2_rn(v.z * scale * wv.z, v.w * scale * wv.w);
    }
}

// ---------------- launch ----------------
extern "C" void kernel_launch(void* const* d_in, const int* in_sizes, int n_in,
                              void* d_out, int out_size)
{
    const float* x          = (const float*)d_in[0];
    const float* in_proj_w  = (const float*)d_in[1];
    const float* conv_w     = (const float*)d_in[2];
    const float* conv_b     = (const float*)d_in[3];
    const float* dt_bias    = (const float*)d_in[4];
    const float* A_log      = (const float*)d_in[5];
    const float* Dp         = (const float*)d_in[6];
    const float* norm_w     = (const float*)d_in[7];
    const float* out_proj_w = (const float*)d_in[8];
    float* out = (float*)d_out;

    float *zx_p = nullptr;
    __half *xh_p, *wih_p, *ynh_p, *owh_p;
    cudaGetSymbolAddress((void**)&zx_p, g_zx);
    cudaGetSymbolAddress((void**)&xh_p, g_xh);
    cudaGetSymbolAddress((void**)&wih_p, g_wih);
    cudaGetSymbolAddress((void**)&ynh_p, g_ynh);
    cudaGetSymbolAddress((void**)&owh_p, g_owh);

    static bool attr_set = false;
    if (!attr_set) {
        cudaFuncSetAttribute(gemm_hmma_fp16, cudaFuncAttributeMaxDynamicSharedMemorySize, GEMM1_SMEM);
        cudaFuncSetAttribute(states_hmma, cudaFuncAttributeMaxDynamicSharedMemorySize, S_SMEM_BYTES);
        cudaFuncSetAttribute(y_hmma, cudaFuncAttributeMaxDynamicSharedMemorySize, Y_SMEM_BYTES);
        attr_set = true;
    }

    const int M = B_SZ * SEQL; // 4096

    // converts (projections)
    {
        long n = (long)M * DMODEL;
        cvt_half<<<(unsigned)((n / 4 + 255) / 256), 256>>>(x, xh_p, n, n);
    }
    {
        long ns = (long)D_IN_PROJ * DMODEL, nt = (long)DIP_PAD * DMODEL;
        cvt_half<<<(unsigned)((nt / 4 + 255) / 256), 256>>>(in_proj_w, wih_p, ns, nt);
    }
    {
        long n = (long)DMODEL * DINNER;
        cvt_half<<<(unsigned)((n / 4 + 255) / 256), 256>>>(out_proj_w, owh_p, n, n);
    }

    // 1) in_proj GEMM
    gemm_hmma_fp16<<<dim3(DIP_PAD / 128, M / 128), 256, GEMM1_SMEM>>>(
        xh_p, wih_p, zx_p, M, D_IN_PROJ, DMODEL);

    // 2) conv + silu
    conv_silu_kernel<<<dim3(CONV_DIM / 128, B_SZ, SEQL / 256), 128>>>(conv_w, conv_b);

    // 3) dt softplus + cumsum
    dt_scan_kernel<<<B_SZ * NHEADS * NCHUNK, CHUNKL>>>(dt_bias, A_log);

    // 4) SSM operand converts
    cvt_cb_kernel<<<(B_SZ * SEQL * 64) / 256, 256>>>();
    cvt_bt_kernel<<<dim3(SEQL / 32, DSTATE / 32, B_SZ), 256>>>();
    cvt_xdt_kernel<<<dim3(SEQL / 64, NHEADS, B_SZ), 256>>>();

    // 5) states (single fp16 HMMA)
    states_hmma<<<B_SZ * NCHUNK * NHEADS, 256, S_SMEM_BYTES>>>();

    // 6) recurrence -> prev fp16
    prev_kernel<<<B_SZ * NHEADS, 1024>>>();

    // 7) Y (single HMMA) + gate
    y_hmma<<<B_SZ * NCHUNK * NHEADS * 4, 256, Y_SMEM_BYTES>>>(Dp);

    // 8) RMSNorm -> fp16
    rmsnorm_kernel<<<B_SZ * SEQL, 256>>>(norm_w);

    // 9) out_proj GEMM
    gemm_hmma_fp16<<<dim3(DMODEL / 128, M / 128), 256, GEMM1_SMEM>>>(
        ynh_p, owh_p, out, M, DMODEL, DINNER);

    (void)in_sizes; (void)n_in; (void)out_size;
}

// round 11
// speedup vs baseline: 6.6375x; 1.0118x over previous
#include <cuda_runtime.h>
#include <cuda_bf16.h>
#include <cuda_fp16.h>
#include <cstdint>
#include <cstring>

#define B_SZ 2
#define SEQL 2048
#define DMODEL 2048
#define DINNER 4096
#define DSTATE 128
#define HEADDIM 64
#define NHEADS 64
#define CHUNKL 256
#define NCHUNK 8
#define CONV_DIM 4352     // DINNER + 2*DSTATE
#define D_IN_PROJ 8512    // 2*DINNER + 2*DSTATE + NHEADS
#define DIP_PAD 8576      // 67*128
#define EPSV 1e-5f

// ---------------- scratch ----------------
__device__ float g_zx[B_SZ*SEQL*D_IN_PROJ];
__device__ float g_dt[B_SZ*SEQL*NHEADS];
__device__ float g_Acs[B_SZ*NHEADS*NCHUNK*CHUNKL];
__device__ float g_yg[B_SZ*SEQL*DINNER];
// fp16 gemm operands
__device__ __half g_xh[B_SZ*SEQL*DMODEL];
__device__ __half g_wih[(size_t)DIP_PAD*DMODEL];
__device__ __half g_ynh[B_SZ*SEQL*DINNER];
__device__ __half g_owh[(size_t)DMODEL*DINNER];
// fp16 activations / SSM operands
__device__ __half g_xs[B_SZ*SEQL*DINNER];                              // conv+silu x_ssm
__device__ __half g_B[B_SZ*SEQL*DSTATE];
__device__ __half g_C[B_SZ*SEQL*DSTATE];
__device__ __half g_BT[B_SZ*DSTATE*SEQL];
__device__ __half g_XdT[(size_t)B_SZ*NHEADS*HEADDIM*SEQL];
__device__ __half g_XdecT[(size_t)B_SZ*NHEADS*HEADDIM*SEQL];
__device__ __half g_statesh[(size_t)B_SZ*NCHUNK*NHEADS*HEADDIM*DSTATE];
__device__ __half g_prev[(size_t)B_SZ*NCHUNK*NHEADS*HEADDIM*DSTATE];

__device__ __forceinline__ float siluf(float a) { return a / (1.f + expf(-a)); }

// ================= common HMMA helpers =================
__device__ __forceinline__ void mma_fp16(float* c, const uint32_t* a, const uint32_t* b) {
    asm volatile(
        "mma.sync.aligned.m16n8k16.row.col.f32.f16.f16.f32 "
        "{%0,%1,%2,%3}, {%4,%5,%6,%7}, {%8,%9}, {%0,%1,%2,%3};"
        : "+f"(c[0]), "+f"(c[1]), "+f"(c[2]), "+f"(c[3])
        : "r"(a[0]), "r"(a[1]), "r"(a[2]), "r"(a[3]), "r"(b[0]), "r"(b[1]));
}
__device__ __forceinline__ void ldsm4(uint32_t* r, uint32_t addr) {
    asm volatile("ldmatrix.sync.aligned.m8n8.x4.shared.b16 {%0,%1,%2,%3}, [%4];"
        : "=r"(r[0]), "=r"(r[1]), "=r"(r[2]), "=r"(r[3]) : "r"(addr));
}
__device__ __forceinline__ void cp16(uint32_t dst, const void* src) {
    asm volatile("cp.async.cg.shared.global [%0], [%1], 16;" :: "r"(dst), "l"(src));
}
__device__ __forceinline__ uint32_t smem_u32(const void* p) {
    uint32_t a;
    asm("{ .reg .u64 t; cvta.to.shared.u64 t, %1; cvt.u32.u64 %0, t; }" : "=r"(a) : "l"(p));
    return a;
}
__device__ __forceinline__ uint32_t packh2(__half a, __half b) {
    __half2 h = __halves2half2(a, b);
    uint32_t u; memcpy(&u, &h, 4); return u;
}

// ================= fp16 HMMA GEMM, BK=64, 3 stages =================
#define OPW64 4096                        // words per 128x64 operand tile
#define STG64 (2 * OPW64)                 // A+B stage, 32 KB
#define GEMM1_SMEM (3 * STG64 * 4)        // 98304 B

// 128 rows x 64 halfs, row = 32 words, swizzle: chunk ^= (r&7)
__device__ __forceinline__ void load_op64(uint32_t sbase_b, const __half* g, int ldk, int tid) {
#pragma unroll
    for (int it = 0; it < 4; it++) {
        int v = tid + (it << 8);
        int r = v >> 3, ch = v & 7;
        int sch = ch ^ (r & 7);
        cp16(sbase_b + (r * 32 + (sch << 2)) * 4, g + (size_t)r * ldk + (ch << 3));
    }
}

__global__ __launch_bounds__(256, 2) void gemm_hmma_fp16(
    const __half* __restrict__ A, const __half* __restrict__ B,
    float* __restrict__ C, int M, int Nreal, int K)
{
    extern __shared__ uint32_t sw[];
    const uint32_t sb = smem_u32(sw);
    const int tid = threadIdx.x, wid = tid >> 5, lane = tid & 31;
    const int warp_m = wid & 1, warp_n = wid >> 1;
    const int m0 = blockIdx.y << 7, n0 = blockIdx.x << 7;
    const int KT = K >> 6;

    const __half* Ab = A + (size_t)m0 * K;
    const __half* Bb = B + (size_t)n0 * K;

    float acc[4][4][4];
#pragma unroll
    for (int i = 0; i < 4; i++)
#pragma unroll
        for (int j = 0; j < 4; j++)
#pragma unroll
            for (int q = 0; q < 4; q++) acc[i][j][q] = 0.f;

    // prologue: stages 0,1
#pragma unroll
    for (int s = 0; s < 2; s++) {
        int koff = s << 6;
        load_op64(sb + (s * STG64) * 4, Ab + koff, K, tid);
        load_op64(sb + (s * STG64 + OPW64) * 4, Bb + koff, K, tid);
        asm volatile("cp.async.commit_group;" ::: "memory");
    }

    const int rowA = warp_m * 64 + ((lane >> 3) & 1) * 8 + (lane & 7);
    const int cA0  = lane >> 4;
    const int rowB = warp_n * 32 + ((lane >> 4) & 1) * 8 + (lane & 7);
    const int cB0  = (lane >> 3) & 1;

    int buf = 0;
    for (int kt = 0; kt < KT; kt++) {
        if (kt + 1 < KT) asm volatile("cp.async.wait_group 1;" ::: "memory");
        else             asm volatile("cp.async.wait_group 0;" ::: "memory");
        __syncthreads();
        if (kt + 2 < KT) {
            int s = buf + 2; if (s >= 3) s -= 3;
            int koff = (kt + 2) << 6;
            load_op64(sb + (s * STG64) * 4, Ab + koff, K, tid);
            load_op64(sb + (s * STG64 + OPW64) * 4, Bb + koff, K, tid);
            asm volatile("cp.async.commit_group;" ::: "memory");
        }

        const uint32_t sA = sb + (uint32_t)buf * STG64 * 4u;
        const uint32_t sB = sA + OPW64 * 4u;

#pragma unroll
        for (int kk = 0; kk < 4; kk++) {
            uint32_t a[4][4];
#pragma unroll
            for (int mi = 0; mi < 4; mi++) {
                int r = rowA + mi * 16;
                uint32_t off = (r * 32 + ((((kk << 1) + cA0) ^ (r & 7)) << 2)) * 4u;
                ldsm4(a[mi], sA + off);
            }
#pragma unroll
            for (int np = 0; np < 2; np++) {
                int r = rowB + np * 16;
                uint32_t boff = (r * 32 + ((((kk << 1) + cB0) ^ (r & 7)) << 2)) * 4u;
                uint32_t b[4];
                ldsm4(b, sB + boff);
#pragma unroll
                for (int mi = 0; mi < 4; mi++) {
                    mma_fp16(acc[mi][2 * np], a[mi], b);
                    mma_fp16(acc[mi][2 * np + 1], a[mi], b + 2);
                }
            }
        }
        buf++; if (buf == 3) buf = 0;
    }

#pragma unroll
    for (int mi = 0; mi < 4; mi++) {
        int rg0 = m0 + warp_m * 64 + mi * 16 + (lane >> 2);
#pragma unroll
        for (int ni = 0; ni < 4; ni++) {
            int cg = n0 + warp_n * 32 + ni * 8 + ((lane & 3) << 1);
            if (cg < Nreal) {
                *(float2*)(C + (size_t)rg0 * Nreal + cg) =
                    make_float2(acc[mi][ni][0], acc[mi][ni][1]);
                *(float2*)(C + (size_t)(rg0 + 8) * Nreal + cg) =
                    make_float2(acc[mi][ni][2], acc[mi][ni][3]);
            }
        }
    }
}

// ---------------- fp32 -> fp16 (with zero-pad tail) ----------------
__global__ void cvt_half(const float* __restrict__ src, __half* __restrict__ dst,
                         long n_src, long n_tot)
{
    long i = ((long)blockIdx.x * 256 + threadIdx.x) * 4;
    if (i >= n_tot) return;
    float4 v = (i < n_src) ? *(const float4*)(src + i) : make_float4(0.f, 0.f, 0.f, 0.f);
    __half2* dp = (__half2*)(dst + i);
    dp[0] = __floats2half2_rn(v.x, v.y);
    dp[1] = __floats2half2_rn(v.z, v.w);
}

// ---------------- causal depthwise conv (width 4) + silu -> fp16 outputs ----------------
__global__ void conv_silu_kernel(const float* __restrict__ conv_w,
                                 const float* __restrict__ conv_b)
{
    int c = blockIdx.x * 128 + threadIdx.x;       // 0..CONV_DIM-1
    int b = blockIdx.y;
    int t0 = blockIdx.z * 256;
    float w0 = conv_w[c * 4 + 0], w1 = conv_w[c * 4 + 1];
    float w2 = conv_w[c * 4 + 2], w3 = conv_w[c * 4 + 3];
    float bias = conv_b[c];
    const float* src = g_zx + (size_t)b * SEQL * D_IN_PROJ + DINNER + c;

    __half* dst;
    int stride;
    if (c < DINNER) {
        dst = g_xs + (size_t)b * SEQL * DINNER + c;          stride = DINNER;
    } else if (c < DINNER + DSTATE) {
        dst = g_B + (size_t)b * SEQL * DSTATE + (c - DINNER); stride = DSTATE;
    } else {
        dst = g_C + (size_t)b * SEQL * DSTATE + (c - DINNER - DSTATE); stride = DSTATE;
    }
    dst += (size_t)t0 * stride;

    float x0 = (t0 >= 3) ? src[(size_t)(t0 - 3) * D_IN_PROJ] : 0.f;
    float x1 = (t0 >= 2) ? src[(size_t)(t0 - 2) * D_IN_PROJ] : 0.f;
    float x2 = (t0 >= 1) ? src[(size_t)(t0 - 1) * D_IN_PROJ] : 0.f;
    for (int t = 0; t < 256; t++) {
        float x3 = src[(size_t)(t0 + t) * D_IN_PROJ];
        float a = bias + w0 * x0 + w1 * x1 + w2 * x2 + w3 * x3;
        dst[(size_t)t * stride] = __float2half_rn(siluf(a));
        x0 = x1; x1 = x2; x2 = x3;
    }
}

// ---------------- dt softplus + per-chunk cumsum of dA ----------------
__global__ void dt_scan_kernel(const float* __restrict__ dt_bias,
                               const float* __restrict__ A_log)
{
    int idx = blockIdx.x;
    int c = idx % NCHUNK; idx /= NCHUNK;
    int h = idx % NHEADS;
    int b = idx / NHEADS;
    int l = threadIdx.x;
    int t = c * CHUNKL + l;
    float raw = g_zx[(size_t)(b * SEQL + t) * D_IN_PROJ + DINNER + CONV_DIM + h];
    float xv = raw + dt_bias[h];
    float dt = (xv > 20.f) ? xv : log1pf(expf(xv));
    g_dt[(b * SEQL + t) * NHEADS + h] = dt;
    float dA = dt * (-expf(A_log[h]));
    __shared__ float s[CHUNKL];
    s[l] = dA;
    __syncthreads();
    for (int off = 1; off < CHUNKL; off <<= 1) {
        float v = (l >= off) ? s[l - off] : 0.f;
        __syncthreads();
        s[l] += v;
        __syncthreads();
    }
    g_Acs[((b * NHEADS + h) * NCHUNK + c) * CHUNKL + l] = s[l];
}

// ---------------- B^T: [b][n][t] (from fp16 g_B) ----------------
__global__ void cvt_bt_kernel()
{
    __shared__ __half tile[32][34];
    int b = blockIdx.z, n0 = blockIdx.y * 32, t0 = blockIdx.x * 32;
    int tid = threadIdx.x;
#pragma unroll
    for (int it = 0; it < 4; it++) {
        int v = tid + it * 256;
        int t = v >> 5, n = v & 31;
        tile[t][n] = g_B[(size_t)(b * SEQL + t0 + t) * DSTATE + n0 + n];
    }
    __syncthreads();
#pragma unroll
    for (int it = 0; it < 2; it++) {
        int v = tid + it * 256;
        int n = v >> 4, tc = (v & 15) << 1;
        size_t o = (size_t)(b * DSTATE + n0 + n) * SEQL + t0 + tc;
        *(__half2*)(g_BT + o) = __halves2half2(tile[tc][n], tile[tc + 1][n]);
    }
}

// ---------------- XdT, XdecT: [b][h][p][t] (from fp16 g_xs) ----------------
__global__ void cvt_xdt_kernel()
{
    __shared__ float xs[64][65];
    __shared__ float dts[64], dec[64];
    int b = blockIdx.z, h = blockIdx.y, tt = blockIdx.x;
    int t0 = tt * 64, tid = threadIdx.x;
    int c = t0 >> 8;
    const float* acs = g_Acs + ((b * NHEADS + h) * NCHUNK + c) * CHUNKL;
    if (tid < 64) {
        int tl = (t0 & 255) + tid;
        dts[tid] = g_dt[(size_t)(b * SEQL + t0 + tid) * NHEADS + h];
        dec[tid] = __expf(acs[CHUNKL - 1] - acs[tl]);
    }
#pragma unroll
    for (int it = 0; it < 16; it++) {
        int v = tid + it * 256;
        int t = v >> 6, p = v & 63;
        xs[t][p] = __half2float(g_xs[(size_t)(b * SEQL + t0 + t) * DINNER + h * HEADDIM + p]);
    }
    __syncthreads();
#pragma unroll
    for (int it = 0; it < 8; it++) {
        int v = tid + it * 256;
        int p = v >> 5, tc = (v & 31) << 1;
        size_t o = ((size_t)((b * NHEADS + h) * HEADDIM) + p) * SEQL + t0 + tc;
        float x0 = xs[tc][p] * dts[tc];
        float x1 = xs[tc + 1][p] * dts[tc + 1];
        *(__half2*)(g_XdT + o)   = __floats2half2_rn(x0, x1);
        *(__half2*)(g_XdecT + o) = __floats2half2_rn(x0 * dec[tc], x1 * dec[tc + 1]);
    }
}

// ---------------- states (single fp16 HMMA) -> fp16 output ----------------
#define S_A_O 0
#define S_B_O 2048
#define S_STG 6144
#define S_SMEM_BYTES (2 * S_STG * 4)    // 49152

__global__ __launch_bounds__(256, 2) void states_hmma()
{
    extern __shared__ uint32_t sw[];
    const uint32_t sb = smem_u32(sw);
    int bid = blockIdx.x;
    int h = bid & 63, cc = (bid >> 6) & 7, b = bid >> 9;
    int tid = threadIdx.x, wid = tid >> 5, lane = tid & 31;
    int warp_m = wid >> 2, warp_n = wid & 3;
    const __half* A = g_XdecT + (size_t)((b * NHEADS + h) * HEADDIM) * SEQL + cc * CHUNKL;
    const __half* B = g_BT + (size_t)(b * DSTATE) * SEQL + cc * CHUNKL;

    float acc[2][4][4];
#pragma unroll
    for (int i = 0; i < 2; i++)
#pragma unroll
        for (int j = 0; j < 4; j++)
#pragma unroll
            for (int q = 0; q < 4; q++) acc[i][j][q] = 0.f;

    auto load_stage = [&](int kc, int buf) {
        uint32_t base = (uint32_t)buf * S_STG;
        int koff = kc * 64;
#pragma unroll
        for (int it = 0; it < 2; it++) {
            int v = tid + (it << 8);
            int r = v >> 3, ch = v & 7;
            int sch = ch ^ (r & 7);
            cp16(sb + (base + S_A_O + r * 32 + sch * 4) * 4, A + (size_t)r * SEQL + koff + ch * 8);
        }
#pragma unroll
        for (int it = 0; it < 4; it++) {
            int v = tid + (it << 8);
            int r = v >> 3, ch = v & 7;
            int sch = ch ^ (r & 7);
            cp16(sb + (base + S_B_O + r * 32 + sch * 4) * 4, B + (size_t)r * SEQL + koff + ch * 8);
        }
        asm volatile("cp.async.commit_group;" ::: "memory");
    };

    load_stage(0, 0);
    load_stage(1, 1);

    const int arow = warp_m * 32 + ((lane >> 3) & 1) * 8 + (lane & 7);
    const int cA0 = lane >> 4;
    const int brl = ((lane >> 4) & 1) * 8 + (lane & 7);
    const int cB0 = (lane >> 3) & 1;

    for (int kc = 0; kc < 4; kc++) {
        if (kc < 3) asm volatile("cp.async.wait_group 1;" ::: "memory");
        else        asm volatile("cp.async.wait_group 0;" ::: "memory");
        __syncthreads();
        uint32_t base = (uint32_t)(kc & 1) * S_STG;
#pragma unroll
        for (int kk = 0; kk < 4; kk++) {
            uint32_t a[2][4];
#pragma unroll
            for (int mi = 0; mi < 2; mi++) {
                int r = arow + mi * 16;
                uint32_t w = base + S_A_O + r * 32 + ((((kk << 1) + cA0) ^ (r & 7)) << 2);
                ldsm4(a[mi], sb + w * 4);
            }
#pragma unroll
            for (int np = 0; np < 2; np++) {
                int rb = warp_n * 32 + np * 16 + brl;
                uint32_t w = base + S_B_O + rb * 32 + ((((kk << 1) + cB0) ^ (rb & 7)) << 2);
                uint32_t bf[4];
                ldsm4(bf, sb + w * 4);
#pragma unroll
                for (int mi = 0; mi < 2; mi++) {
                    mma_fp16(acc[mi][2 * np], a[mi], bf);
                    mma_fp16(acc[mi][2 * np + 1], a[mi], bf + 2);
                }
            }
        }
        __syncthreads();
        if (kc + 2 < 4) load_stage(kc + 2, kc & 1);
    }

    __half* out = g_statesh + (size_t)((b * NCHUNK + cc) * NHEADS + h) * HEADDIM * DSTATE;
#pragma unroll
    for (int mi = 0; mi < 2; mi++) {
        int r0 = warp_m * 32 + mi * 16 + (lane >> 2);
#pragma unroll
        for (int ni = 0; ni < 4; ni++) {
            int col = warp_n * 32 + ni * 8 + 2 * (lane & 3);
            *(__half2*)(out + (size_t)r0 * DSTATE + col) =
                __floats2half2_rn(acc[mi][ni][0], acc[mi][ni][1]);
            *(__half2*)(out + (size_t)(r0 + 8) * DSTATE + col) =
                __floats2half2_rn(acc[mi][ni][2], acc[mi][ni][3]);
        }
    }
}

// ---------------- inter-chunk recurrence (fp16 states in, fp16 prev out, fp32 accum) ----------------
__global__ __launch_bounds__(1024) void prev_kernel()
{
    int b = blockIdx.x >> 6;
    int h = blockIdx.x & 63;
    int tid = threadIdx.x;
    float P[8];
#pragma unroll
    for (int i = 0; i < 8; i++) P[i] = 0.f;
    for (int c = 0; c < NCHUNK; c++) {
        float decay = __expf(g_Acs[((b * NHEADS + h) * NCHUNK + c) * CHUNKL + CHUNKL - 1]);
        size_t base = (size_t)((b * NCHUNK + c) * NHEADS + h) * HEADDIM * DSTATE;
#pragma unroll
        for (int i = 0; i < 8; i++) {
            int e = i * 1024 + tid;
            float v = P[i];
            g_prev[base + e] = __float2half_rn(v);
            P[i] = v * decay + __half2float(g_statesh[base + e]);
        }
    }
}

// ---------------- Y via single fp16 HMMA, double-buffered B/Xd tiles ----------------
#define Y_ACS_O 0
#define Y_C_O 256
#define Y_PV_O (Y_C_O + 4352)
#define Y_B0_O (Y_PV_O + 4352)
#define Y_B1_O (Y_B0_O + 4352)
#define Y_X0_O (Y_B1_O + 4352)
#define Y_X1_O (Y_X0_O + 2304)
#define Y_S_O  (Y_X1_O + 2304)
#define Y_SMEM_BYTES ((Y_S_O + 2304) * 4)   // 98304

__global__ __launch_bounds__(256, 2) void y_hmma(const float* __restrict__ Dp)
{
    extern __shared__ uint32_t sw[];
    const uint32_t sb = smem_u32(sw);
    float* acs_s = (float*)(sw + Y_ACS_O);
    int bid = blockIdx.x;
    int lt = bid & 3, h = (bid >> 2) & 63, c = (bid >> 8) & 7, b = bid >> 11;
    int tid = threadIdx.x, wid = tid >> 5, lane = tid & 31;
    int warp_m = wid >> 2, warp_n = wid & 3;
    int l0 = lt * 64;
    const int bt0 = b * SEQL + c * CHUNKL;

    acs_s[tid] = g_Acs[((b * NHEADS + h) * NCHUNK + c) * CHUNKL + tid];

    const __half* gB = g_B + (size_t)bt0 * DSTATE;
    const __half* gX = g_XdT + (size_t)((b * NHEADS + h) * HEADDIM) * SEQL + c * CHUNKL;

    auto load_bx = [&](int st, int pbuf) {
        const __half* Bp = gB + (size_t)(st * 64) * DSTATE;
        const __half* Xp = gX + st * 64;
        uint32_t bo = pbuf ? (uint32_t)Y_B1_O : (uint32_t)Y_B0_O;
        uint32_t xo = pbuf ? (uint32_t)Y_X1_O : (uint32_t)Y_X0_O;
#pragma unroll
        for (int it = 0; it < 4; it++) {
            int v = tid + (it << 8);
            int r = v >> 4, ch = v & 15;
            cp16(sb + (bo + r * 68 + ch * 4) * 4, Bp + (size_t)r * DSTATE + ch * 8);
        }
#pragma unroll
        for (int it = 0; it < 2; it++) {
            int v = tid + (it << 8);
            int r = v >> 3, ch = v & 7;
            cp16(sb + (xo + r * 36 + ch * 4) * 4, Xp + (size_t)r * SEQL + ch * 8);
        }
        asm volatile("cp.async.commit_group;" ::: "memory");
    };

    // group 0: C (rows l0..l0+63) + prev
    {
        const __half* sC = g_C + (size_t)(bt0 + l0) * DSTATE;
        size_t pb = (size_t)((b * NCHUNK + c) * NHEADS + h) * HEADDIM * DSTATE;
        const __half* sP = g_prev + pb;
#pragma unroll
        for (int it = 0; it < 4; it++) {
            int v = tid + (it << 8);
            int r = v >> 4, ch = v & 15;
            cp16(sb + (Y_C_O + r * 68 + ch * 4) * 4, sC + (size_t)r * DSTATE + ch * 8);
            cp16(sb + (Y_PV_O + r * 68 + ch * 4) * 4, sP + (size_t)r * DSTATE + ch * 8);
        }
        asm volatile("cp.async.commit_group;" ::: "memory");
    }
    // group 1: B/Xd tile for st=0
    load_bx(0, 0);

    asm volatile("cp.async.wait_group 1;" ::: "memory");  // C+prev done
    __syncthreads();

    float Yacc[2][2][4];
#pragma unroll
    for (int i = 0; i < 2; i++)
#pragma unroll
        for (int j = 0; j < 2; j++)
#pragma unroll
            for (int q = 0; q < 4; q++) Yacc[i][j][q] = 0.f;

    const int arow = warp_m * 32 + ((lane >> 3) & 1) * 8 + (lane & 7);
    const int akw  = (lane >> 4) << 2;
    const int brow = warp_n * 16 + ((lane >> 4) & 1) * 8 + (lane & 7);
    const int bkw  = ((lane >> 3) & 1) << 2;

    // Y_off = C * prev^T  (K = 128)
#pragma unroll
    for (int kk = 0; kk < 8; kk++) {
        uint32_t a[2][4], bf[4];
#pragma unroll
        for (int mi = 0; mi < 2; mi++)
            ldsm4(a[mi], sb + (uint32_t)(Y_C_O + (arow + mi * 16) * 68 + kk * 8 + akw) * 4);
        ldsm4(bf, sb + (uint32_t)(Y_PV_O + brow * 68 + kk * 8 + bkw) * 4);
#pragma unroll
        for (int mi = 0; mi < 2; mi++) {
            mma_fp16(Yacc[mi][0], a[mi], bf);
            mma_fp16(Yacc[mi][1], a[mi], bf + 2);
        }
    }
    // scale Y_off rows by exp(acs[l])
#pragma unroll
    for (int mi = 0; mi < 2; mi++) {
        int r0 = l0 + warp_m * 32 + mi * 16 + (lane >> 2);
        float e0 = __expf(acs_s[r0]);
        float e1 = __expf(acs_s[r0 + 8]);
#pragma unroll
        for (int ni = 0; ni < 2; ni++) {
            Yacc[mi][ni][0] *= e0; Yacc[mi][ni][1] *= e0;
            Yacc[mi][ni][2] *= e1; Yacc[mi][ni][3] *= e1;
        }
    }

    for (int st = 0; st <= lt; st++) {
        // prefetch next s-tile while computing this one
        if (st + 1 <= lt) {
            load_bx(st + 1, (st + 1) & 1);
            asm volatile("cp.async.wait_group 1;" ::: "memory");
        } else {
            asm volatile("cp.async.wait_group 0;" ::: "memory");
        }
        __syncthreads();

        const uint32_t bo = (st & 1) ? (uint32_t)Y_B1_O : (uint32_t)Y_B0_O;
        const uint32_t xo = (st & 1) ? (uint32_t)Y_X1_O : (uint32_t)Y_X0_O;
        int s0 = st * 64;

        // S = C * B^T (K=128)
        float sacc[2][2][4];
#pragma unroll
        for (int i = 0; i < 2; i++)
#pragma unroll
            for (int j = 0; j < 2; j++)
#pragma unroll
                for (int q = 0; q < 4; q++) sacc[i][j][q] = 0.f;
#pragma unroll
        for (int kk = 0; kk < 8; kk++) {
            uint32_t a[2][4], bf[4];
#pragma unroll
            for (int mi = 0; mi < 2; mi++)
                ldsm4(a[mi], sb + (uint32_t)(Y_C_O + (arow + mi * 16) * 68 + kk * 8 + akw) * 4);
            ldsm4(bf, sb + (bo + brow * 68 + kk * 8 + bkw) * 4);
#pragma unroll
            for (int mi = 0; mi < 2; mi++) {
                mma_fp16(sacc[mi][0], a[mi], bf);
                mma_fp16(sacc[mi][1], a[mi], bf + 2);
            }
        }
        // mask + decay -> S fp16 in smem
#pragma unroll
        for (int mi = 0; mi < 2; mi++) {
            int rr0 = warp_m * 32 + mi * 16 + (lane >> 2);
            int lg0 = l0 + rr0, lg1 = lg0 + 8;
            float a0 = acs_s[lg0], a1 = acs_s[lg1];
#pragma unroll
            for (int ni = 0; ni < 2; ni++) {
                int ccc = warp_n * 16 + ni * 8 + 2 * (lane & 3);
                int sg = s0 + ccc;
                float as0 = acs_s[sg], as1 = acs_s[sg + 1];
                float v00 = (sg     <= lg0) ? sacc[mi][ni][0] * __expf(a0 - as0) : 0.f;
                float v01 = (sg + 1 <= lg0) ? sacc[mi][ni][1] * __expf(a0 - as1) : 0.f;
                float v10 = (sg     <= lg1) ? sacc[mi][ni][2] * __expf(a1 - as0) : 0.f;
                float v11 = (sg + 1 <= lg1) ? sacc[mi][ni][3] * __expf(a1 - as1) : 0.f;
                sw[Y_S_O + rr0 * 36 + (ccc >> 1)] =
                    packh2(__float2half_rn(v00), __float2half_rn(v01));
                sw[Y_S_O + (rr0 + 8) * 36 + (ccc >> 1)] =
                    packh2(__float2half_rn(v10), __float2half_rn(v11));
            }
        }
        __syncthreads();
        // Y += S * Xd^T  (K = 64)   [no trailing sync: next top barrier orders S reuse]
#pragma unroll
        for (int kk = 0; kk < 4; kk++) {
            uint32_t a[2][4], bf[4];
#pragma unroll
            for (int mi = 0; mi < 2; mi++)
                ldsm4(a[mi], sb + (uint32_t)(Y_S_O + (arow + mi * 16) * 36 + kk * 8 + akw) * 4);
            ldsm4(bf, sb + (xo + brow * 36 + kk * 8 + bkw) * 4);
#pragma unroll
            for (int mi = 0; mi < 2; mi++) {
                mma_fp16(Yacc[mi][0], a[mi], bf);
                mma_fp16(Yacc[mi][1], a[mi], bf + 2);
            }
        }
    }

    // epilogue: + D*x_ssm, gate with silu(z)
    float Dh = Dp[h];
#pragma unroll
    for (int mi = 0; mi < 2; mi++) {
#pragma unroll
        for (int q = 0; q < 2; q++) {
            int rr = warp_m * 32 + mi * 16 + (lane >> 2) + q * 8;
            int t = bt0 + l0 + rr;
#pragma unroll
            for (int ni = 0; ni < 2; ni++) {
                int pp = warp_n * 16 + ni * 8 + 2 * (lane & 3);
                float2 xs = __half22float2(*(const __half2*)(g_xs + (size_t)t * DINNER + h * HEADDIM + pp));
                float2 zz = *(const float2*)(g_zx + (size_t)t * D_IN_PROJ + h * HEADDIM + pp);
                float y0 = Yacc[mi][ni][q * 2 + 0] + xs.x * Dh;
                float y1 = Yacc[mi][ni][q * 2 + 1] + xs.y * Dh;
                float2 o = make_float2(y0 * siluf(zz.x), y1 * siluf(zz.y));
                *(float2*)(g_yg + (size_t)t * DINNER + h * HEADDIM + pp) = o;
            }
        }
    }
}

// ---------------- RMSNorm -> fp16 ----------------
__global__ __launch_bounds__(256) void rmsnorm_kernel(const float* __restrict__ w)
{
    int row = blockIdx.x;
    const float* y = g_yg + (size_t)row * DINNER;
    __half* oh = g_ynh + (size_t)row * DINNER;
    int tid = threadIdx.x;
    float ss = 0.f;
#pragma unroll
    for (int it = 0; it < 4; it++) {
        float4 v = *(const float4*)(y + it * 1024 + tid * 4);
        ss += v.x * v.x + v.y * v.y + v.z * v.z + v.w * v.w;
    }
#pragma unroll
    for (int off = 16; off; off >>= 1) ss += __shfl_xor_sync(0xFFFFFFFFu, ss, off);
    __shared__ float red[8];
    if ((tid & 31) == 0) red[tid >> 5] = ss;
    __syncthreads();
    float tot = 0.f;
#pragma unroll
    for (int i = 0; i < 8; i++) tot += red[i];
    float scale = rsqrtf(tot / (float)DINNER + EPSV);
#pragma unroll
    for (int it = 0; it < 4; it++) {
        int i = it * 1024 + tid * 4;
        float4 v = *(const float4*)(y + i);
        float4 wv = *(const float4*)(w + i);
        __half2* hp = (__half2*)(oh + i);
        hp[0] = __floats2half2_rn(v.x * scale * wv.x, v.y * scale * wv.y);
        hp[1] = __floats2half2_rn(v.z * scale * wv.z, v.w * scale * wv.w);
    }
}

// ---------------- launch ----------------
extern "C" void kernel_launch(void* const* d_in, const int* in_sizes, int n_in,
                              void* d_out, int out_size)
{
    const float* x          = (const float*)d_in[0];
    const float* in_proj_w  = (const float*)d_in[1];
    const float* conv_w     = (const float*)d_in[2];
    const float* conv_b     = (const float*)d_in[3];
    const float* dt_bias    = (const float*)d_in[4];
    const float* A_log      = (const float*)d_in[5];
    const float* Dp         = (const float*)d_in[6];
    const float* norm_w     = (const float*)d_in[7];
    const float* out_proj_w = (const float*)d_in[8];
    float* out = (float*)d_out;

    float *zx_p = nullptr;
    __half *xh_p, *wih_p, *ynh_p, *owh_p;
    cudaGetSymbolAddress((void**)&zx_p, g_zx);
    cudaGetSymbolAddress((void**)&xh_p, g_xh);
    cudaGetSymbolAddress((void**)&wih_p, g_wih);
    cudaGetSymbolAddress((void**)&ynh_p, g_ynh);
    cudaGetSymbolAddress((void**)&owh_p, g_owh);

    static bool attr_set = false;
    if (!attr_set) {
        cudaFuncSetAttribute(gemm_hmma_fp16, cudaFuncAttributeMaxDynamicSharedMemorySize, GEMM1_SMEM);
        cudaFuncSetAttribute(states_hmma, cudaFuncAttributeMaxDynamicSharedMemorySize, S_SMEM_BYTES);
        cudaFuncSetAttribute(y_hmma, cudaFuncAttributeMaxDynamicSharedMemorySize, Y_SMEM_BYTES);
        attr_set = true;
    }

    const int M = B_SZ * SEQL; // 4096

    // converts (projections)
    {
        long n = (long)M * DMODEL;
        cvt_half<<<(unsigned)((n / 4 + 255) / 256), 256>>>(x, xh_p, n, n);
    }
    {
        long ns = (long)D_IN_PROJ * DMODEL, nt = (long)DIP_PAD * DMODEL;
        cvt_half<<<(unsigned)((nt / 4 + 255) / 256), 256>>>(in_proj_w, wih_p, ns, nt);
    }
    {
        long n = (long)DMODEL * DINNER;
        cvt_half<<<(unsigned)((n / 4 + 255) / 256), 256>>>(out_proj_w, owh_p, n, n);
    }

    // 1) in_proj GEMM
    gemm_hmma_fp16<<<dim3(DIP_PAD / 128, M / 128), 256, GEMM1_SMEM>>>(
        xh_p, wih_p, zx_p, M, D_IN_PROJ, DMODEL);

    // 2) conv + silu -> fp16 (g_xs, g_B, g_C)
    conv_silu_kernel<<<dim3(CONV_DIM / 128, B_SZ, SEQL / 256), 128>>>(conv_w, conv_b);

    // 3) dt softplus + cumsum
    dt_scan_kernel<<<B_SZ * NHEADS * NCHUNK, CHUNKL>>>(dt_bias, A_log);

    // 4) SSM operand converts
    cvt_bt_kernel<<<dim3(SEQL / 32, DSTATE / 32, B_SZ), 256>>>();
    cvt_xdt_kernel<<<dim3(SEQL / 64, NHEADS, B_SZ), 256>>>();

    // 5) states (single fp16 HMMA) -> fp16
    states_hmma<<<B_SZ * NCHUNK * NHEADS, 256, S_SMEM_BYTES>>>();

    // 6) recurrence -> prev fp16
    prev_kernel<<<B_SZ * NHEADS, 1024>>>();

    // 7) Y (single HMMA) + gate
    y_hmma<<<B_SZ * NCHUNK * NHEADS * 4, 256, Y_SMEM_BYTES>>>(Dp);

    // 8) RMSNorm -> fp16
    rmsnorm_kernel<<<B_SZ * SEQL, 256>>>(norm_w);

    // 9) out_proj GEMM
    gemm_hmma_fp16<<<dim3(DMODEL / 128, M / 128), 256, GEMM1_SMEM>>>(
        ynh_p, owh_p, out, M, DMODEL, DINNER);

    (void)in_sizes; (void)n_in; (void)out_size;
}